// round 1
// baseline (speedup 1.0000x reference)
#include <cuda_runtime.h>
#include <cstdint>

#define TB 256

// ---- problem constants ----
constexpr int Bv = 8, Tv = 1024, Hv = 16, Dv = 64, Cv = 1024, Lv = 256, Ev = 8, Iv = 2048;
constexpr int Nv  = Bv * Tv;   // 8192 tokens
constexpr int BHv = Bv * Hv;   // 128

// ---- scratch (device globals; allocation-free) ----
__device__ float g_h  [Nv * Cv];
__device__ float g_q  [Nv * Cv];
__device__ float g_kv [Nv * Lv];
__device__ float g_k  [Nv * Cv];          // [b,h,t,d]
__device__ float g_v  [Nv * Cv];          // [b,h,t,d]
__device__ float g_S  [(size_t)BHv * Tv * Tv];   // scores / probs (512 MB)
__device__ float g_at [Nv * Cv];
__device__ float g_x1 [Nv * Cv];
__device__ float g_h2 [Nv * Cv];
__device__ float g_a1 [Nv * Iv];
__device__ float g_a3 [Nv * Iv];
__device__ float g_u  [Nv * Iv];
__device__ float g_sh [Nv * Cv];
__device__ float g_c1 [Nv * Iv];
__device__ float g_c3 [Nv * Iv];
__device__ float g_uc [Nv * Iv];
__device__ float g_yc [Nv * Cv];
__device__ int   g_sel[Nv];
__device__ float g_p  [Nv];
__device__ int   g_cnt[Ev];
__device__ int   g_off[Ev];
__device__ int   g_cur[Ev];
__device__ int   g_perm[Nv];

// ============================================================
// RMSNorm: one block per token
// ============================================================
__global__ void rmsnorm_kernel(const float* __restrict__ x, const float* __restrict__ w,
                               float* __restrict__ y)
{
    int n = blockIdx.x, tid = threadIdx.x;
    const float* xr = x + (size_t)n * Cv;
    __shared__ float red[TB];
    float ss = 0.f;
    for (int c = tid; c < Cv; c += TB) { float v = xr[c]; ss += v * v; }
    red[tid] = ss; __syncthreads();
    for (int s = TB / 2; s > 0; s >>= 1) { if (tid < s) red[tid] += red[tid + s]; __syncthreads(); }
    float rs = rsqrtf(red[0] / (float)Cv + 1e-6f);
    float* yr = y + (size_t)n * Cv;
    for (int c = tid; c < Cv; c += TB) yr[c] = xr[c] * rs * w[c];
}

// ============================================================
// Generic SGEMM: C = alpha*A(MxK)@B(KxN) (+Res). M,N mult of 128, K mult of 16.
// 128x128x16 tile, 256 threads, 8x8 per thread.
// ============================================================
__global__ void sgemm128(const float* __restrict__ A, const float* __restrict__ B,
                         float* __restrict__ Cmat, const float* __restrict__ Res,
                         int K, int N, float alpha)
{
    __shared__ float As[16][132];
    __shared__ float Bs[16][128];
    const int tid = threadIdx.x;
    const int bm = blockIdx.y * 128, bn = blockIdx.x * 128;
    const int a_row = tid >> 2,        a_col = (tid & 3) << 2;
    const int b_row = tid >> 5,        b_col = (tid & 31) << 2;
    const int tr    = (tid >> 4) << 3, tc    = (tid & 15) << 3;
    float acc[8][8];
#pragma unroll
    for (int i = 0; i < 8; i++)
#pragma unroll
        for (int j = 0; j < 8; j++) acc[i][j] = 0.f;

    for (int k0 = 0; k0 < K; k0 += 16) {
#pragma unroll
        for (int i = 0; i < 2; i++) {
            int r = a_row + (i << 6);
            float4 v = *(const float4*)(A + (size_t)(bm + r) * K + k0 + a_col);
            As[a_col + 0][r] = v.x; As[a_col + 1][r] = v.y;
            As[a_col + 2][r] = v.z; As[a_col + 3][r] = v.w;
        }
#pragma unroll
        for (int i = 0; i < 2; i++) {
            int r = b_row + (i << 3);
            *(float4*)(&Bs[r][b_col]) = *(const float4*)(B + (size_t)(k0 + r) * N + bn + b_col);
        }
        __syncthreads();
#pragma unroll
        for (int kk = 0; kk < 16; kk++) {
            float ra[8], rb[8];
#pragma unroll
            for (int i = 0; i < 8; i++) ra[i] = As[kk][tr + i];
#pragma unroll
            for (int j = 0; j < 8; j++) rb[j] = Bs[kk][tc + j];
#pragma unroll
            for (int i = 0; i < 8; i++)
#pragma unroll
                for (int j = 0; j < 8; j++) acc[i][j] += ra[i] * rb[j];
        }
        __syncthreads();
    }
#pragma unroll
    for (int i = 0; i < 8; i++) {
        size_t row = (size_t)(bm + tr + i);
#pragma unroll
        for (int j = 0; j < 8; j += 4) {
            size_t idx = row * N + bn + tc + j;
            float4 v = make_float4(acc[i][j] * alpha, acc[i][j + 1] * alpha,
                                   acc[i][j + 2] * alpha, acc[i][j + 3] * alpha);
            if (Res) {
                float4 r4 = *(const float4*)(Res + idx);
                v.x += r4.x; v.y += r4.y; v.z += r4.z; v.w += r4.w;
            }
            *(float4*)(Cmat + idx) = v;
        }
    }
}

// ============================================================
// Grouped (per-expert) SGEMM with optional row gather.
// A rows gathered via g_perm (GATHER) or compact (off+lr).
// Out: compact row-major [Nv x N]. 128x128x16 tile.
// ============================================================
template <bool GATHER>
__global__ void gg_sgemm(const float* __restrict__ A, const float* __restrict__ Bbase,
                         size_t strideB, int K, int N, float* __restrict__ Out)
{
    int e = blockIdx.z;
    int cnt = g_cnt[e];
    int base = blockIdx.x * 128;
    if (base >= cnt) return;
    int o = g_off[e];
    const float* B = Bbase + (size_t)e * strideB;

    __shared__ float As[16][132];
    __shared__ float Bs[16][128];
    const int tid = threadIdx.x;
    const int bn = blockIdx.y * 128;
    const int a_row = tid >> 2,        a_col = (tid & 3) << 2;
    const int b_row = tid >> 5,        b_col = (tid & 31) << 2;
    const int tr    = (tid >> 4) << 3, tc    = (tid & 15) << 3;
    float acc[8][8];
#pragma unroll
    for (int i = 0; i < 8; i++)
#pragma unroll
        for (int j = 0; j < 8; j++) acc[i][j] = 0.f;

    for (int k0 = 0; k0 < K; k0 += 16) {
#pragma unroll
        for (int i = 0; i < 2; i++) {
            int lr = base + a_row + (i << 6);
            float4 v = make_float4(0.f, 0.f, 0.f, 0.f);
            if (lr < cnt) {
                int grow = GATHER ? g_perm[o + lr] : (o + lr);
                v = *(const float4*)(A + (size_t)grow * K + k0 + a_col);
            }
            int r = a_row + (i << 6);
            As[a_col + 0][r] = v.x; As[a_col + 1][r] = v.y;
            As[a_col + 2][r] = v.z; As[a_col + 3][r] = v.w;
        }
#pragma unroll
        for (int i = 0; i < 2; i++) {
            int r = b_row + (i << 3);
            *(float4*)(&Bs[r][b_col]) = *(const float4*)(B + (size_t)(k0 + r) * N + bn + b_col);
        }
        __syncthreads();
#pragma unroll
        for (int kk = 0; kk < 16; kk++) {
            float ra[8], rb[8];
#pragma unroll
            for (int i = 0; i < 8; i++) ra[i] = As[kk][tr + i];
#pragma unroll
            for (int j = 0; j < 8; j++) rb[j] = Bs[kk][tc + j];
#pragma unroll
            for (int i = 0; i < 8; i++)
#pragma unroll
                for (int j = 0; j < 8; j++) acc[i][j] += ra[i] * rb[j];
        }
        __syncthreads();
    }
#pragma unroll
    for (int i = 0; i < 8; i++) {
        int lr = base + tr + i;
        if (lr >= cnt) continue;
        size_t row = (size_t)(o + lr);
#pragma unroll
        for (int j = 0; j < 8; j += 4) {
            size_t idx = row * N + bn + tc + j;
            *(float4*)(Out + idx) = make_float4(acc[i][j], acc[i][j + 1], acc[i][j + 2], acc[i][j + 3]);
        }
    }
}

// ============================================================
// K/V up-projection per head: out[b,h,t,:] = kv[n,:] @ Wup[h] (L=256 x D=64)
// grid (Nv/64, 1, H), 64x64 tile, 4x4 per thread.
// ============================================================
__global__ void kvup_kernel(const float* __restrict__ kv, const float* __restrict__ Wup,
                            float* __restrict__ outb)
{
    int h = blockIdx.z;
    int bm = blockIdx.x * 64;
    const float* Bm = Wup + (size_t)h * Lv * Dv;
    __shared__ float As[16][65];
    __shared__ float Bs[16][64];
    const int tid = threadIdx.x;
    const int ar = tid >> 2,        ac = (tid & 3) << 2;
    const int br = tid >> 4,        bc = (tid & 15) << 2;
    const int ti = (tid >> 4) << 2, tc = (tid & 15) << 2;
    float acc[4][4];
#pragma unroll
    for (int i = 0; i < 4; i++)
#pragma unroll
        for (int j = 0; j < 4; j++) acc[i][j] = 0.f;

    for (int k0 = 0; k0 < Lv; k0 += 16) {
        float4 av = *(const float4*)(kv + (size_t)(bm + ar) * Lv + k0 + ac);
        As[ac + 0][ar] = av.x; As[ac + 1][ar] = av.y; As[ac + 2][ar] = av.z; As[ac + 3][ar] = av.w;
        *(float4*)(&Bs[br][bc]) = *(const float4*)(Bm + (size_t)(k0 + br) * Dv + bc);
        __syncthreads();
#pragma unroll
        for (int kk = 0; kk < 16; kk++) {
            float ra[4], rb[4];
#pragma unroll
            for (int i = 0; i < 4; i++) ra[i] = As[kk][ti + i];
#pragma unroll
            for (int j = 0; j < 4; j++) rb[j] = Bs[kk][tc + j];
#pragma unroll
            for (int i = 0; i < 4; i++)
#pragma unroll
                for (int j = 0; j < 4; j++) acc[i][j] += ra[i] * rb[j];
        }
        __syncthreads();
    }
#pragma unroll
    for (int i = 0; i < 4; i++) {
        int n = bm + ti + i;
        int b = n >> 10, t = n & 1023;
        size_t idx = ((size_t)(b * Hv + h) * Tv + t) * Dv + tc;
        *(float4*)(outb + idx) = make_float4(acc[i][0], acc[i][1], acc[i][2], acc[i][3]);
    }
}

// ============================================================
// RoPE in place on 64-wide head vectors. posDiv: Hv for q-layout, 1 for k-layout.
// ============================================================
__global__ void rope_kernel(float* __restrict__ xp, int posDiv)
{
    int idx = blockIdx.x * TB + threadIdx.x;   // pair index; exact grid
    int outer = idx >> 5;
    int j = idx & 31;
    int pos = (outer / posDiv) & (Tv - 1);
    float invf = powf(100000.0f, -(float)j * (1.0f / 32.0f));
    float f = (float)pos * invf;
    float s, c; sincosf(f, &s, &c);
    float* p = xp + (size_t)outer * Dv;
    float x1 = p[j], x2 = p[j + 32];
    p[j]      = x1 * c - x2 * s;
    p[j + 32] = x1 * s + x2 * c;
}

// ============================================================
// Attention scores: S[bh, t, s] = (q_t . k_s) / 8, causal tile skip.
// grid (T/64 = ks tiles, T/64 = qs tiles, BH). 64x64 tile, K=64.
// ============================================================
__global__ void scores_kernel(const float* __restrict__ q, const float* __restrict__ k,
                              float* __restrict__ S)
{
    int bh = blockIdx.z, b = bh >> 4, h = bh & 15;
    int qs = blockIdx.y * 64, ks = blockIdx.x * 64;
    if (ks > qs) return;   // fully masked tile
    __shared__ float Qs[64][65];
    __shared__ float Ks[64][65];
    const int tid = threadIdx.x;
    const int r = tid >> 2, c0 = tid & 3;
#pragma unroll
    for (int i = 0; i < 4; i++) {
        int col = (c0 + 4 * i) << 2;
        float4 v = *(const float4*)(q + (size_t)(b * Tv + qs + r) * Cv + h * Dv + col);
        Qs[r][col] = v.x; Qs[r][col + 1] = v.y; Qs[r][col + 2] = v.z; Qs[r][col + 3] = v.w;
        float4 w = *(const float4*)(k + ((size_t)bh * Tv + ks + r) * Dv + col);
        Ks[r][col] = w.x; Ks[r][col + 1] = w.y; Ks[r][col + 2] = w.z; Ks[r][col + 3] = w.w;
    }
    __syncthreads();
    const int ti = (tid >> 4) << 2, tj = (tid & 15) << 2;
    float acc[4][4];
#pragma unroll
    for (int i = 0; i < 4; i++)
#pragma unroll
        for (int j = 0; j < 4; j++) acc[i][j] = 0.f;
#pragma unroll
    for (int d = 0; d < 64; d++) {
        float ra[4], rb[4];
#pragma unroll
        for (int i = 0; i < 4; i++) ra[i] = Qs[ti + i][d];
#pragma unroll
        for (int j = 0; j < 4; j++) rb[j] = Ks[tj + j][d];
#pragma unroll
        for (int i = 0; i < 4; i++)
#pragma unroll
            for (int j = 0; j < 4; j++) acc[i][j] += ra[i] * rb[j];
    }
#pragma unroll
    for (int i = 0; i < 4; i++) {
        size_t idx = ((size_t)bh * Tv + qs + ti + i) * Tv + ks + tj;
        *(float4*)(S + idx) = make_float4(acc[i][0] * 0.125f, acc[i][1] * 0.125f,
                                          acc[i][2] * 0.125f, acc[i][3] * 0.125f);
    }
}

// ============================================================
// Causal row softmax in place; zeros masked tail. One block per (bh,t).
// ============================================================
__global__ void softmax_kernel(float* __restrict__ S)
{
    long long row = blockIdx.x;
    int t = (int)(row & (Tv - 1));
    float* Sr = S + row * (long long)Tv;
    int len = t + 1;
    int tid = threadIdx.x;
    __shared__ float red[TB];
    float m = -1e30f;
    for (int s = tid; s < len; s += TB) m = fmaxf(m, Sr[s]);
    red[tid] = m; __syncthreads();
    for (int st = TB / 2; st > 0; st >>= 1) { if (tid < st) red[tid] = fmaxf(red[tid], red[tid + st]); __syncthreads(); }
    float rowmax = red[0];
    __syncthreads();
    float sum = 0.f;
    for (int s = tid; s < len; s += TB) sum += expf(Sr[s] - rowmax);
    red[tid] = sum; __syncthreads();
    for (int st = TB / 2; st > 0; st >>= 1) { if (tid < st) red[tid] += red[tid + st]; __syncthreads(); }
    float inv = 1.f / red[0];
    for (int s = tid; s < Tv; s += TB)
        Sr[s] = (s < len) ? expf(Sr[s] - rowmax) * inv : 0.f;
}

// ============================================================
// O = P @ V per (b,h); causal K-bound. Output token-major [n][h*D+d].
// grid (T/64, 1, BH). 64x64 tile, BK=16.
// ============================================================
__global__ void av_kernel(const float* __restrict__ P, const float* __restrict__ V,
                          float* __restrict__ O)
{
    int bh = blockIdx.z, b = bh >> 4, h = bh & 15;
    int qs = blockIdx.x * 64;
    const float* Pr = P + (size_t)bh * Tv * Tv;
    const float* Vr = V + (size_t)bh * Tv * Dv;
    __shared__ float As[16][65];
    __shared__ float Bs[16][64];
    const int tid = threadIdx.x;
    const int ar = tid >> 2,        ac = (tid & 3) << 2;
    const int br = tid >> 4,        bc = (tid & 15) << 2;
    const int ti = (tid >> 4) << 2, tc = (tid & 15) << 2;
    float acc[4][4];
#pragma unroll
    for (int i = 0; i < 4; i++)
#pragma unroll
        for (int j = 0; j < 4; j++) acc[i][j] = 0.f;

    int kend = qs + 64;
    for (int k0 = 0; k0 < kend; k0 += 16) {
        float4 av = *(const float4*)(Pr + (size_t)(qs + ar) * Tv + k0 + ac);
        As[ac + 0][ar] = av.x; As[ac + 1][ar] = av.y; As[ac + 2][ar] = av.z; As[ac + 3][ar] = av.w;
        *(float4*)(&Bs[br][bc]) = *(const float4*)(Vr + (size_t)(k0 + br) * Dv + bc);
        __syncthreads();
#pragma unroll
        for (int kk = 0; kk < 16; kk++) {
            float ra[4], rb[4];
#pragma unroll
            for (int i = 0; i < 4; i++) ra[i] = As[kk][ti + i];
#pragma unroll
            for (int j = 0; j < 4; j++) rb[j] = Bs[kk][tc + j];
#pragma unroll
            for (int i = 0; i < 4; i++)
#pragma unroll
                for (int j = 0; j < 4; j++) acc[i][j] += ra[i] * rb[j];
        }
        __syncthreads();
    }
#pragma unroll
    for (int i = 0; i < 4; i++) {
        size_t idx = (size_t)(b * Tv + qs + ti + i) * Cv + h * Dv + tc;
        *(float4*)(O + idx) = make_float4(acc[i][0], acc[i][1], acc[i][2], acc[i][3]);
    }
}

// ============================================================
// Router: logits = clip(h2@Wr + bias, -50, 50); sigmoid; argmax (first max).
// ============================================================
__global__ void router_kernel(const float* __restrict__ h2, const float* __restrict__ Wr,
                              const float* __restrict__ rb)
{
    int n = blockIdx.x, tid = threadIdx.x;
    const float* xr = h2 + (size_t)n * Cv;
    float part[Ev];
#pragma unroll
    for (int e = 0; e < Ev; e++) part[e] = 0.f;
    for (int c = tid; c < Cv; c += TB) {
        float xv = xr[c];
#pragma unroll
        for (int e = 0; e < Ev; e++) part[e] += xv * Wr[c * Ev + e];
    }
    __shared__ float sd[Ev][TB];
#pragma unroll
    for (int e = 0; e < Ev; e++) sd[e][tid] = part[e];
    __syncthreads();
    for (int st = TB / 2; st > 0; st >>= 1) {
        if (tid < st)
#pragma unroll
            for (int e = 0; e < Ev; e++) sd[e][tid] += sd[e][tid + st];
        __syncthreads();
    }
    if (tid == 0) {
        int best = 0; float bp = -1.f;
#pragma unroll
        for (int e = 0; e < Ev; e++) {
            float lg = fminf(fmaxf(sd[e][0] + rb[e], -50.f), 50.f);
            float pr = 1.f / (1.f + expf(-lg));
            if (pr > bp) { bp = pr; best = e; }
        }
        g_sel[n] = best;
        g_p[n]   = fminf(fmaxf(bp, 1e-8f), 1.f - 1e-8f);
    }
}

__global__ void zero_kernel() {
    int t = threadIdx.x;
    if (t < Ev) { g_cnt[t] = 0; g_cur[t] = 0; }
}
__global__ void hist_kernel() {
    int n = blockIdx.x * TB + threadIdx.x;
    if (n < Nv) atomicAdd(&g_cnt[g_sel[n]], 1);
}
__global__ void offsets_kernel() {
    int s = 0;
    for (int e = 0; e < Ev; e++) { g_off[e] = s; s += g_cnt[e]; }
}
__global__ void scatter_kernel() {
    int n = blockIdx.x * TB + threadIdx.x;
    if (n < Nv) {
        int e = g_sel[n];
        int pos = atomicAdd(&g_cur[e], 1);
        g_perm[g_off[e] + pos] = n;
    }
}

__global__ void silumul_kernel(const float* __restrict__ a, const float* __restrict__ b,
                               float* __restrict__ o)
{
    int i = blockIdx.x * TB + threadIdx.x;   // exact grid Nv*Iv
    float v = a[i];
    o[i] = (v / (1.f + expf(-v))) * b[i];
}

// out[n] = x1[n] + (0.5/tw)*shared[n] + (p/tw)*expert_out(compact s)
__global__ void combine_kernel(const float* __restrict__ x1, const float* __restrict__ sh,
                               const float* __restrict__ yc, float* __restrict__ out)
{
    int s = blockIdx.x;
    int n = g_perm[s];
    float p = g_p[n];
    float tw = fminf(fmaxf(0.5f + p + 1e-8f, 0.5f), 2.0f);
    float wsh = 0.5f / tw, wex = p / tw;
    const float* a = x1 + (size_t)n * Cv;
    const float* b = sh + (size_t)n * Cv;
    const float* c = yc + (size_t)s * Cv;
    float* o = out + (size_t)n * Cv;
    for (int i = threadIdx.x; i < Cv; i += TB)
        o[i] = a[i] + wsh * b[i] + wex * c[i];
}

// ============================================================
// launcher
// ============================================================
extern "C" void kernel_launch(void* const* d_in, const int* in_sizes, int n_in,
                              void* d_out, int out_size)
{
    const float* x    = (const float*)d_in[0];
    const float* ln1  = (const float*)d_in[1];
    const float* ln2  = (const float*)d_in[2];
    const float* Wq   = (const float*)d_in[3];
    const float* Wkv  = (const float*)d_in[4];
    const float* Wk_up= (const float*)d_in[5];
    const float* Wv_up= (const float*)d_in[6];
    const float* Wo   = (const float*)d_in[7];
    const float* Wr   = (const float*)d_in[8];
    const float* rb   = (const float*)d_in[9];
    const float* sw1  = (const float*)d_in[10];
    const float* sw2  = (const float*)d_in[11];
    const float* sw3  = (const float*)d_in[12];
    const float* ew1  = (const float*)d_in[13];
    const float* ew2  = (const float*)d_in[14];
    const float* ew3  = (const float*)d_in[15];
    float* out = (float*)d_out;

    float *ph, *pq, *pkv, *pk, *pv, *pS, *pat, *px1, *ph2;
    float *pa1, *pa3, *pu, *psh, *pc1, *pc3, *puc, *pyc;
    cudaGetSymbolAddress((void**)&ph,  g_h);
    cudaGetSymbolAddress((void**)&pq,  g_q);
    cudaGetSymbolAddress((void**)&pkv, g_kv);
    cudaGetSymbolAddress((void**)&pk,  g_k);
    cudaGetSymbolAddress((void**)&pv,  g_v);
    cudaGetSymbolAddress((void**)&pS,  g_S);
    cudaGetSymbolAddress((void**)&pat, g_at);
    cudaGetSymbolAddress((void**)&px1, g_x1);
    cudaGetSymbolAddress((void**)&ph2, g_h2);
    cudaGetSymbolAddress((void**)&pa1, g_a1);
    cudaGetSymbolAddress((void**)&pa3, g_a3);
    cudaGetSymbolAddress((void**)&pu,  g_u);
    cudaGetSymbolAddress((void**)&psh, g_sh);
    cudaGetSymbolAddress((void**)&pc1, g_c1);
    cudaGetSymbolAddress((void**)&pc3, g_c3);
    cudaGetSymbolAddress((void**)&puc, g_uc);
    cudaGetSymbolAddress((void**)&pyc, g_yc);

    // ---- attention ----
    rmsnorm_kernel<<<Nv, TB>>>(x, ln1, ph);
    sgemm128<<<dim3(Cv / 128, Nv / 128), TB>>>(ph, Wq,  pq,  nullptr, Cv, Cv, 1.f);
    sgemm128<<<dim3(Lv / 128, Nv / 128), TB>>>(ph, Wkv, pkv, nullptr, Cv, Lv, 0.25f);
    kvup_kernel<<<dim3(Nv / 64, 1, Hv), TB>>>(pkv, Wk_up, pk);
    kvup_kernel<<<dim3(Nv / 64, 1, Hv), TB>>>(pkv, Wv_up, pv);
    rope_kernel<<<(Nv * Hv * 32) / TB, TB>>>(pq, Hv);
    rope_kernel<<<(Nv * Hv * 32) / TB, TB>>>(pk, 1);
    scores_kernel<<<dim3(Tv / 64, Tv / 64, BHv), TB>>>(pq, pk, pS);
    softmax_kernel<<<BHv * Tv, TB>>>(pS);
    av_kernel<<<dim3(Tv / 64, 1, BHv), TB>>>(pS, pv, pat);
    sgemm128<<<dim3(Cv / 128, Nv / 128), TB>>>(pat, Wo, px1, x, Cv, Cv, 1.f);   // + residual x

    // ---- MoE ----
    rmsnorm_kernel<<<Nv, TB>>>(px1, ln2, ph2);
    router_kernel<<<Nv, TB>>>(ph2, Wr, rb);
    zero_kernel<<<1, 32>>>();
    hist_kernel<<<Nv / TB, TB>>>();
    offsets_kernel<<<1, 1>>>();
    scatter_kernel<<<Nv / TB, TB>>>();

    // shared expert
    sgemm128<<<dim3(Iv / 128, Nv / 128), TB>>>(ph2, sw1, pa1, nullptr, Cv, Iv, 1.f);
    sgemm128<<<dim3(Iv / 128, Nv / 128), TB>>>(ph2, sw3, pa3, nullptr, Cv, Iv, 1.f);
    silumul_kernel<<<(Nv * Iv) / TB, TB>>>(pa1, pa3, pu);
    sgemm128<<<dim3(Cv / 128, Nv / 128), TB>>>(pu, sw2, psh, nullptr, Iv, Cv, 1.f);

    // routed experts (grouped, gathered)
    gg_sgemm<true ><<<dim3(Nv / 128, Iv / 128, Ev), TB>>>(ph2, ew1, (size_t)Cv * Iv, Cv, Iv, pc1);
    gg_sgemm<true ><<<dim3(Nv / 128, Iv / 128, Ev), TB>>>(ph2, ew3, (size_t)Cv * Iv, Cv, Iv, pc3);
    silumul_kernel<<<(Nv * Iv) / TB, TB>>>(pc1, pc3, puc);
    gg_sgemm<false><<<dim3(Nv / 128, Cv / 128, Ev), TB>>>(puc, ew2, (size_t)Iv * Cv, Iv, Cv, pyc);

    // combine + residual
    combine_kernel<<<Nv, TB>>>(px1, psh, pyc, out);
}

// round 2
// speedup vs baseline: 1.3343x; 1.3343x over previous
#include <cuda_runtime.h>
#include <mma.h>
#include <cstdint>

using namespace nvcuda;

#define TB 256

// ---- problem constants ----
constexpr int Bv = 8, Tv = 1024, Hv = 16, Dv = 64, Cv = 1024, Lv = 256, Ev = 8, Iv = 2048;
constexpr int Nv  = Bv * Tv;   // 8192 tokens
constexpr int BHv = Bv * Hv;   // 128

// ---- scratch (device globals; allocation-free) ----
__device__ float g_h  [Nv * Cv];
__device__ float g_q  [Nv * Cv];
__device__ float g_kv [Nv * Lv];
__device__ float g_k  [Nv * Cv];          // [b,h,t,d]
__device__ float g_v  [Nv * Cv];          // [b,h,t,d]
__device__ float g_S  [(size_t)BHv * Tv * Tv];   // scores / probs (512 MB)
__device__ float g_at [Nv * Cv];
__device__ float g_x1 [Nv * Cv];
__device__ float g_h2 [Nv * Cv];
__device__ float g_a1 [Nv * Iv];
__device__ float g_a3 [Nv * Iv];
__device__ float g_u  [Nv * Iv];
__device__ float g_sh [Nv * Cv];
__device__ float g_c1 [Nv * Iv];
__device__ float g_c3 [Nv * Iv];
__device__ float g_uc [Nv * Iv];
__device__ float g_yc [Nv * Cv];
__device__ int   g_sel[Nv];
__device__ float g_p  [Nv];
__device__ int   g_cnt[Ev];
__device__ int   g_off[Ev];
__device__ int   g_cur[Ev];
__device__ int   g_perm[Nv];

__device__ __forceinline__ float to_tf32(float x) {
    float r; asm("cvt.rna.tf32.f32 %0, %1;" : "=f"(r) : "f"(x)); return r;
}

// ============================================================
// RMSNorm: one block per token
// ============================================================
__global__ void rmsnorm_kernel(const float* __restrict__ x, const float* __restrict__ w,
                               float* __restrict__ y)
{
    int n = blockIdx.x, tid = threadIdx.x;
    const float* xr = x + (size_t)n * Cv;
    __shared__ float red[TB];
    float ss = 0.f;
    for (int c = tid; c < Cv; c += TB) { float v = xr[c]; ss += v * v; }
    red[tid] = ss; __syncthreads();
    for (int s = TB / 2; s > 0; s >>= 1) { if (tid < s) red[tid] += red[tid + s]; __syncthreads(); }
    float rs = rsqrtf(red[0] / (float)Cv + 1e-6f);
    float* yr = y + (size_t)n * Cv;
    for (int c = tid; c < Cv; c += TB) yr[c] = xr[c] * rs * w[c];
}

// ============================================================
// TF32 tensor-core GEMM: C = alpha*A(MxK)@B(KxN) (+Res).
// M,N multiples of 128, K multiple of 32.
// Block 256 thr = 8 warps (4x2); warp tile 32x64; wmma m16n16k8 tf32.
// ============================================================
__global__ void tgemm(const float* __restrict__ A, const float* __restrict__ B,
                      float* __restrict__ Cmat, const float* __restrict__ Res,
                      int K, int N, float alpha)
{
    __shared__ float As[128][36];
    __shared__ float Bs[32][132];
    const int tid  = threadIdx.x;
    const int warp = tid >> 5;
    const int wm   = warp & 3, wn = warp >> 2;
    const int bm   = blockIdx.y * 128, bn = blockIdx.x * 128;

    wmma::fragment<wmma::accumulator, 16, 16, 8, float> acc[2][4];
#pragma unroll
    for (int mi = 0; mi < 2; mi++)
#pragma unroll
        for (int ni = 0; ni < 4; ni++) wmma::fill_fragment(acc[mi][ni], 0.f);

    const int ar0 = tid >> 3, ac = (tid & 7) << 2;
    const int br0 = tid >> 5, bc = (tid & 31) << 2;

    for (int k0 = 0; k0 < K; k0 += 32) {
#pragma unroll
        for (int i = 0; i < 4; i++) {
            int r = ar0 + (i << 5);
            float4 v = *(const float4*)(A + (size_t)(bm + r) * K + k0 + ac);
            As[r][ac + 0] = to_tf32(v.x); As[r][ac + 1] = to_tf32(v.y);
            As[r][ac + 2] = to_tf32(v.z); As[r][ac + 3] = to_tf32(v.w);
        }
#pragma unroll
        for (int i = 0; i < 4; i++) {
            int r = br0 + (i << 3);
            float4 v = *(const float4*)(B + (size_t)(k0 + r) * N + bn + bc);
            Bs[r][bc + 0] = to_tf32(v.x); Bs[r][bc + 1] = to_tf32(v.y);
            Bs[r][bc + 2] = to_tf32(v.z); Bs[r][bc + 3] = to_tf32(v.w);
        }
        __syncthreads();
#pragma unroll
        for (int k8 = 0; k8 < 32; k8 += 8) {
            wmma::fragment<wmma::matrix_a, 16, 16, 8, wmma::precision::tf32, wmma::row_major> af[2];
            wmma::fragment<wmma::matrix_b, 16, 16, 8, wmma::precision::tf32, wmma::row_major> bf[4];
#pragma unroll
            for (int mi = 0; mi < 2; mi++)
                wmma::load_matrix_sync(af[mi], &As[wm * 32 + mi * 16][k8], 36);
#pragma unroll
            for (int ni = 0; ni < 4; ni++)
                wmma::load_matrix_sync(bf[ni], &Bs[k8][wn * 64 + ni * 16], 132);
#pragma unroll
            for (int mi = 0; mi < 2; mi++)
#pragma unroll
                for (int ni = 0; ni < 4; ni++)
                    wmma::mma_sync(acc[mi][ni], af[mi], bf[ni], acc[mi][ni]);
        }
        __syncthreads();
    }

#pragma unroll
    for (int mi = 0; mi < 2; mi++)
#pragma unroll
        for (int ni = 0; ni < 4; ni++) {
            size_t row = (size_t)(bm + wm * 32 + mi * 16);
            size_t col = (size_t)(bn + wn * 64 + ni * 16);
            float* cp = Cmat + row * N + col;
            if (Res) {
                wmma::fragment<wmma::accumulator, 16, 16, 8, float> rf;
                wmma::load_matrix_sync(rf, Res + row * N + col, N, wmma::mem_row_major);
#pragma unroll
                for (int t = 0; t < rf.num_elements; t++)
                    acc[mi][ni].x[t] = acc[mi][ni].x[t] * alpha + rf.x[t];
            } else if (alpha != 1.f) {
#pragma unroll
                for (int t = 0; t < acc[mi][ni].num_elements; t++)
                    acc[mi][ni].x[t] *= alpha;
            }
            wmma::store_matrix_sync(cp, acc[mi][ni], N, wmma::mem_row_major);
        }
}

// ============================================================
// Grouped (per-expert) TF32 GEMM with optional row gather.
// A rows gathered via g_perm (GATHER) or compact (off+lr).
// Out: compact row-major [Nv x N]. Staged epilogue for row bounds.
// ============================================================
template <bool GATHER>
__global__ void gg_tgemm(const float* __restrict__ A, const float* __restrict__ Bbase,
                         size_t strideB, int K, int N, float* __restrict__ Out)
{
    int e = blockIdx.z;
    int cnt = g_cnt[e];
    int base = blockIdx.x * 128;
    if (base >= cnt) return;
    int o = g_off[e];
    const float* B = Bbase + (size_t)e * strideB;

    __shared__ float As[128][36];
    __shared__ float Bs[32][132];
    const int tid  = threadIdx.x;
    const int warp = tid >> 5;
    const int lane = tid & 31;
    const int wm   = warp & 3, wn = warp >> 2;
    const int bn   = blockIdx.y * 128;

    wmma::fragment<wmma::accumulator, 16, 16, 8, float> acc[2][4];
#pragma unroll
    for (int mi = 0; mi < 2; mi++)
#pragma unroll
        for (int ni = 0; ni < 4; ni++) wmma::fill_fragment(acc[mi][ni], 0.f);

    const int ar0 = tid >> 3, ac = (tid & 7) << 2;
    const int br0 = tid >> 5, bc = (tid & 31) << 2;

    for (int k0 = 0; k0 < K; k0 += 32) {
#pragma unroll
        for (int i = 0; i < 4; i++) {
            int r = ar0 + (i << 5);
            int lr = base + r;
            float4 v = make_float4(0.f, 0.f, 0.f, 0.f);
            if (lr < cnt) {
                int grow = GATHER ? g_perm[o + lr] : (o + lr);
                v = *(const float4*)(A + (size_t)grow * K + k0 + ac);
            }
            As[r][ac + 0] = to_tf32(v.x); As[r][ac + 1] = to_tf32(v.y);
            As[r][ac + 2] = to_tf32(v.z); As[r][ac + 3] = to_tf32(v.w);
        }
#pragma unroll
        for (int i = 0; i < 4; i++) {
            int r = br0 + (i << 3);
            float4 v = *(const float4*)(B + (size_t)(k0 + r) * N + bn + bc);
            Bs[r][bc + 0] = to_tf32(v.x); Bs[r][bc + 1] = to_tf32(v.y);
            Bs[r][bc + 2] = to_tf32(v.z); Bs[r][bc + 3] = to_tf32(v.w);
        }
        __syncthreads();
#pragma unroll
        for (int k8 = 0; k8 < 32; k8 += 8) {
            wmma::fragment<wmma::matrix_a, 16, 16, 8, wmma::precision::tf32, wmma::row_major> af[2];
            wmma::fragment<wmma::matrix_b, 16, 16, 8, wmma::precision::tf32, wmma::row_major> bf[4];
#pragma unroll
            for (int mi = 0; mi < 2; mi++)
                wmma::load_matrix_sync(af[mi], &As[wm * 32 + mi * 16][k8], 36);
#pragma unroll
            for (int ni = 0; ni < 4; ni++)
                wmma::load_matrix_sync(bf[ni], &Bs[k8][wn * 64 + ni * 16], 132);
#pragma unroll
            for (int mi = 0; mi < 2; mi++)
#pragma unroll
                for (int ni = 0; ni < 4; ni++)
                    wmma::mma_sync(acc[mi][ni], af[mi], bf[ni], acc[mi][ni]);
        }
        __syncthreads();
    }

    // Staged epilogue: per-warp 16x16 tile through smem for per-row bounds check.
    float* stage = &As[0][0] + warp * 320;   // 16 rows x ldm 20
    const int sr = lane >> 1, sc0 = (lane & 1) << 3;
#pragma unroll
    for (int mi = 0; mi < 2; mi++)
#pragma unroll
        for (int ni = 0; ni < 4; ni++) {
            wmma::store_matrix_sync(stage, acc[mi][ni], 20, wmma::mem_row_major);
            __syncwarp();
            int lr = base + wm * 32 + mi * 16 + sr;
            if (lr < cnt) {
                size_t row = (size_t)(o + lr);
                int col = bn + wn * 64 + ni * 16 + sc0;
                float4 v0 = *(float4*)(stage + sr * 20 + sc0);
                float4 v1 = *(float4*)(stage + sr * 20 + sc0 + 4);
                *(float4*)(Out + row * N + col)     = v0;
                *(float4*)(Out + row * N + col + 4) = v1;
            }
            __syncwarp();
        }
}

// ============================================================
// K/V up-projection per head: out[b,h,t,:] = kv[n,:] @ Wup[h] (L=256 x D=64)
// ============================================================
__global__ void kvup_kernel(const float* __restrict__ kv, const float* __restrict__ Wup,
                            float* __restrict__ outb)
{
    int h = blockIdx.z;
    int bm = blockIdx.x * 64;
    const float* Bm = Wup + (size_t)h * Lv * Dv;
    __shared__ float As[16][65];
    __shared__ float Bs[16][64];
    const int tid = threadIdx.x;
    const int ar = tid >> 2,        ac = (tid & 3) << 2;
    const int br = tid >> 4,        bc = (tid & 15) << 2;
    const int ti = (tid >> 4) << 2, tc = (tid & 15) << 2;
    float acc[4][4];
#pragma unroll
    for (int i = 0; i < 4; i++)
#pragma unroll
        for (int j = 0; j < 4; j++) acc[i][j] = 0.f;

    for (int k0 = 0; k0 < Lv; k0 += 16) {
        float4 av = *(const float4*)(kv + (size_t)(bm + ar) * Lv + k0 + ac);
        As[ac + 0][ar] = av.x; As[ac + 1][ar] = av.y; As[ac + 2][ar] = av.z; As[ac + 3][ar] = av.w;
        *(float4*)(&Bs[br][bc]) = *(const float4*)(Bm + (size_t)(k0 + br) * Dv + bc);
        __syncthreads();
#pragma unroll
        for (int kk = 0; kk < 16; kk++) {
            float ra[4], rb[4];
#pragma unroll
            for (int i = 0; i < 4; i++) ra[i] = As[kk][ti + i];
#pragma unroll
            for (int j = 0; j < 4; j++) rb[j] = Bs[kk][tc + j];
#pragma unroll
            for (int i = 0; i < 4; i++)
#pragma unroll
                for (int j = 0; j < 4; j++) acc[i][j] += ra[i] * rb[j];
        }
        __syncthreads();
    }
#pragma unroll
    for (int i = 0; i < 4; i++) {
        int n = bm + ti + i;
        int b = n >> 10, t = n & 1023;
        size_t idx = ((size_t)(b * Hv + h) * Tv + t) * Dv + tc;
        *(float4*)(outb + idx) = make_float4(acc[i][0], acc[i][1], acc[i][2], acc[i][3]);
    }
}

// ============================================================
// RoPE in place on 64-wide head vectors. posDiv: Hv for q-layout, 1 for k-layout.
// ============================================================
__global__ void rope_kernel(float* __restrict__ xp, int posDiv)
{
    int idx = blockIdx.x * TB + threadIdx.x;   // pair index; exact grid
    int outer = idx >> 5;
    int j = idx & 31;
    int pos = (outer / posDiv) & (Tv - 1);
    float invf = powf(100000.0f, -(float)j * (1.0f / 32.0f));
    float f = (float)pos * invf;
    float s, c; sincosf(f, &s, &c);
    float* p = xp + (size_t)outer * Dv;
    float x1 = p[j], x2 = p[j + 32];
    p[j]      = x1 * c - x2 * s;
    p[j + 32] = x1 * s + x2 * c;
}

// ============================================================
// Attention scores: S[bh, t, s] = (q_t . k_s) / 8, causal tile skip.
// ============================================================
__global__ void scores_kernel(const float* __restrict__ q, const float* __restrict__ k,
                              float* __restrict__ S)
{
    int bh = blockIdx.z, b = bh >> 4, h = bh & 15;
    int qs = blockIdx.y * 64, ks = blockIdx.x * 64;
    if (ks > qs) return;   // fully masked tile
    __shared__ float Qs[64][65];
    __shared__ float Ks[64][65];
    const int tid = threadIdx.x;
    const int r = tid >> 2, c0 = tid & 3;
#pragma unroll
    for (int i = 0; i < 4; i++) {
        int col = (c0 + 4 * i) << 2;
        float4 v = *(const float4*)(q + (size_t)(b * Tv + qs + r) * Cv + h * Dv + col);
        Qs[r][col] = v.x; Qs[r][col + 1] = v.y; Qs[r][col + 2] = v.z; Qs[r][col + 3] = v.w;
        float4 w = *(const float4*)(k + ((size_t)bh * Tv + ks + r) * Dv + col);
        Ks[r][col] = w.x; Ks[r][col + 1] = w.y; Ks[r][col + 2] = w.z; Ks[r][col + 3] = w.w;
    }
    __syncthreads();
    const int ti = (tid >> 4) << 2, tj = (tid & 15) << 2;
    float acc[4][4];
#pragma unroll
    for (int i = 0; i < 4; i++)
#pragma unroll
        for (int j = 0; j < 4; j++) acc[i][j] = 0.f;
#pragma unroll
    for (int d = 0; d < 64; d++) {
        float ra[4], rb[4];
#pragma unroll
        for (int i = 0; i < 4; i++) ra[i] = Qs[ti + i][d];
#pragma unroll
        for (int j = 0; j < 4; j++) rb[j] = Ks[tj + j][d];
#pragma unroll
        for (int i = 0; i < 4; i++)
#pragma unroll
            for (int j = 0; j < 4; j++) acc[i][j] += ra[i] * rb[j];
    }
#pragma unroll
    for (int i = 0; i < 4; i++) {
        size_t idx = ((size_t)bh * Tv + qs + ti + i) * Tv + ks + tj;
        *(float4*)(S + idx) = make_float4(acc[i][0] * 0.125f, acc[i][1] * 0.125f,
                                          acc[i][2] * 0.125f, acc[i][3] * 0.125f);
    }
}

// ============================================================
// Causal row softmax in place; zeros masked tail. One block per (bh,t).
// ============================================================
__global__ void softmax_kernel(float* __restrict__ S)
{
    long long row = blockIdx.x;
    int t = (int)(row & (Tv - 1));
    float* Sr = S + row * (long long)Tv;
    int len = t + 1;
    int tid = threadIdx.x;
    __shared__ float red[TB];
    float m = -1e30f;
    for (int s = tid; s < len; s += TB) m = fmaxf(m, Sr[s]);
    red[tid] = m; __syncthreads();
    for (int st = TB / 2; st > 0; st >>= 1) { if (tid < st) red[tid] = fmaxf(red[tid], red[tid + st]); __syncthreads(); }
    float rowmax = red[0];
    __syncthreads();
    float sum = 0.f;
    for (int s = tid; s < len; s += TB) sum += expf(Sr[s] - rowmax);
    red[tid] = sum; __syncthreads();
    for (int st = TB / 2; st > 0; st >>= 1) { if (tid < st) red[tid] += red[tid + st]; __syncthreads(); }
    float inv = 1.f / red[0];
    for (int s = tid; s < Tv; s += TB)
        Sr[s] = (s < len) ? expf(Sr[s] - rowmax) * inv : 0.f;
}

// ============================================================
// O = P @ V per (b,h); causal K-bound. Output token-major [n][h*D+d].
// ============================================================
__global__ void av_kernel(const float* __restrict__ P, const float* __restrict__ V,
                          float* __restrict__ O)
{
    int bh = blockIdx.z, b = bh >> 4, h = bh & 15;
    int qs = blockIdx.x * 64;
    const float* Pr = P + (size_t)bh * Tv * Tv;
    const float* Vr = V + (size_t)bh * Tv * Dv;
    __shared__ float As[16][65];
    __shared__ float Bs[16][64];
    const int tid = threadIdx.x;
    const int ar = tid >> 2,        ac = (tid & 3) << 2;
    const int br = tid >> 4,        bc = (tid & 15) << 2;
    const int ti = (tid >> 4) << 2, tc = (tid & 15) << 2;
    float acc[4][4];
#pragma unroll
    for (int i = 0; i < 4; i++)
#pragma unroll
        for (int j = 0; j < 4; j++) acc[i][j] = 0.f;

    int kend = qs + 64;
    for (int k0 = 0; k0 < kend; k0 += 16) {
        float4 av = *(const float4*)(Pr + (size_t)(qs + ar) * Tv + k0 + ac);
        As[ac + 0][ar] = av.x; As[ac + 1][ar] = av.y; As[ac + 2][ar] = av.z; As[ac + 3][ar] = av.w;
        *(float4*)(&Bs[br][bc]) = *(const float4*)(Vr + (size_t)(k0 + br) * Dv + bc);
        __syncthreads();
#pragma unroll
        for (int kk = 0; kk < 16; kk++) {
            float ra[4], rb[4];
#pragma unroll
            for (int i = 0; i < 4; i++) ra[i] = As[kk][ti + i];
#pragma unroll
            for (int j = 0; j < 4; j++) rb[j] = Bs[kk][tc + j];
#pragma unroll
            for (int i = 0; i < 4; i++)
#pragma unroll
                for (int j = 0; j < 4; j++) acc[i][j] += ra[i] * rb[j];
        }
        __syncthreads();
    }
#pragma unroll
    for (int i = 0; i < 4; i++) {
        size_t idx = (size_t)(b * Tv + qs + ti + i) * Cv + h * Dv + tc;
        *(float4*)(O + idx) = make_float4(acc[i][0], acc[i][1], acc[i][2], acc[i][3]);
    }
}

// ============================================================
// Router: logits = clip(h2@Wr + bias, -50, 50); sigmoid; argmax (first max).
// ============================================================
__global__ void router_kernel(const float* __restrict__ h2, const float* __restrict__ Wr,
                              const float* __restrict__ rb)
{
    int n = blockIdx.x, tid = threadIdx.x;
    const float* xr = h2 + (size_t)n * Cv;
    float part[Ev];
#pragma unroll
    for (int e = 0; e < Ev; e++) part[e] = 0.f;
    for (int c = tid; c < Cv; c += TB) {
        float xv = xr[c];
#pragma unroll
        for (int e = 0; e < Ev; e++) part[e] += xv * Wr[c * Ev + e];
    }
    __shared__ float sd[Ev][TB];
#pragma unroll
    for (int e = 0; e < Ev; e++) sd[e][tid] = part[e];
    __syncthreads();
    for (int st = TB / 2; st > 0; st >>= 1) {
        if (tid < st)
#pragma unroll
            for (int e = 0; e < Ev; e++) sd[e][tid] += sd[e][tid + st];
        __syncthreads();
    }
    if (tid == 0) {
        int best = 0; float bp = -1.f;
#pragma unroll
        for (int e = 0; e < Ev; e++) {
            float lg = fminf(fmaxf(sd[e][0] + rb[e], -50.f), 50.f);
            float pr = 1.f / (1.f + expf(-lg));
            if (pr > bp) { bp = pr; best = e; }
        }
        g_sel[n] = best;
        g_p[n]   = fminf(fmaxf(bp, 1e-8f), 1.f - 1e-8f);
    }
}

__global__ void zero_kernel() {
    int t = threadIdx.x;
    if (t < Ev) { g_cnt[t] = 0; g_cur[t] = 0; }
}
__global__ void hist_kernel() {
    int n = blockIdx.x * TB + threadIdx.x;
    if (n < Nv) atomicAdd(&g_cnt[g_sel[n]], 1);
}
__global__ void offsets_kernel() {
    int s = 0;
    for (int e = 0; e < Ev; e++) { g_off[e] = s; s += g_cnt[e]; }
}
__global__ void scatter_kernel() {
    int n = blockIdx.x * TB + threadIdx.x;
    if (n < Nv) {
        int e = g_sel[n];
        int pos = atomicAdd(&g_cur[e], 1);
        g_perm[g_off[e] + pos] = n;
    }
}

__global__ void silumul_kernel(const float* __restrict__ a, const float* __restrict__ b,
                               float* __restrict__ o)
{
    int i = blockIdx.x * TB + threadIdx.x;   // exact grid Nv*Iv
    float v = a[i];
    o[i] = (v / (1.f + expf(-v))) * b[i];
}

// out[n] = x1[n] + (0.5/tw)*shared[n] + (p/tw)*expert_out(compact s)
__global__ void combine_kernel(const float* __restrict__ x1, const float* __restrict__ sh,
                               const float* __restrict__ yc, float* __restrict__ out)
{
    int s = blockIdx.x;
    int n = g_perm[s];
    float p = g_p[n];
    float tw = fminf(fmaxf(0.5f + p + 1e-8f, 0.5f), 2.0f);
    float wsh = 0.5f / tw, wex = p / tw;
    const float* a = x1 + (size_t)n * Cv;
    const float* b = sh + (size_t)n * Cv;
    const float* c = yc + (size_t)s * Cv;
    float* o = out + (size_t)n * Cv;
    for (int i = threadIdx.x; i < Cv; i += TB)
        o[i] = a[i] + wsh * b[i] + wex * c[i];
}

// ============================================================
// launcher
// ============================================================
extern "C" void kernel_launch(void* const* d_in, const int* in_sizes, int n_in,
                              void* d_out, int out_size)
{
    const float* x    = (const float*)d_in[0];
    const float* ln1  = (const float*)d_in[1];
    const float* ln2  = (const float*)d_in[2];
    const float* Wq   = (const float*)d_in[3];
    const float* Wkv  = (const float*)d_in[4];
    const float* Wk_up= (const float*)d_in[5];
    const float* Wv_up= (const float*)d_in[6];
    const float* Wo   = (const float*)d_in[7];
    const float* Wr   = (const float*)d_in[8];
    const float* rb   = (const float*)d_in[9];
    const float* sw1  = (const float*)d_in[10];
    const float* sw2  = (const float*)d_in[11];
    const float* sw3  = (const float*)d_in[12];
    const float* ew1  = (const float*)d_in[13];
    const float* ew2  = (const float*)d_in[14];
    const float* ew3  = (const float*)d_in[15];
    float* out = (float*)d_out;

    float *ph, *pq, *pkv, *pk, *pv, *pS, *pat, *px1, *ph2;
    float *pa1, *pa3, *pu, *psh, *pc1, *pc3, *puc, *pyc;
    cudaGetSymbolAddress((void**)&ph,  g_h);
    cudaGetSymbolAddress((void**)&pq,  g_q);
    cudaGetSymbolAddress((void**)&pkv, g_kv);
    cudaGetSymbolAddress((void**)&pk,  g_k);
    cudaGetSymbolAddress((void**)&pv,  g_v);
    cudaGetSymbolAddress((void**)&pS,  g_S);
    cudaGetSymbolAddress((void**)&pat, g_at);
    cudaGetSymbolAddress((void**)&px1, g_x1);
    cudaGetSymbolAddress((void**)&ph2, g_h2);
    cudaGetSymbolAddress((void**)&pa1, g_a1);
    cudaGetSymbolAddress((void**)&pa3, g_a3);
    cudaGetSymbolAddress((void**)&pu,  g_u);
    cudaGetSymbolAddress((void**)&psh, g_sh);
    cudaGetSymbolAddress((void**)&pc1, g_c1);
    cudaGetSymbolAddress((void**)&pc3, g_c3);
    cudaGetSymbolAddress((void**)&puc, g_uc);
    cudaGetSymbolAddress((void**)&pyc, g_yc);

    // ---- attention ----
    rmsnorm_kernel<<<Nv, TB>>>(x, ln1, ph);
    tgemm<<<dim3(Cv / 128, Nv / 128), TB>>>(ph, Wq,  pq,  nullptr, Cv, Cv, 1.f);
    tgemm<<<dim3(Lv / 128, Nv / 128), TB>>>(ph, Wkv, pkv, nullptr, Cv, Lv, 0.25f);
    kvup_kernel<<<dim3(Nv / 64, 1, Hv), TB>>>(pkv, Wk_up, pk);
    kvup_kernel<<<dim3(Nv / 64, 1, Hv), TB>>>(pkv, Wv_up, pv);
    rope_kernel<<<(Nv * Hv * 32) / TB, TB>>>(pq, Hv);
    rope_kernel<<<(Nv * Hv * 32) / TB, TB>>>(pk, 1);
    scores_kernel<<<dim3(Tv / 64, Tv / 64, BHv), TB>>>(pq, pk, pS);
    softmax_kernel<<<BHv * Tv, TB>>>(pS);
    av_kernel<<<dim3(Tv / 64, 1, BHv), TB>>>(pS, pv, pat);
    tgemm<<<dim3(Cv / 128, Nv / 128), TB>>>(pat, Wo, px1, x, Cv, Cv, 1.f);   // + residual x

    // ---- MoE ----
    rmsnorm_kernel<<<Nv, TB>>>(px1, ln2, ph2);
    router_kernel<<<Nv, TB>>>(ph2, Wr, rb);
    zero_kernel<<<1, 32>>>();
    hist_kernel<<<Nv / TB, TB>>>();
    offsets_kernel<<<1, 1>>>();
    scatter_kernel<<<Nv / TB, TB>>>();

    // shared expert
    tgemm<<<dim3(Iv / 128, Nv / 128), TB>>>(ph2, sw1, pa1, nullptr, Cv, Iv, 1.f);
    tgemm<<<dim3(Iv / 128, Nv / 128), TB>>>(ph2, sw3, pa3, nullptr, Cv, Iv, 1.f);
    silumul_kernel<<<(Nv * Iv) / TB, TB>>>(pa1, pa3, pu);
    tgemm<<<dim3(Cv / 128, Nv / 128), TB>>>(pu, sw2, psh, nullptr, Iv, Cv, 1.f);

    // routed experts (grouped, gathered)
    gg_tgemm<true ><<<dim3(Nv / 128, Iv / 128, Ev), TB>>>(ph2, ew1, (size_t)Cv * Iv, Cv, Iv, pc1);
    gg_tgemm<true ><<<dim3(Nv / 128, Iv / 128, Ev), TB>>>(ph2, ew3, (size_t)Cv * Iv, Cv, Iv, pc3);
    silumul_kernel<<<(Nv * Iv) / TB, TB>>>(pc1, pc3, puc);
    gg_tgemm<false><<<dim3(Nv / 128, Cv / 128, Ev), TB>>>(puc, ew2, (size_t)Iv * Cv, Iv, Cv, pyc);

    // combine + residual
    combine_kernel<<<Nv, TB>>>(px1, psh, pyc, out);
}

// round 3
// speedup vs baseline: 2.2766x; 1.7062x over previous
#include <cuda_runtime.h>
#include <cuda_bf16.h>
#include <mma.h>
#include <cstdint>

using namespace nvcuda;

#define TB 256

// ---- problem constants ----
constexpr int Bv = 8, Tv = 1024, Hv = 16, Dv = 64, Cv = 1024, Lv = 256, Ev = 8, Iv = 2048;
constexpr int Nv  = Bv * Tv;   // 8192 tokens
constexpr int BHv = Bv * Hv;   // 128

// ---- scratch (device globals; allocation-free) ----
__device__ float g_h  [Nv * Cv];
__device__ float g_q  [Nv * Cv];
__device__ float g_kv [Nv * Lv];
__device__ float g_k  [Nv * Cv];          // [b,h,t,d]
__device__ float g_v  [Nv * Cv];          // [b,h,t,d]
__device__ float g_S  [(size_t)BHv * Tv * Tv];   // scores / probs (512 MB)
__device__ float g_at [Nv * Cv];
__device__ float g_x1 [Nv * Cv];
__device__ float g_h2 [Nv * Cv];
__device__ float g_a1 [Nv * Iv];
__device__ float g_a3 [Nv * Iv];
__device__ float g_u  [Nv * Iv];
__device__ float g_sh [Nv * Cv];
__device__ float g_c1 [Nv * Iv];
__device__ float g_c3 [Nv * Iv];
__device__ float g_uc [Nv * Iv];
__device__ float g_yc [Nv * Cv];
__device__ int   g_sel[Nv];
__device__ float g_p  [Nv];
__device__ int   g_cnt[Ev];
__device__ int   g_off[Ev];
__device__ int   g_cur[Ev];
__device__ int   g_perm[Nv];

__device__ __forceinline__ uint2 f4_to_bf4(float4 v) {
    __nv_bfloat162 lo = __floats2bfloat162_rn(v.x, v.y);
    __nv_bfloat162 hi = __floats2bfloat162_rn(v.z, v.w);
    uint2 r;
    r.x = *reinterpret_cast<unsigned int*>(&lo);
    r.y = *reinterpret_cast<unsigned int*>(&hi);
    return r;
}

// ============================================================
// RMSNorm: one block per token
// ============================================================
__global__ void rmsnorm_kernel(const float* __restrict__ x, const float* __restrict__ w,
                               float* __restrict__ y)
{
    int n = blockIdx.x, tid = threadIdx.x;
    const float* xr = x + (size_t)n * Cv;
    __shared__ float red[TB];
    float ss = 0.f;
    for (int c = tid; c < Cv; c += TB) { float v = xr[c]; ss += v * v; }
    red[tid] = ss; __syncthreads();
    for (int s = TB / 2; s > 0; s >>= 1) { if (tid < s) red[tid] += red[tid + s]; __syncthreads(); }
    float rs = rsqrtf(red[0] / (float)Cv + 1e-6f);
    float* yr = y + (size_t)n * Cv;
    for (int c = tid; c < Cv; c += TB) yr[c] = xr[c] * rs * w[c];
}

// ============================================================
// BF16 tensor-core GEMM: C = alpha*A(MxK)@B(KxN) (+Res).
// M,N multiples of 128, K multiple of 32. fp32 accumulate.
// Block 256 thr = 8 warps (4x2); warp tile 32x64; double-buffered smem.
// ============================================================
__global__ void tgemm(const float* __restrict__ A, const float* __restrict__ B,
                      float* __restrict__ Cmat, const float* __restrict__ Res,
                      int K, int N, float alpha)
{
    __shared__ __nv_bfloat16 As[2][128][40];
    __shared__ __nv_bfloat16 Bs[2][32][136];
    const int tid  = threadIdx.x;
    const int warp = tid >> 5;
    const int wm   = warp & 3, wn = warp >> 2;
    const int bm   = blockIdx.y * 128, bn = blockIdx.x * 128;

    wmma::fragment<wmma::accumulator, 16, 16, 16, float> acc[2][4];
#pragma unroll
    for (int mi = 0; mi < 2; mi++)
#pragma unroll
        for (int ni = 0; ni < 4; ni++) wmma::fill_fragment(acc[mi][ni], 0.f);

    const int ar0 = tid >> 3, ac = (tid & 7) << 2;
    const int br0 = tid >> 5, bc = (tid & 31) << 2;

    float4 aR[4], bR[4];
    const int nch = K >> 5;

    // prologue: chunk 0
#pragma unroll
    for (int i = 0; i < 4; i++)
        aR[i] = *(const float4*)(A + (size_t)(bm + ar0 + (i << 5)) * K + ac);
#pragma unroll
    for (int i = 0; i < 4; i++)
        bR[i] = *(const float4*)(B + (size_t)(br0 + (i << 3)) * N + bn + bc);
#pragma unroll
    for (int i = 0; i < 4; i++)
        *(uint2*)&As[0][ar0 + (i << 5)][ac] = f4_to_bf4(aR[i]);
#pragma unroll
    for (int i = 0; i < 4; i++)
        *(uint2*)&Bs[0][br0 + (i << 3)][bc] = f4_to_bf4(bR[i]);
    __syncthreads();

    int cur = 0;
    for (int ch = 0; ch < nch; ch++) {
        bool has = (ch + 1) < nch;
        if (has) {
            int k0 = (ch + 1) << 5;
#pragma unroll
            for (int i = 0; i < 4; i++)
                aR[i] = *(const float4*)(A + (size_t)(bm + ar0 + (i << 5)) * K + k0 + ac);
#pragma unroll
            for (int i = 0; i < 4; i++)
                bR[i] = *(const float4*)(B + (size_t)(k0 + br0 + (i << 3)) * N + bn + bc);
        }
#pragma unroll
        for (int ks = 0; ks < 2; ks++) {
            int k16 = ks << 4;
            wmma::fragment<wmma::matrix_a, 16, 16, 16, __nv_bfloat16, wmma::row_major> af[2];
            wmma::fragment<wmma::matrix_b, 16, 16, 16, __nv_bfloat16, wmma::row_major> bf[4];
#pragma unroll
            for (int mi = 0; mi < 2; mi++)
                wmma::load_matrix_sync(af[mi], &As[cur][wm * 32 + mi * 16][k16], 40);
#pragma unroll
            for (int ni = 0; ni < 4; ni++)
                wmma::load_matrix_sync(bf[ni], &Bs[cur][k16][wn * 64 + ni * 16], 136);
#pragma unroll
            for (int mi = 0; mi < 2; mi++)
#pragma unroll
                for (int ni = 0; ni < 4; ni++)
                    wmma::mma_sync(acc[mi][ni], af[mi], bf[ni], acc[mi][ni]);
        }
        if (has) {
            int nxt = cur ^ 1;
#pragma unroll
            for (int i = 0; i < 4; i++)
                *(uint2*)&As[nxt][ar0 + (i << 5)][ac] = f4_to_bf4(aR[i]);
#pragma unroll
            for (int i = 0; i < 4; i++)
                *(uint2*)&Bs[nxt][br0 + (i << 3)][bc] = f4_to_bf4(bR[i]);
        }
        __syncthreads();
        cur ^= 1;
    }

#pragma unroll
    for (int mi = 0; mi < 2; mi++)
#pragma unroll
        for (int ni = 0; ni < 4; ni++) {
            size_t row = (size_t)(bm + wm * 32 + mi * 16);
            size_t col = (size_t)(bn + wn * 64 + ni * 16);
            float* cp = Cmat + row * N + col;
            if (Res) {
                wmma::fragment<wmma::accumulator, 16, 16, 16, float> rf;
                wmma::load_matrix_sync(rf, Res + row * N + col, N, wmma::mem_row_major);
#pragma unroll
                for (int t = 0; t < rf.num_elements; t++)
                    acc[mi][ni].x[t] = acc[mi][ni].x[t] * alpha + rf.x[t];
            } else if (alpha != 1.f) {
#pragma unroll
                for (int t = 0; t < acc[mi][ni].num_elements; t++)
                    acc[mi][ni].x[t] *= alpha;
            }
            wmma::store_matrix_sync(cp, acc[mi][ni], N, wmma::mem_row_major);
        }
}

// ============================================================
// Grouped (per-expert) BF16 GEMM with optional row gather.
// ============================================================
template <bool GATHER>
__global__ void gg_tgemm(const float* __restrict__ A, const float* __restrict__ Bbase,
                         size_t strideB, int K, int N, float* __restrict__ Out)
{
    int e = blockIdx.z;
    int cnt = g_cnt[e];
    int base = blockIdx.x * 128;
    if (base >= cnt) return;
    int o = g_off[e];
    const float* B = Bbase + (size_t)e * strideB;

    __shared__ __nv_bfloat16 As[2][128][40];
    __shared__ __nv_bfloat16 Bs[2][32][136];
    __shared__ float stage[8 * 320];
    const int tid  = threadIdx.x;
    const int warp = tid >> 5;
    const int lane = tid & 31;
    const int wm   = warp & 3, wn = warp >> 2;
    const int bn   = blockIdx.y * 128;

    wmma::fragment<wmma::accumulator, 16, 16, 16, float> acc[2][4];
#pragma unroll
    for (int mi = 0; mi < 2; mi++)
#pragma unroll
        for (int ni = 0; ni < 4; ni++) wmma::fill_fragment(acc[mi][ni], 0.f);

    const int ar0 = tid >> 3, ac = (tid & 7) << 2;
    const int br0 = tid >> 5, bc = (tid & 31) << 2;

    // precompute gathered rows + validity
    int grow[4]; bool gv[4];
#pragma unroll
    for (int i = 0; i < 4; i++) {
        int lr = base + ar0 + (i << 5);
        gv[i] = lr < cnt;
        grow[i] = gv[i] ? (GATHER ? g_perm[o + lr] : (o + lr)) : 0;
    }

    float4 aR[4], bR[4];
    const int nch = K >> 5;

#pragma unroll
    for (int i = 0; i < 4; i++)
        aR[i] = gv[i] ? *(const float4*)(A + (size_t)grow[i] * K + ac)
                      : make_float4(0.f, 0.f, 0.f, 0.f);
#pragma unroll
    for (int i = 0; i < 4; i++)
        bR[i] = *(const float4*)(B + (size_t)(br0 + (i << 3)) * N + bn + bc);
#pragma unroll
    for (int i = 0; i < 4; i++)
        *(uint2*)&As[0][ar0 + (i << 5)][ac] = f4_to_bf4(aR[i]);
#pragma unroll
    for (int i = 0; i < 4; i++)
        *(uint2*)&Bs[0][br0 + (i << 3)][bc] = f4_to_bf4(bR[i]);
    __syncthreads();

    int cur = 0;
    for (int ch = 0; ch < nch; ch++) {
        bool has = (ch + 1) < nch;
        if (has) {
            int k0 = (ch + 1) << 5;
#pragma unroll
            for (int i = 0; i < 4; i++)
                aR[i] = gv[i] ? *(const float4*)(A + (size_t)grow[i] * K + k0 + ac)
                              : make_float4(0.f, 0.f, 0.f, 0.f);
#pragma unroll
            for (int i = 0; i < 4; i++)
                bR[i] = *(const float4*)(B + (size_t)(k0 + br0 + (i << 3)) * N + bn + bc);
        }
#pragma unroll
        for (int ks = 0; ks < 2; ks++) {
            int k16 = ks << 4;
            wmma::fragment<wmma::matrix_a, 16, 16, 16, __nv_bfloat16, wmma::row_major> af[2];
            wmma::fragment<wmma::matrix_b, 16, 16, 16, __nv_bfloat16, wmma::row_major> bf[4];
#pragma unroll
            for (int mi = 0; mi < 2; mi++)
                wmma::load_matrix_sync(af[mi], &As[cur][wm * 32 + mi * 16][k16], 40);
#pragma unroll
            for (int ni = 0; ni < 4; ni++)
                wmma::load_matrix_sync(bf[ni], &Bs[cur][k16][wn * 64 + ni * 16], 136);
#pragma unroll
            for (int mi = 0; mi < 2; mi++)
#pragma unroll
                for (int ni = 0; ni < 4; ni++)
                    wmma::mma_sync(acc[mi][ni], af[mi], bf[ni], acc[mi][ni]);
        }
        if (has) {
            int nxt = cur ^ 1;
#pragma unroll
            for (int i = 0; i < 4; i++)
                *(uint2*)&As[nxt][ar0 + (i << 5)][ac] = f4_to_bf4(aR[i]);
#pragma unroll
            for (int i = 0; i < 4; i++)
                *(uint2*)&Bs[nxt][br0 + (i << 3)][bc] = f4_to_bf4(bR[i]);
        }
        __syncthreads();
        cur ^= 1;
    }

    // Staged epilogue: per-warp 16x16 tile through smem for per-row bounds check.
    float* st = stage + warp * 320;   // 16 rows x ldm 20
    const int sr = lane >> 1, sc0 = (lane & 1) << 3;
#pragma unroll
    for (int mi = 0; mi < 2; mi++)
#pragma unroll
        for (int ni = 0; ni < 4; ni++) {
            wmma::store_matrix_sync(st, acc[mi][ni], 20, wmma::mem_row_major);
            __syncwarp();
            int lr = base + wm * 32 + mi * 16 + sr;
            if (lr < cnt) {
                size_t row = (size_t)(o + lr);
                int col = bn + wn * 64 + ni * 16 + sc0;
                float4 v0 = *(float4*)(st + sr * 20 + sc0);
                float4 v1 = *(float4*)(st + sr * 20 + sc0 + 4);
                *(float4*)(Out + row * N + col)     = v0;
                *(float4*)(Out + row * N + col + 4) = v1;
            }
            __syncwarp();
        }
}

// ============================================================
// K/V up-projection, bf16 wmma. grid (Nv/128, Hv*2).
// y = h*2 + which; which 0 -> K (Wk_up), 1 -> V (Wv_up).
// out[b,h,t,d], block tile 128 tokens x 64 d, K=L=256.
// ============================================================
__global__ void kvup_wmma(const float* __restrict__ kv,
                          const float* __restrict__ Wk_up, const float* __restrict__ Wv_up,
                          float* __restrict__ kout, float* __restrict__ vout)
{
    int y = blockIdx.y;
    int h = y >> 1, which = y & 1;
    const float* W = (which ? Wv_up : Wk_up) + (size_t)h * Lv * Dv;
    float* outp = which ? vout : kout;
    int bm = blockIdx.x * 128;

    __shared__ __nv_bfloat16 As[2][128][40];
    __shared__ __nv_bfloat16 Bs[2][32][72];
    const int tid  = threadIdx.x;
    const int warp = tid >> 5;
    const int wm   = warp & 3, wn = warp >> 2;

    wmma::fragment<wmma::accumulator, 16, 16, 16, float> acc[2][2];
#pragma unroll
    for (int mi = 0; mi < 2; mi++)
#pragma unroll
        for (int ni = 0; ni < 2; ni++) wmma::fill_fragment(acc[mi][ni], 0.f);

    const int ar0 = tid >> 3, ac = (tid & 7) << 2;
    const int br0 = tid >> 4, bc = (tid & 15) << 2;

    float4 aR[4], bR[2];
    const int nch = Lv >> 5;   // 8

#pragma unroll
    for (int i = 0; i < 4; i++)
        aR[i] = *(const float4*)(kv + (size_t)(bm + ar0 + (i << 5)) * Lv + ac);
#pragma unroll
    for (int i = 0; i < 2; i++)
        bR[i] = *(const float4*)(W + (size_t)(br0 + (i << 4)) * Dv + bc);
#pragma unroll
    for (int i = 0; i < 4; i++)
        *(uint2*)&As[0][ar0 + (i << 5)][ac] = f4_to_bf4(aR[i]);
#pragma unroll
    for (int i = 0; i < 2; i++)
        *(uint2*)&Bs[0][br0 + (i << 4)][bc] = f4_to_bf4(bR[i]);
    __syncthreads();

    int cur = 0;
    for (int ch = 0; ch < nch; ch++) {
        bool has = (ch + 1) < nch;
        if (has) {
            int k0 = (ch + 1) << 5;
#pragma unroll
            for (int i = 0; i < 4; i++)
                aR[i] = *(const float4*)(kv + (size_t)(bm + ar0 + (i << 5)) * Lv + k0 + ac);
#pragma unroll
            for (int i = 0; i < 2; i++)
                bR[i] = *(const float4*)(W + (size_t)(k0 + br0 + (i << 4)) * Dv + bc);
        }
#pragma unroll
        for (int ks = 0; ks < 2; ks++) {
            int k16 = ks << 4;
            wmma::fragment<wmma::matrix_a, 16, 16, 16, __nv_bfloat16, wmma::row_major> af[2];
            wmma::fragment<wmma::matrix_b, 16, 16, 16, __nv_bfloat16, wmma::row_major> bf[2];
#pragma unroll
            for (int mi = 0; mi < 2; mi++)
                wmma::load_matrix_sync(af[mi], &As[cur][wm * 32 + mi * 16][k16], 40);
#pragma unroll
            for (int ni = 0; ni < 2; ni++)
                wmma::load_matrix_sync(bf[ni], &Bs[cur][k16][wn * 32 + ni * 16], 72);
#pragma unroll
            for (int mi = 0; mi < 2; mi++)
#pragma unroll
                for (int ni = 0; ni < 2; ni++)
                    wmma::mma_sync(acc[mi][ni], af[mi], bf[ni], acc[mi][ni]);
        }
        if (has) {
            int nxt = cur ^ 1;
#pragma unroll
            for (int i = 0; i < 4; i++)
                *(uint2*)&As[nxt][ar0 + (i << 5)][ac] = f4_to_bf4(aR[i]);
#pragma unroll
            for (int i = 0; i < 2; i++)
                *(uint2*)&Bs[nxt][br0 + (i << 4)][bc] = f4_to_bf4(bR[i]);
        }
        __syncthreads();
        cur ^= 1;
    }

#pragma unroll
    for (int mi = 0; mi < 2; mi++) {
        int n0 = bm + wm * 32 + mi * 16;
        int b = n0 >> 10, t0 = n0 & 1023;
        float* bp = outp + ((size_t)(b * Hv + h) * Tv + t0) * Dv;
#pragma unroll
        for (int ni = 0; ni < 2; ni++)
            wmma::store_matrix_sync(bp + wn * 32 + ni * 16, acc[mi][ni], Dv, wmma::mem_row_major);
    }
}

// ============================================================
// RoPE in place on 64-wide head vectors. posDiv: Hv for q-layout, 1 for k-layout.
// ============================================================
__global__ void rope_kernel(float* __restrict__ xp, int posDiv)
{
    int idx = blockIdx.x * TB + threadIdx.x;   // pair index; exact grid
    int outer = idx >> 5;
    int j = idx & 31;
    int pos = (outer / posDiv) & (Tv - 1);
    float invf = powf(100000.0f, -(float)j * (1.0f / 32.0f));
    float f = (float)pos * invf;
    float s, c; sincosf(f, &s, &c);
    float* p = xp + (size_t)outer * Dv;
    float x1 = p[j], x2 = p[j + 32];
    p[j]      = x1 * c - x2 * s;
    p[j + 32] = x1 * s + x2 * c;
}

// ============================================================
// Attention scores: S[bh, t, s] = (q_t . k_s) / 8, causal tile skip.
// ============================================================
__global__ void scores_kernel(const float* __restrict__ q, const float* __restrict__ k,
                              float* __restrict__ S)
{
    int bh = blockIdx.z, b = bh >> 4, h = bh & 15;
    int qs = blockIdx.y * 64, ks = blockIdx.x * 64;
    if (ks > qs) return;   // fully masked tile
    __shared__ float Qs[64][65];
    __shared__ float Ks[64][65];
    const int tid = threadIdx.x;
    const int r = tid >> 2, c0 = tid & 3;
#pragma unroll
    for (int i = 0; i < 4; i++) {
        int col = (c0 + 4 * i) << 2;
        float4 v = *(const float4*)(q + (size_t)(b * Tv + qs + r) * Cv + h * Dv + col);
        Qs[r][col] = v.x; Qs[r][col + 1] = v.y; Qs[r][col + 2] = v.z; Qs[r][col + 3] = v.w;
        float4 w = *(const float4*)(k + ((size_t)bh * Tv + ks + r) * Dv + col);
        Ks[r][col] = w.x; Ks[r][col + 1] = w.y; Ks[r][col + 2] = w.z; Ks[r][col + 3] = w.w;
    }
    __syncthreads();
    const int ti = (tid >> 4) << 2, tj = (tid & 15) << 2;
    float acc[4][4];
#pragma unroll
    for (int i = 0; i < 4; i++)
#pragma unroll
        for (int j = 0; j < 4; j++) acc[i][j] = 0.f;
#pragma unroll
    for (int d = 0; d < 64; d++) {
        float ra[4], rb[4];
#pragma unroll
        for (int i = 0; i < 4; i++) ra[i] = Qs[ti + i][d];
#pragma unroll
        for (int j = 0; j < 4; j++) rb[j] = Ks[tj + j][d];
#pragma unroll
        for (int i = 0; i < 4; i++)
#pragma unroll
            for (int j = 0; j < 4; j++) acc[i][j] += ra[i] * rb[j];
    }
#pragma unroll
    for (int i = 0; i < 4; i++) {
        size_t idx = ((size_t)bh * Tv + qs + ti + i) * Tv + ks + tj;
        *(float4*)(S + idx) = make_float4(acc[i][0] * 0.125f, acc[i][1] * 0.125f,
                                          acc[i][2] * 0.125f, acc[i][3] * 0.125f);
    }
}

// ============================================================
// Causal row softmax in place; zeros masked tail up to next 64 boundary.
// ============================================================
__global__ void softmax_kernel(float* __restrict__ S)
{
    long long row = blockIdx.x;
    int t = (int)(row & (Tv - 1));
    float* Sr = S + row * (long long)Tv;
    int len = t + 1;
    int wlim = (t + 64) & ~63;   // av_kernel never reads past this
    int tid = threadIdx.x;
    __shared__ float red[TB];
    float m = -1e30f;
    for (int s = tid; s < len; s += TB) m = fmaxf(m, Sr[s]);
    red[tid] = m; __syncthreads();
    for (int st = TB / 2; st > 0; st >>= 1) { if (tid < st) red[tid] = fmaxf(red[tid], red[tid + st]); __syncthreads(); }
    float rowmax = red[0];
    __syncthreads();
    float sum = 0.f;
    for (int s = tid; s < len; s += TB) sum += expf(Sr[s] - rowmax);
    red[tid] = sum; __syncthreads();
    for (int st = TB / 2; st > 0; st >>= 1) { if (tid < st) red[tid] += red[tid + st]; __syncthreads(); }
    float inv = 1.f / red[0];
    for (int s = tid; s < wlim; s += TB)
        Sr[s] = (s < len) ? expf(Sr[s] - rowmax) * inv : 0.f;
}

// ============================================================
// O = P @ V per (b,h); causal K-bound. Output token-major [n][h*D+d].
// ============================================================
__global__ void av_kernel(const float* __restrict__ P, const float* __restrict__ V,
                          float* __restrict__ O)
{
    int bh = blockIdx.z, b = bh >> 4, h = bh & 15;
    int qs = blockIdx.x * 64;
    const float* Pr = P + (size_t)bh * Tv * Tv;
    const float* Vr = V + (size_t)bh * Tv * Dv;
    __shared__ float As[16][65];
    __shared__ float Bs[16][64];
    const int tid = threadIdx.x;
    const int ar = tid >> 2,        ac = (tid & 3) << 2;
    const int br = tid >> 4,        bc = (tid & 15) << 2;
    const int ti = (tid >> 4) << 2, tc = (tid & 15) << 2;
    float acc[4][4];
#pragma unroll
    for (int i = 0; i < 4; i++)
#pragma unroll
        for (int j = 0; j < 4; j++) acc[i][j] = 0.f;

    int kend = qs + 64;
    for (int k0 = 0; k0 < kend; k0 += 16) {
        float4 av = *(const float4*)(Pr + (size_t)(qs + ar) * Tv + k0 + ac);
        As[ac + 0][ar] = av.x; As[ac + 1][ar] = av.y; As[ac + 2][ar] = av.z; As[ac + 3][ar] = av.w;
        *(float4*)(&Bs[br][bc]) = *(const float4*)(Vr + (size_t)(k0 + br) * Dv + bc);
        __syncthreads();
#pragma unroll
        for (int kk = 0; kk < 16; kk++) {
            float ra[4], rb[4];
#pragma unroll
            for (int i = 0; i < 4; i++) ra[i] = As[kk][ti + i];
#pragma unroll
            for (int j = 0; j < 4; j++) rb[j] = Bs[kk][tc + j];
#pragma unroll
            for (int i = 0; i < 4; i++)
#pragma unroll
                for (int j = 0; j < 4; j++) acc[i][j] += ra[i] * rb[j];
        }
        __syncthreads();
    }
#pragma unroll
    for (int i = 0; i < 4; i++) {
        size_t idx = (size_t)(b * Tv + qs + ti + i) * Cv + h * Dv + tc;
        *(float4*)(O + idx) = make_float4(acc[i][0], acc[i][1], acc[i][2], acc[i][3]);
    }
}

// ============================================================
// Router: logits = clip(h2@Wr + bias, -50, 50); sigmoid; argmax (first max).
// ============================================================
__global__ void router_kernel(const float* __restrict__ h2, const float* __restrict__ Wr,
                              const float* __restrict__ rb)
{
    int n = blockIdx.x, tid = threadIdx.x;
    const float* xr = h2 + (size_t)n * Cv;
    float part[Ev];
#pragma unroll
    for (int e = 0; e < Ev; e++) part[e] = 0.f;
    for (int c = tid; c < Cv; c += TB) {
        float xv = xr[c];
#pragma unroll
        for (int e = 0; e < Ev; e++) part[e] += xv * Wr[c * Ev + e];
    }
    __shared__ float sd[Ev][TB];
#pragma unroll
    for (int e = 0; e < Ev; e++) sd[e][tid] = part[e];
    __syncthreads();
    for (int st = TB / 2; st > 0; st >>= 1) {
        if (tid < st)
#pragma unroll
            for (int e = 0; e < Ev; e++) sd[e][tid] += sd[e][tid + st];
        __syncthreads();
    }
    if (tid == 0) {
        int best = 0; float bp = -1.f;
#pragma unroll
        for (int e = 0; e < Ev; e++) {
            float lg = fminf(fmaxf(sd[e][0] + rb[e], -50.f), 50.f);
            float pr = 1.f / (1.f + expf(-lg));
            if (pr > bp) { bp = pr; best = e; }
        }
        g_sel[n] = best;
        g_p[n]   = fminf(fmaxf(bp, 1e-8f), 1.f - 1e-8f);
    }
}

__global__ void zero_kernel() {
    int t = threadIdx.x;
    if (t < Ev) { g_cnt[t] = 0; g_cur[t] = 0; }
}
__global__ void hist_kernel() {
    int n = blockIdx.x * TB + threadIdx.x;
    if (n < Nv) atomicAdd(&g_cnt[g_sel[n]], 1);
}
__global__ void offsets_kernel() {
    int s = 0;
    for (int e = 0; e < Ev; e++) { g_off[e] = s; s += g_cnt[e]; }
}
__global__ void scatter_kernel() {
    int n = blockIdx.x * TB + threadIdx.x;
    if (n < Nv) {
        int e = g_sel[n];
        int pos = atomicAdd(&g_cur[e], 1);
        g_perm[g_off[e] + pos] = n;
    }
}

__global__ void silumul_kernel(const float* __restrict__ a, const float* __restrict__ b,
                               float* __restrict__ o)
{
    int i = blockIdx.x * TB + threadIdx.x;   // exact grid Nv*Iv
    float v = a[i];
    o[i] = (v / (1.f + expf(-v))) * b[i];
}

// out[n] = x1[n] + (0.5/tw)*shared[n] + (p/tw)*expert_out(compact s)
__global__ void combine_kernel(const float* __restrict__ x1, const float* __restrict__ sh,
                               const float* __restrict__ yc, float* __restrict__ out)
{
    int s = blockIdx.x;
    int n = g_perm[s];
    float p = g_p[n];
    float tw = fminf(fmaxf(0.5f + p + 1e-8f, 0.5f), 2.0f);
    float wsh = 0.5f / tw, wex = p / tw;
    const float* a = x1 + (size_t)n * Cv;
    const float* b = sh + (size_t)n * Cv;
    const float* c = yc + (size_t)s * Cv;
    float* o = out + (size_t)n * Cv;
    for (int i = threadIdx.x; i < Cv; i += TB)
        o[i] = a[i] + wsh * b[i] + wex * c[i];
}

// ============================================================
// launcher
// ============================================================
extern "C" void kernel_launch(void* const* d_in, const int* in_sizes, int n_in,
                              void* d_out, int out_size)
{
    const float* x    = (const float*)d_in[0];
    const float* ln1  = (const float*)d_in[1];
    const float* ln2  = (const float*)d_in[2];
    const float* Wq   = (const float*)d_in[3];
    const float* Wkv  = (const float*)d_in[4];
    const float* Wk_up= (const float*)d_in[5];
    const float* Wv_up= (const float*)d_in[6];
    const float* Wo   = (const float*)d_in[7];
    const float* Wr   = (const float*)d_in[8];
    const float* rb   = (const float*)d_in[9];
    const float* sw1  = (const float*)d_in[10];
    const float* sw2  = (const float*)d_in[11];
    const float* sw3  = (const float*)d_in[12];
    const float* ew1  = (const float*)d_in[13];
    const float* ew2  = (const float*)d_in[14];
    const float* ew3  = (const float*)d_in[15];
    float* out = (float*)d_out;

    float *ph, *pq, *pkv, *pk, *pv, *pS, *pat, *px1, *ph2;
    float *pa1, *pa3, *pu, *psh, *pc1, *pc3, *puc, *pyc;
    cudaGetSymbolAddress((void**)&ph,  g_h);
    cudaGetSymbolAddress((void**)&pq,  g_q);
    cudaGetSymbolAddress((void**)&pkv, g_kv);
    cudaGetSymbolAddress((void**)&pk,  g_k);
    cudaGetSymbolAddress((void**)&pv,  g_v);
    cudaGetSymbolAddress((void**)&pS,  g_S);
    cudaGetSymbolAddress((void**)&pat, g_at);
    cudaGetSymbolAddress((void**)&px1, g_x1);
    cudaGetSymbolAddress((void**)&ph2, g_h2);
    cudaGetSymbolAddress((void**)&pa1, g_a1);
    cudaGetSymbolAddress((void**)&pa3, g_a3);
    cudaGetSymbolAddress((void**)&pu,  g_u);
    cudaGetSymbolAddress((void**)&psh, g_sh);
    cudaGetSymbolAddress((void**)&pc1, g_c1);
    cudaGetSymbolAddress((void**)&pc3, g_c3);
    cudaGetSymbolAddress((void**)&puc, g_uc);
    cudaGetSymbolAddress((void**)&pyc, g_yc);

    // ---- attention ----
    rmsnorm_kernel<<<Nv, TB>>>(x, ln1, ph);
    tgemm<<<dim3(Cv / 128, Nv / 128), TB>>>(ph, Wq,  pq,  nullptr, Cv, Cv, 1.f);
    tgemm<<<dim3(Lv / 128, Nv / 128), TB>>>(ph, Wkv, pkv, nullptr, Cv, Lv, 0.25f);
    kvup_wmma<<<dim3(Nv / 128, Hv * 2), TB>>>(pkv, Wk_up, Wv_up, pk, pv);
    rope_kernel<<<(Nv * Hv * 32) / TB, TB>>>(pq, Hv);
    rope_kernel<<<(Nv * Hv * 32) / TB, TB>>>(pk, 1);
    scores_kernel<<<dim3(Tv / 64, Tv / 64, BHv), TB>>>(pq, pk, pS);
    softmax_kernel<<<BHv * Tv, TB>>>(pS);
    av_kernel<<<dim3(Tv / 64, 1, BHv), TB>>>(pS, pv, pat);
    tgemm<<<dim3(Cv / 128, Nv / 128), TB>>>(pat, Wo, px1, x, Cv, Cv, 1.f);   // + residual x

    // ---- MoE ----
    rmsnorm_kernel<<<Nv, TB>>>(px1, ln2, ph2);
    router_kernel<<<Nv, TB>>>(ph2, Wr, rb);
    zero_kernel<<<1, 32>>>();
    hist_kernel<<<Nv / TB, TB>>>();
    offsets_kernel<<<1, 1>>>();
    scatter_kernel<<<Nv / TB, TB>>>();

    // shared expert
    tgemm<<<dim3(Iv / 128, Nv / 128), TB>>>(ph2, sw1, pa1, nullptr, Cv, Iv, 1.f);
    tgemm<<<dim3(Iv / 128, Nv / 128), TB>>>(ph2, sw3, pa3, nullptr, Cv, Iv, 1.f);
    silumul_kernel<<<(Nv * Iv) / TB, TB>>>(pa1, pa3, pu);
    tgemm<<<dim3(Cv / 128, Nv / 128), TB>>>(pu, sw2, psh, nullptr, Iv, Cv, 1.f);

    // routed experts (grouped, gathered)
    gg_tgemm<true ><<<dim3(Nv / 128, Iv / 128, Ev), TB>>>(ph2, ew1, (size_t)Cv * Iv, Cv, Iv, pc1);
    gg_tgemm<true ><<<dim3(Nv / 128, Iv / 128, Ev), TB>>>(ph2, ew3, (size_t)Cv * Iv, Cv, Iv, pc3);
    silumul_kernel<<<(Nv * Iv) / TB, TB>>>(pc1, pc3, puc);
    gg_tgemm<false><<<dim3(Nv / 128, Cv / 128, Ev), TB>>>(puc, ew2, (size_t)Iv * Cv, Iv, Cv, pyc);

    // combine + residual
    combine_kernel<<<Nv, TB>>>(px1, psh, pyc, out);
}

// round 4
// speedup vs baseline: 2.3770x; 1.0441x over previous
#include <cuda_runtime.h>
#include <cuda_bf16.h>
#include <mma.h>
#include <cstdint>

using namespace nvcuda;

#define TB 256

// ---- problem constants ----
constexpr int Bv = 8, Tv = 1024, Hv = 16, Dv = 64, Cv = 1024, Lv = 256, Ev = 8, Iv = 2048;
constexpr int Nv  = Bv * Tv;   // 8192 tokens
constexpr int BHv = Bv * Hv;   // 128

// ---- scratch (device globals; allocation-free) ----
__device__ float g_h  [Nv * Cv];
__device__ float g_q  [Nv * Cv];
__device__ float g_kv [Nv * Lv];
__device__ float g_k  [Nv * Cv];          // [b,h,t,d]
__device__ float g_v  [Nv * Cv];          // [b,h,t,d]
__device__ float g_S  [(size_t)BHv * Tv * Tv];   // scores / probs (512 MB)
__device__ float g_at [Nv * Cv];
__device__ float g_x1 [Nv * Cv];
__device__ float g_h2 [Nv * Cv];
__device__ float g_a1 [Nv * Iv];
__device__ float g_a3 [Nv * Iv];
__device__ float g_u  [Nv * Iv];
__device__ float g_sh [Nv * Cv];
__device__ float g_c1 [Nv * Iv];
__device__ float g_c3 [Nv * Iv];
__device__ float g_uc [Nv * Iv];
__device__ float g_yc [Nv * Cv];
__device__ int   g_sel[Nv];
__device__ float g_p  [Nv];
__device__ int   g_cnt[Ev];
__device__ int   g_off[Ev];
__device__ int   g_cur[Ev];
__device__ int   g_perm[Nv];

__device__ __forceinline__ uint2 f4_to_bf4(float4 v) {
    __nv_bfloat162 lo = __floats2bfloat162_rn(v.x, v.y);
    __nv_bfloat162 hi = __floats2bfloat162_rn(v.z, v.w);
    uint2 r;
    r.x = *reinterpret_cast<unsigned int*>(&lo);
    r.y = *reinterpret_cast<unsigned int*>(&hi);
    return r;
}

__device__ __forceinline__ float to_tf32(float x) {
    float r; asm("cvt.rna.tf32.f32 %0, %1;" : "=f"(r) : "f"(x)); return r;
}

// ============================================================
// RMSNorm: one block per token
// ============================================================
__global__ void rmsnorm_kernel(const float* __restrict__ x, const float* __restrict__ w,
                               float* __restrict__ y)
{
    int n = blockIdx.x, tid = threadIdx.x;
    const float* xr = x + (size_t)n * Cv;
    __shared__ float red[TB];
    float ss = 0.f;
    for (int c = tid; c < Cv; c += TB) { float v = xr[c]; ss += v * v; }
    red[tid] = ss; __syncthreads();
    for (int s = TB / 2; s > 0; s >>= 1) { if (tid < s) red[tid] += red[tid + s]; __syncthreads(); }
    float rs = rsqrtf(red[0] / (float)Cv + 1e-6f);
    float* yr = y + (size_t)n * Cv;
    for (int c = tid; c < Cv; c += TB) yr[c] = xr[c] * rs * w[c];
}

// ============================================================
// BF16 tensor-core GEMM: C = alpha*A(MxK)@B(KxN) (+Res).
// M,N multiples of 128, K multiple of 32. fp32 accumulate.
// ============================================================
__global__ void tgemm(const float* __restrict__ A, const float* __restrict__ B,
                      float* __restrict__ Cmat, const float* __restrict__ Res,
                      int K, int N, float alpha)
{
    __shared__ __nv_bfloat16 As[2][128][40];
    __shared__ __nv_bfloat16 Bs[2][32][136];
    const int tid  = threadIdx.x;
    const int warp = tid >> 5;
    const int wm   = warp & 3, wn = warp >> 2;
    const int bm   = blockIdx.y * 128, bn = blockIdx.x * 128;

    wmma::fragment<wmma::accumulator, 16, 16, 16, float> acc[2][4];
#pragma unroll
    for (int mi = 0; mi < 2; mi++)
#pragma unroll
        for (int ni = 0; ni < 4; ni++) wmma::fill_fragment(acc[mi][ni], 0.f);

    const int ar0 = tid >> 3, ac = (tid & 7) << 2;
    const int br0 = tid >> 5, bc = (tid & 31) << 2;

    float4 aR[4], bR[4];
    const int nch = K >> 5;

#pragma unroll
    for (int i = 0; i < 4; i++)
        aR[i] = *(const float4*)(A + (size_t)(bm + ar0 + (i << 5)) * K + ac);
#pragma unroll
    for (int i = 0; i < 4; i++)
        bR[i] = *(const float4*)(B + (size_t)(br0 + (i << 3)) * N + bn + bc);
#pragma unroll
    for (int i = 0; i < 4; i++)
        *(uint2*)&As[0][ar0 + (i << 5)][ac] = f4_to_bf4(aR[i]);
#pragma unroll
    for (int i = 0; i < 4; i++)
        *(uint2*)&Bs[0][br0 + (i << 3)][bc] = f4_to_bf4(bR[i]);
    __syncthreads();

    int cur = 0;
    for (int ch = 0; ch < nch; ch++) {
        bool has = (ch + 1) < nch;
        if (has) {
            int k0 = (ch + 1) << 5;
#pragma unroll
            for (int i = 0; i < 4; i++)
                aR[i] = *(const float4*)(A + (size_t)(bm + ar0 + (i << 5)) * K + k0 + ac);
#pragma unroll
            for (int i = 0; i < 4; i++)
                bR[i] = *(const float4*)(B + (size_t)(k0 + br0 + (i << 3)) * N + bn + bc);
        }
#pragma unroll
        for (int ks = 0; ks < 2; ks++) {
            int k16 = ks << 4;
            wmma::fragment<wmma::matrix_a, 16, 16, 16, __nv_bfloat16, wmma::row_major> af[2];
            wmma::fragment<wmma::matrix_b, 16, 16, 16, __nv_bfloat16, wmma::row_major> bf[4];
#pragma unroll
            for (int mi = 0; mi < 2; mi++)
                wmma::load_matrix_sync(af[mi], &As[cur][wm * 32 + mi * 16][k16], 40);
#pragma unroll
            for (int ni = 0; ni < 4; ni++)
                wmma::load_matrix_sync(bf[ni], &Bs[cur][k16][wn * 64 + ni * 16], 136);
#pragma unroll
            for (int mi = 0; mi < 2; mi++)
#pragma unroll
                for (int ni = 0; ni < 4; ni++)
                    wmma::mma_sync(acc[mi][ni], af[mi], bf[ni], acc[mi][ni]);
        }
        if (has) {
            int nxt = cur ^ 1;
#pragma unroll
            for (int i = 0; i < 4; i++)
                *(uint2*)&As[nxt][ar0 + (i << 5)][ac] = f4_to_bf4(aR[i]);
#pragma unroll
            for (int i = 0; i < 4; i++)
                *(uint2*)&Bs[nxt][br0 + (i << 3)][bc] = f4_to_bf4(bR[i]);
        }
        __syncthreads();
        cur ^= 1;
    }

#pragma unroll
    for (int mi = 0; mi < 2; mi++)
#pragma unroll
        for (int ni = 0; ni < 4; ni++) {
            size_t row = (size_t)(bm + wm * 32 + mi * 16);
            size_t col = (size_t)(bn + wn * 64 + ni * 16);
            float* cp = Cmat + row * N + col;
            if (Res) {
                wmma::fragment<wmma::accumulator, 16, 16, 16, float> rf;
                wmma::load_matrix_sync(rf, Res + row * N + col, N, wmma::mem_row_major);
#pragma unroll
                for (int t = 0; t < rf.num_elements; t++)
                    acc[mi][ni].x[t] = acc[mi][ni].x[t] * alpha + rf.x[t];
            } else if (alpha != 1.f) {
#pragma unroll
                for (int t = 0; t < acc[mi][ni].num_elements; t++)
                    acc[mi][ni].x[t] *= alpha;
            }
            wmma::store_matrix_sync(cp, acc[mi][ni], N, wmma::mem_row_major);
        }
}

// ============================================================
// Grouped (per-expert) BF16 GEMM with optional row gather.
// ============================================================
template <bool GATHER>
__global__ void gg_tgemm(const float* __restrict__ A, const float* __restrict__ Bbase,
                         size_t strideB, int K, int N, float* __restrict__ Out)
{
    int e = blockIdx.z;
    int cnt = g_cnt[e];
    int base = blockIdx.x * 128;
    if (base >= cnt) return;
    int o = g_off[e];
    const float* B = Bbase + (size_t)e * strideB;

    __shared__ __nv_bfloat16 As[2][128][40];
    __shared__ __nv_bfloat16 Bs[2][32][136];
    __shared__ float stage[8 * 320];
    const int tid  = threadIdx.x;
    const int warp = tid >> 5;
    const int lane = tid & 31;
    const int wm   = warp & 3, wn = warp >> 2;
    const int bn   = blockIdx.y * 128;

    wmma::fragment<wmma::accumulator, 16, 16, 16, float> acc[2][4];
#pragma unroll
    for (int mi = 0; mi < 2; mi++)
#pragma unroll
        for (int ni = 0; ni < 4; ni++) wmma::fill_fragment(acc[mi][ni], 0.f);

    const int ar0 = tid >> 3, ac = (tid & 7) << 2;
    const int br0 = tid >> 5, bc = (tid & 31) << 2;

    int grow[4]; bool gv[4];
#pragma unroll
    for (int i = 0; i < 4; i++) {
        int lr = base + ar0 + (i << 5);
        gv[i] = lr < cnt;
        grow[i] = gv[i] ? (GATHER ? g_perm[o + lr] : (o + lr)) : 0;
    }

    float4 aR[4], bR[4];
    const int nch = K >> 5;

#pragma unroll
    for (int i = 0; i < 4; i++)
        aR[i] = gv[i] ? *(const float4*)(A + (size_t)grow[i] * K + ac)
                      : make_float4(0.f, 0.f, 0.f, 0.f);
#pragma unroll
    for (int i = 0; i < 4; i++)
        bR[i] = *(const float4*)(B + (size_t)(br0 + (i << 3)) * N + bn + bc);
#pragma unroll
    for (int i = 0; i < 4; i++)
        *(uint2*)&As[0][ar0 + (i << 5)][ac] = f4_to_bf4(aR[i]);
#pragma unroll
    for (int i = 0; i < 4; i++)
        *(uint2*)&Bs[0][br0 + (i << 3)][bc] = f4_to_bf4(bR[i]);
    __syncthreads();

    int cur = 0;
    for (int ch = 0; ch < nch; ch++) {
        bool has = (ch + 1) < nch;
        if (has) {
            int k0 = (ch + 1) << 5;
#pragma unroll
            for (int i = 0; i < 4; i++)
                aR[i] = gv[i] ? *(const float4*)(A + (size_t)grow[i] * K + k0 + ac)
                              : make_float4(0.f, 0.f, 0.f, 0.f);
#pragma unroll
            for (int i = 0; i < 4; i++)
                bR[i] = *(const float4*)(B + (size_t)(k0 + br0 + (i << 3)) * N + bn + bc);
        }
#pragma unroll
        for (int ks = 0; ks < 2; ks++) {
            int k16 = ks << 4;
            wmma::fragment<wmma::matrix_a, 16, 16, 16, __nv_bfloat16, wmma::row_major> af[2];
            wmma::fragment<wmma::matrix_b, 16, 16, 16, __nv_bfloat16, wmma::row_major> bf[4];
#pragma unroll
            for (int mi = 0; mi < 2; mi++)
                wmma::load_matrix_sync(af[mi], &As[cur][wm * 32 + mi * 16][k16], 40);
#pragma unroll
            for (int ni = 0; ni < 4; ni++)
                wmma::load_matrix_sync(bf[ni], &Bs[cur][k16][wn * 64 + ni * 16], 136);
#pragma unroll
            for (int mi = 0; mi < 2; mi++)
#pragma unroll
                for (int ni = 0; ni < 4; ni++)
                    wmma::mma_sync(acc[mi][ni], af[mi], bf[ni], acc[mi][ni]);
        }
        if (has) {
            int nxt = cur ^ 1;
#pragma unroll
            for (int i = 0; i < 4; i++)
                *(uint2*)&As[nxt][ar0 + (i << 5)][ac] = f4_to_bf4(aR[i]);
#pragma unroll
            for (int i = 0; i < 4; i++)
                *(uint2*)&Bs[nxt][br0 + (i << 3)][bc] = f4_to_bf4(bR[i]);
        }
        __syncthreads();
        cur ^= 1;
    }

    float* st = stage + warp * 320;
    const int sr = lane >> 1, sc0 = (lane & 1) << 3;
#pragma unroll
    for (int mi = 0; mi < 2; mi++)
#pragma unroll
        for (int ni = 0; ni < 4; ni++) {
            wmma::store_matrix_sync(st, acc[mi][ni], 20, wmma::mem_row_major);
            __syncwarp();
            int lr = base + wm * 32 + mi * 16 + sr;
            if (lr < cnt) {
                size_t row = (size_t)(o + lr);
                int col = bn + wn * 64 + ni * 16 + sc0;
                float4 v0 = *(float4*)(st + sr * 20 + sc0);
                float4 v1 = *(float4*)(st + sr * 20 + sc0 + 4);
                *(float4*)(Out + row * N + col)     = v0;
                *(float4*)(Out + row * N + col + 4) = v1;
            }
            __syncwarp();
        }
}

// ============================================================
// K/V up-projection, bf16 wmma. grid (Nv/128, Hv*2).
// ============================================================
__global__ void kvup_wmma(const float* __restrict__ kv,
                          const float* __restrict__ Wk_up, const float* __restrict__ Wv_up,
                          float* __restrict__ kout, float* __restrict__ vout)
{
    int y = blockIdx.y;
    int h = y >> 1, which = y & 1;
    const float* W = (which ? Wv_up : Wk_up) + (size_t)h * Lv * Dv;
    float* outp = which ? vout : kout;
    int bm = blockIdx.x * 128;

    __shared__ __nv_bfloat16 As[2][128][40];
    __shared__ __nv_bfloat16 Bs[2][32][72];
    const int tid  = threadIdx.x;
    const int warp = tid >> 5;
    const int wm   = warp & 3, wn = warp >> 2;

    wmma::fragment<wmma::accumulator, 16, 16, 16, float> acc[2][2];
#pragma unroll
    for (int mi = 0; mi < 2; mi++)
#pragma unroll
        for (int ni = 0; ni < 2; ni++) wmma::fill_fragment(acc[mi][ni], 0.f);

    const int ar0 = tid >> 3, ac = (tid & 7) << 2;
    const int br0 = tid >> 4, bc = (tid & 15) << 2;

    float4 aR[4], bR[2];
    const int nch = Lv >> 5;   // 8

#pragma unroll
    for (int i = 0; i < 4; i++)
        aR[i] = *(const float4*)(kv + (size_t)(bm + ar0 + (i << 5)) * Lv + ac);
#pragma unroll
    for (int i = 0; i < 2; i++)
        bR[i] = *(const float4*)(W + (size_t)(br0 + (i << 4)) * Dv + bc);
#pragma unroll
    for (int i = 0; i < 4; i++)
        *(uint2*)&As[0][ar0 + (i << 5)][ac] = f4_to_bf4(aR[i]);
#pragma unroll
    for (int i = 0; i < 2; i++)
        *(uint2*)&Bs[0][br0 + (i << 4)][bc] = f4_to_bf4(bR[i]);
    __syncthreads();

    int cur = 0;
    for (int ch = 0; ch < nch; ch++) {
        bool has = (ch + 1) < nch;
        if (has) {
            int k0 = (ch + 1) << 5;
#pragma unroll
            for (int i = 0; i < 4; i++)
                aR[i] = *(const float4*)(kv + (size_t)(bm + ar0 + (i << 5)) * Lv + k0 + ac);
#pragma unroll
            for (int i = 0; i < 2; i++)
                bR[i] = *(const float4*)(W + (size_t)(k0 + br0 + (i << 4)) * Dv + bc);
        }
#pragma unroll
        for (int ks = 0; ks < 2; ks++) {
            int k16 = ks << 4;
            wmma::fragment<wmma::matrix_a, 16, 16, 16, __nv_bfloat16, wmma::row_major> af[2];
            wmma::fragment<wmma::matrix_b, 16, 16, 16, __nv_bfloat16, wmma::row_major> bf[2];
#pragma unroll
            for (int mi = 0; mi < 2; mi++)
                wmma::load_matrix_sync(af[mi], &As[cur][wm * 32 + mi * 16][k16], 40);
#pragma unroll
            for (int ni = 0; ni < 2; ni++)
                wmma::load_matrix_sync(bf[ni], &Bs[cur][k16][wn * 32 + ni * 16], 72);
#pragma unroll
            for (int mi = 0; mi < 2; mi++)
#pragma unroll
                for (int ni = 0; ni < 2; ni++)
                    wmma::mma_sync(acc[mi][ni], af[mi], bf[ni], acc[mi][ni]);
        }
        if (has) {
            int nxt = cur ^ 1;
#pragma unroll
            for (int i = 0; i < 4; i++)
                *(uint2*)&As[nxt][ar0 + (i << 5)][ac] = f4_to_bf4(aR[i]);
#pragma unroll
            for (int i = 0; i < 2; i++)
                *(uint2*)&Bs[nxt][br0 + (i << 4)][bc] = f4_to_bf4(bR[i]);
        }
        __syncthreads();
        cur ^= 1;
    }

#pragma unroll
    for (int mi = 0; mi < 2; mi++) {
        int n0 = bm + wm * 32 + mi * 16;
        int b = n0 >> 10, t0 = n0 & 1023;
        float* bp = outp + ((size_t)(b * Hv + h) * Tv + t0) * Dv;
#pragma unroll
        for (int ni = 0; ni < 2; ni++)
            wmma::store_matrix_sync(bp + wn * 32 + ni * 16, acc[mi][ni], Dv, wmma::mem_row_major);
    }
}

// ============================================================
// RoPE in place on 64-wide head vectors.
// ============================================================
__global__ void rope_kernel(float* __restrict__ xp, int posDiv)
{
    int idx = blockIdx.x * TB + threadIdx.x;
    int outer = idx >> 5;
    int j = idx & 31;
    int pos = (outer / posDiv) & (Tv - 1);
    float invf = powf(100000.0f, -(float)j * (1.0f / 32.0f));
    float f = (float)pos * invf;
    float s, c; sincosf(f, &s, &c);
    float* p = xp + (size_t)outer * Dv;
    float x1 = p[j], x2 = p[j + 32];
    p[j]      = x1 * c - x2 * s;
    p[j + 32] = x1 * s + x2 * c;
}

// ============================================================
// Attention scores via TF32 wmma: S[bh,t,s] = (q_t.k_s)/8, causal skip.
// 64x64 tile, 256 thr = 8 warps (4 rows x 2 cols), warp = 16x32.
// ============================================================
__global__ void scores_wmma(const float* __restrict__ q, const float* __restrict__ k,
                            float* __restrict__ S)
{
    int bh = blockIdx.z, b = bh >> 4, h = bh & 15;
    int qs = blockIdx.y * 64, ks = blockIdx.x * 64;
    if (ks > qs) return;   // fully masked tile
    __shared__ float Qs[64][68];
    __shared__ float Ks[64][68];
    const int tid = threadIdx.x;
    const int r = tid >> 2, c0 = (tid & 3) << 4;
    const float* qrow = q + (size_t)(b * Tv + qs + r) * Cv + h * Dv;
    const float* krow = k + ((size_t)bh * Tv + ks + r) * Dv;
#pragma unroll
    for (int i = 0; i < 4; i++) {
        int c = c0 + (i << 2);
        float4 v = *(const float4*)(qrow + c);
        Qs[r][c + 0] = to_tf32(v.x); Qs[r][c + 1] = to_tf32(v.y);
        Qs[r][c + 2] = to_tf32(v.z); Qs[r][c + 3] = to_tf32(v.w);
        float4 w = *(const float4*)(krow + c);
        Ks[r][c + 0] = to_tf32(w.x); Ks[r][c + 1] = to_tf32(w.y);
        Ks[r][c + 2] = to_tf32(w.z); Ks[r][c + 3] = to_tf32(w.w);
    }
    __syncthreads();

    const int warp = tid >> 5;
    const int wm = warp & 3, wn = warp >> 2;
    wmma::fragment<wmma::accumulator, 16, 16, 8, float> acc[2];
    wmma::fill_fragment(acc[0], 0.f);
    wmma::fill_fragment(acc[1], 0.f);
#pragma unroll
    for (int k8 = 0; k8 < 64; k8 += 8) {
        wmma::fragment<wmma::matrix_a, 16, 16, 8, wmma::precision::tf32, wmma::row_major> af;
        wmma::fragment<wmma::matrix_b, 16, 16, 8, wmma::precision::tf32, wmma::col_major> bf0, bf1;
        wmma::load_matrix_sync(af, &Qs[wm * 16][k8], 68);
        wmma::load_matrix_sync(bf0, &Ks[wn * 32][k8], 68);
        wmma::load_matrix_sync(bf1, &Ks[wn * 32 + 16][k8], 68);
        wmma::mma_sync(acc[0], af, bf0, acc[0]);
        wmma::mma_sync(acc[1], af, bf1, acc[1]);
    }
#pragma unroll
    for (int ni = 0; ni < 2; ni++) {
#pragma unroll
        for (int t = 0; t < acc[ni].num_elements; t++) acc[ni].x[t] *= 0.125f;
        size_t idx = ((size_t)bh * Tv + qs + wm * 16) * Tv + ks + wn * 32 + ni * 16;
        wmma::store_matrix_sync(S + idx, acc[ni], Tv, wmma::mem_row_major);
    }
}

// ============================================================
// Causal row softmax in place; zeros masked tail up to next 64 boundary.
// ============================================================
__global__ void softmax_kernel(float* __restrict__ S)
{
    long long row = blockIdx.x;
    int t = (int)(row & (Tv - 1));
    float* Sr = S + row * (long long)Tv;
    int len = t + 1;
    int wlim = (t + 64) & ~63;
    int tid = threadIdx.x;
    __shared__ float red[TB];
    float m = -1e30f;
    for (int s = tid; s < len; s += TB) m = fmaxf(m, Sr[s]);
    red[tid] = m; __syncthreads();
    for (int st = TB / 2; st > 0; st >>= 1) { if (tid < st) red[tid] = fmaxf(red[tid], red[tid + st]); __syncthreads(); }
    float rowmax = red[0];
    __syncthreads();
    float sum = 0.f;
    for (int s = tid; s < len; s += TB) sum += expf(Sr[s] - rowmax);
    red[tid] = sum; __syncthreads();
    for (int st = TB / 2; st > 0; st >>= 1) { if (tid < st) red[tid] += red[tid + st]; __syncthreads(); }
    float inv = 1.f / red[0];
    for (int s = tid; s < wlim; s += TB)
        Sr[s] = (s < len) ? expf(Sr[s] - rowmax) * inv : 0.f;
}

// ============================================================
// O = P @ V via TF32 wmma; causal K-bound. Output token-major [n][h*D+d].
// 64x64 out tile, k-chunk 32. 8 warps (4 rows x 2 cols), warp 16x32.
// ============================================================
__global__ void av_wmma(const float* __restrict__ P, const float* __restrict__ V,
                        float* __restrict__ O)
{
    int bh = blockIdx.z, b = bh >> 4, h = bh & 15;
    int qs = blockIdx.x * 64;
    const float* Pr = P + (size_t)bh * Tv * Tv;
    const float* Vr = V + (size_t)bh * Tv * Dv;
    __shared__ float Ps[64][36];
    __shared__ float Vs[32][68];
    const int tid = threadIdx.x;
    const int warp = tid >> 5;
    const int wm = warp & 3, wn = warp >> 2;

    wmma::fragment<wmma::accumulator, 16, 16, 8, float> acc[2];
    wmma::fill_fragment(acc[0], 0.f);
    wmma::fill_fragment(acc[1], 0.f);

    const int pr = tid >> 2, pc = (tid & 3) << 3;   // P: 64 x 32
    const int vr = tid >> 3, vc = (tid & 7) << 3;   // V: 32 x 64

    int kend = qs + 64;
    for (int k0 = 0; k0 < kend; k0 += 32) {
#pragma unroll
        for (int i = 0; i < 2; i++) {
            float4 v = *(const float4*)(Pr + (size_t)(qs + pr) * Tv + k0 + pc + (i << 2));
            Ps[pr][pc + (i << 2) + 0] = to_tf32(v.x); Ps[pr][pc + (i << 2) + 1] = to_tf32(v.y);
            Ps[pr][pc + (i << 2) + 2] = to_tf32(v.z); Ps[pr][pc + (i << 2) + 3] = to_tf32(v.w);
        }
#pragma unroll
        for (int i = 0; i < 2; i++) {
            float4 v = *(const float4*)(Vr + (size_t)(k0 + vr) * Dv + vc + (i << 2));
            Vs[vr][vc + (i << 2) + 0] = to_tf32(v.x); Vs[vr][vc + (i << 2) + 1] = to_tf32(v.y);
            Vs[vr][vc + (i << 2) + 2] = to_tf32(v.z); Vs[vr][vc + (i << 2) + 3] = to_tf32(v.w);
        }
        __syncthreads();
#pragma unroll
        for (int k8 = 0; k8 < 32; k8 += 8) {
            wmma::fragment<wmma::matrix_a, 16, 16, 8, wmma::precision::tf32, wmma::row_major> af;
            wmma::fragment<wmma::matrix_b, 16, 16, 8, wmma::precision::tf32, wmma::row_major> bf0, bf1;
            wmma::load_matrix_sync(af, &Ps[wm * 16][k8], 36);
            wmma::load_matrix_sync(bf0, &Vs[k8][wn * 32], 68);
            wmma::load_matrix_sync(bf1, &Vs[k8][wn * 32 + 16], 68);
            wmma::mma_sync(acc[0], af, bf0, acc[0]);
            wmma::mma_sync(acc[1], af, bf1, acc[1]);
        }
        __syncthreads();
    }
#pragma unroll
    for (int ni = 0; ni < 2; ni++) {
        size_t idx = (size_t)(b * Tv + qs + wm * 16) * Cv + h * Dv + wn * 32 + ni * 16;
        wmma::store_matrix_sync(O + idx, acc[ni], Cv, wmma::mem_row_major);
    }
}

// ============================================================
// Router
// ============================================================
__global__ void router_kernel(const float* __restrict__ h2, const float* __restrict__ Wr,
                              const float* __restrict__ rb)
{
    int n = blockIdx.x, tid = threadIdx.x;
    const float* xr = h2 + (size_t)n * Cv;
    float part[Ev];
#pragma unroll
    for (int e = 0; e < Ev; e++) part[e] = 0.f;
    for (int c = tid; c < Cv; c += TB) {
        float xv = xr[c];
#pragma unroll
        for (int e = 0; e < Ev; e++) part[e] += xv * Wr[c * Ev + e];
    }
    __shared__ float sd[Ev][TB];
#pragma unroll
    for (int e = 0; e < Ev; e++) sd[e][tid] = part[e];
    __syncthreads();
    for (int st = TB / 2; st > 0; st >>= 1) {
        if (tid < st)
#pragma unroll
            for (int e = 0; e < Ev; e++) sd[e][tid] += sd[e][tid + st];
        __syncthreads();
    }
    if (tid == 0) {
        int best = 0; float bp = -1.f;
#pragma unroll
        for (int e = 0; e < Ev; e++) {
            float lg = fminf(fmaxf(sd[e][0] + rb[e], -50.f), 50.f);
            float pr = 1.f / (1.f + expf(-lg));
            if (pr > bp) { bp = pr; best = e; }
        }
        g_sel[n] = best;
        g_p[n]   = fminf(fmaxf(bp, 1e-8f), 1.f - 1e-8f);
    }
}

__global__ void zero_kernel() {
    int t = threadIdx.x;
    if (t < Ev) { g_cnt[t] = 0; g_cur[t] = 0; }
}
__global__ void hist_kernel() {
    int n = blockIdx.x * TB + threadIdx.x;
    if (n < Nv) atomicAdd(&g_cnt[g_sel[n]], 1);
}
__global__ void offsets_kernel() {
    int s = 0;
    for (int e = 0; e < Ev; e++) { g_off[e] = s; s += g_cnt[e]; }
}
__global__ void scatter_kernel() {
    int n = blockIdx.x * TB + threadIdx.x;
    if (n < Nv) {
        int e = g_sel[n];
        int pos = atomicAdd(&g_cur[e], 1);
        g_perm[g_off[e] + pos] = n;
    }
}

__global__ void silumul_kernel(const float* __restrict__ a, const float* __restrict__ b,
                               float* __restrict__ o)
{
    int i = blockIdx.x * TB + threadIdx.x;
    float v = a[i];
    o[i] = (v / (1.f + expf(-v))) * b[i];
}

__global__ void combine_kernel(const float* __restrict__ x1, const float* __restrict__ sh,
                               const float* __restrict__ yc, float* __restrict__ out)
{
    int s = blockIdx.x;
    int n = g_perm[s];
    float p = g_p[n];
    float tw = fminf(fmaxf(0.5f + p + 1e-8f, 0.5f), 2.0f);
    float wsh = 0.5f / tw, wex = p / tw;
    const float* a = x1 + (size_t)n * Cv;
    const float* b = sh + (size_t)n * Cv;
    const float* c = yc + (size_t)s * Cv;
    float* o = out + (size_t)n * Cv;
    for (int i = threadIdx.x; i < Cv; i += TB)
        o[i] = a[i] + wsh * b[i] + wex * c[i];
}

// ============================================================
// launcher
// ============================================================
extern "C" void kernel_launch(void* const* d_in, const int* in_sizes, int n_in,
                              void* d_out, int out_size)
{
    const float* x    = (const float*)d_in[0];
    const float* ln1  = (const float*)d_in[1];
    const float* ln2  = (const float*)d_in[2];
    const float* Wq   = (const float*)d_in[3];
    const float* Wkv  = (const float*)d_in[4];
    const float* Wk_up= (const float*)d_in[5];
    const float* Wv_up= (const float*)d_in[6];
    const float* Wo   = (const float*)d_in[7];
    const float* Wr   = (const float*)d_in[8];
    const float* rb   = (const float*)d_in[9];
    const float* sw1  = (const float*)d_in[10];
    const float* sw2  = (const float*)d_in[11];
    const float* sw3  = (const float*)d_in[12];
    const float* ew1  = (const float*)d_in[13];
    const float* ew2  = (const float*)d_in[14];
    const float* ew3  = (const float*)d_in[15];
    float* out = (float*)d_out;

    float *ph, *pq, *pkv, *pk, *pv, *pS, *pat, *px1, *ph2;
    float *pa1, *pa3, *pu, *psh, *pc1, *pc3, *puc, *pyc;
    cudaGetSymbolAddress((void**)&ph,  g_h);
    cudaGetSymbolAddress((void**)&pq,  g_q);
    cudaGetSymbolAddress((void**)&pkv, g_kv);
    cudaGetSymbolAddress((void**)&pk,  g_k);
    cudaGetSymbolAddress((void**)&pv,  g_v);
    cudaGetSymbolAddress((void**)&pS,  g_S);
    cudaGetSymbolAddress((void**)&pat, g_at);
    cudaGetSymbolAddress((void**)&px1, g_x1);
    cudaGetSymbolAddress((void**)&ph2, g_h2);
    cudaGetSymbolAddress((void**)&pa1, g_a1);
    cudaGetSymbolAddress((void**)&pa3, g_a3);
    cudaGetSymbolAddress((void**)&pu,  g_u);
    cudaGetSymbolAddress((void**)&psh, g_sh);
    cudaGetSymbolAddress((void**)&pc1, g_c1);
    cudaGetSymbolAddress((void**)&pc3, g_c3);
    cudaGetSymbolAddress((void**)&puc, g_uc);
    cudaGetSymbolAddress((void**)&pyc, g_yc);

    // ---- attention ----
    rmsnorm_kernel<<<Nv, TB>>>(x, ln1, ph);
    tgemm<<<dim3(Cv / 128, Nv / 128), TB>>>(ph, Wq,  pq,  nullptr, Cv, Cv, 1.f);
    tgemm<<<dim3(Lv / 128, Nv / 128), TB>>>(ph, Wkv, pkv, nullptr, Cv, Lv, 0.25f);
    kvup_wmma<<<dim3(Nv / 128, Hv * 2), TB>>>(pkv, Wk_up, Wv_up, pk, pv);
    rope_kernel<<<(Nv * Hv * 32) / TB, TB>>>(pq, Hv);
    rope_kernel<<<(Nv * Hv * 32) / TB, TB>>>(pk, 1);
    scores_wmma<<<dim3(Tv / 64, Tv / 64, BHv), TB>>>(pq, pk, pS);
    softmax_kernel<<<BHv * Tv, TB>>>(pS);
    av_wmma<<<dim3(Tv / 64, 1, BHv), TB>>>(pS, pv, pat);
    tgemm<<<dim3(Cv / 128, Nv / 128), TB>>>(pat, Wo, px1, x, Cv, Cv, 1.f);

    // ---- MoE ----
    rmsnorm_kernel<<<Nv, TB>>>(px1, ln2, ph2);
    router_kernel<<<Nv, TB>>>(ph2, Wr, rb);
    zero_kernel<<<1, 32>>>();
    hist_kernel<<<Nv / TB, TB>>>();
    offsets_kernel<<<1, 1>>>();
    scatter_kernel<<<Nv / TB, TB>>>();

    tgemm<<<dim3(Iv / 128, Nv / 128), TB>>>(ph2, sw1, pa1, nullptr, Cv, Iv, 1.f);
    tgemm<<<dim3(Iv / 128, Nv / 128), TB>>>(ph2, sw3, pa3, nullptr, Cv, Iv, 1.f);
    silumul_kernel<<<(Nv * Iv) / TB, TB>>>(pa1, pa3, pu);
    tgemm<<<dim3(Cv / 128, Nv / 128), TB>>>(pu, sw2, psh, nullptr, Iv, Cv, 1.f);

    gg_tgemm<true ><<<dim3(Nv / 128, Iv / 128, Ev), TB>>>(ph2, ew1, (size_t)Cv * Iv, Cv, Iv, pc1);
    gg_tgemm<true ><<<dim3(Nv / 128, Iv / 128, Ev), TB>>>(ph2, ew3, (size_t)Cv * Iv, Cv, Iv, pc3);
    silumul_kernel<<<(Nv * Iv) / TB, TB>>>(pc1, pc3, puc);
    gg_tgemm<false><<<dim3(Nv / 128, Cv / 128, Ev), TB>>>(puc, ew2, (size_t)Iv * Cv, Iv, Cv, pyc);

    combine_kernel<<<Nv, TB>>>(px1, psh, pyc, out);
}

// round 5
// speedup vs baseline: 3.4213x; 1.4393x over previous
#include <cuda_runtime.h>
#include <cuda_bf16.h>
#include <mma.h>
#include <cstdint>

using namespace nvcuda;

#define TB 256

// ---- problem constants ----
constexpr int Bv = 8, Tv = 1024, Hv = 16, Dv = 64, Cv = 1024, Lv = 256, Ev = 8, Iv = 2048;
constexpr int Nv  = Bv * Tv;   // 8192 tokens
constexpr int BHv = Bv * Hv;   // 128

// ---- scratch (device globals; allocation-free) ----
__device__ float g_kv [Nv * Lv];
__device__ float g_q  [Nv * Cv];
__device__ float g_k  [Nv * Cv];          // [b,h,t,d]
__device__ float g_v  [Nv * Cv];          // [b,h,t,d]
__device__ float g_S  [(size_t)BHv * Tv * Tv];   // scores / probs (512 MB)
__device__ float g_at [Nv * Cv];
__device__ float g_x1 [Nv * Cv];
__device__ float g_h2 [Nv * Cv];
__device__ float g_sh [Nv * Cv];
__device__ float g_c1 [Nv * Iv];
__device__ float g_c3 [Nv * Iv];
__device__ float g_a1 [Nv * Iv];
__device__ float g_a3 [Nv * Iv];
__device__ float g_yc [Nv * Cv];
__device__ int   g_sel[Nv];
__device__ float g_p  [Nv];
__device__ int   g_cnt[Ev];
__device__ int   g_off[Ev];
__device__ int   g_cur[Ev];
__device__ int   g_perm[Nv];

// bf16 activation buffers
__device__ __nv_bfloat16 g_hbf  [Nv * Cv];
__device__ __nv_bfloat16 g_h2bf [Nv * Cv];
__device__ __nv_bfloat16 g_atbf [Nv * Cv];
__device__ __nv_bfloat16 g_ubf  [Nv * Iv];
__device__ __nv_bfloat16 g_ucbf [Nv * Iv];

// bf16 weight buffers (converted per launch)
__device__ __nv_bfloat16 g_Wq_bf [Cv * Cv];
__device__ __nv_bfloat16 g_Wkv_bf[Cv * Lv];
__device__ __nv_bfloat16 g_Wo_bf [Cv * Cv];
__device__ __nv_bfloat16 g_sw1_bf[Cv * Iv];
__device__ __nv_bfloat16 g_sw3_bf[Cv * Iv];
__device__ __nv_bfloat16 g_sw2_bf[Iv * Cv];
__device__ __nv_bfloat16 g_ew1_bf[Ev * Cv * Iv];
__device__ __nv_bfloat16 g_ew3_bf[Ev * Cv * Iv];
__device__ __nv_bfloat16 g_ew2_bf[Ev * Iv * Cv];

__device__ __forceinline__ uint2 f4_to_bf4(float4 v) {
    __nv_bfloat162 lo = __floats2bfloat162_rn(v.x, v.y);
    __nv_bfloat162 hi = __floats2bfloat162_rn(v.z, v.w);
    uint2 r;
    r.x = *reinterpret_cast<unsigned int*>(&lo);
    r.y = *reinterpret_cast<unsigned int*>(&hi);
    return r;
}
__device__ __forceinline__ float to_tf32(float x) {
    float r; asm("cvt.rna.tf32.f32 %0, %1;" : "=f"(r) : "f"(x)); return r;
}
__device__ __forceinline__ void cp16(void* sdst, const void* gsrc) {
    uint32_t s = (uint32_t)__cvta_generic_to_shared(sdst);
    asm volatile("cp.async.ca.shared.global [%0], [%1], 16;" :: "r"(s), "l"(gsrc));
}
__device__ __forceinline__ void cp16z(void* sdst, const void* gsrc, bool p) {
    uint32_t s = (uint32_t)__cvta_generic_to_shared(sdst);
    asm volatile("cp.async.ca.shared.global [%0], [%1], 16, %2;" :: "r"(s), "l"(gsrc), "r"(p ? 16 : 0));
}
#define CP_COMMIT() asm volatile("cp.async.commit_group;")
#define CP_WAIT1()  asm volatile("cp.async.wait_group 1;")

// ============================================================
// fp32 -> bf16 convert (n multiple of 4)
// ============================================================
__global__ void f2bf_kernel(const float* __restrict__ in, __nv_bfloat16* __restrict__ out, int n)
{
    int i = (blockIdx.x * TB + threadIdx.x) << 2;
    if (i < n) {
        float4 v = *(const float4*)(in + i);
        *(uint2*)(out + i) = f4_to_bf4(v);
    }
}

// ============================================================
// RMSNorm: one block per token; dual fp32 (optional) + bf16 output
// ============================================================
__global__ void rmsnorm_kernel(const float* __restrict__ x, const float* __restrict__ w,
                               float* __restrict__ y, __nv_bfloat16* __restrict__ yb)
{
    int n = blockIdx.x, tid = threadIdx.x;
    const float* xr = x + (size_t)n * Cv;
    __shared__ float red[TB];
    float ss = 0.f;
    for (int c = tid; c < Cv; c += TB) { float v = xr[c]; ss += v * v; }
    red[tid] = ss; __syncthreads();
    for (int s = TB / 2; s > 0; s >>= 1) { if (tid < s) red[tid] += red[tid + s]; __syncthreads(); }
    float rs = rsqrtf(red[0] / (float)Cv + 1e-6f);
    __nv_bfloat16* ybr = yb + (size_t)n * Cv;
    float* yr = y ? y + (size_t)n * Cv : nullptr;
    for (int c = tid; c < Cv; c += TB) {
        float v = xr[c] * rs * w[c];
        ybr[c] = __float2bfloat16(v);
        if (yr) yr[c] = v;
    }
}

// ============================================================
// BF16-native cp.async 3-stage GEMM: C = alpha*A@B (+Res)
// A[M,K] bf16 row-major, B[K,N] bf16 row-major, C fp32.
// M,N mult of 128, K mult of 32 (>=96). 256 thr, warp tile 32x64.
// ============================================================
__global__ void tgemm_bf(const __nv_bfloat16* __restrict__ A, const __nv_bfloat16* __restrict__ B,
                         float* __restrict__ Cmat, const float* __restrict__ Res,
                         int K, int N, float alpha)
{
    __shared__ __align__(16) __nv_bfloat16 As[3][128][40];
    __shared__ __align__(16) __nv_bfloat16 Bs[3][32][136];
    const int tid  = threadIdx.x;
    const int warp = tid >> 5;
    const int wm   = warp & 3, wn = warp >> 2;
    const int bm   = blockIdx.y * 128, bn = blockIdx.x * 128;

    wmma::fragment<wmma::accumulator, 16, 16, 16, float> acc[2][4];
#pragma unroll
    for (int mi = 0; mi < 2; mi++)
#pragma unroll
        for (int ni = 0; ni < 4; ni++) wmma::fill_fragment(acc[mi][ni], 0.f);

    const int nch = K >> 5;

    auto issue = [&](int stage, int k0) {
#pragma unroll
        for (int i = 0; i < 2; i++) {
            int ch = (i << 8) + tid;
            int ar = ch >> 2, ac = (ch & 3) << 3;
            cp16(&As[stage][ar][ac], A + (size_t)(bm + ar) * K + k0 + ac);
        }
#pragma unroll
        for (int i = 0; i < 2; i++) {
            int ch = (i << 8) + tid;
            int br = ch >> 4, bc = (ch & 15) << 3;
            cp16(&Bs[stage][br][bc], B + (size_t)(k0 + br) * N + bn + bc);
        }
    };

    issue(0, 0);  CP_COMMIT();
    issue(1, 32); CP_COMMIT();

    for (int ch = 0; ch < nch; ch++) {
        CP_WAIT1();
        __syncthreads();
        if (ch + 2 < nch) issue((ch + 2) % 3, (ch + 2) << 5);
        CP_COMMIT();
        int buf = ch % 3;
#pragma unroll
        for (int ks = 0; ks < 2; ks++) {
            int k16 = ks << 4;
            wmma::fragment<wmma::matrix_a, 16, 16, 16, __nv_bfloat16, wmma::row_major> af[2];
            wmma::fragment<wmma::matrix_b, 16, 16, 16, __nv_bfloat16, wmma::row_major> bf[4];
#pragma unroll
            for (int mi = 0; mi < 2; mi++)
                wmma::load_matrix_sync(af[mi], &As[buf][wm * 32 + mi * 16][k16], 40);
#pragma unroll
            for (int ni = 0; ni < 4; ni++)
                wmma::load_matrix_sync(bf[ni], &Bs[buf][k16][wn * 64 + ni * 16], 136);
#pragma unroll
            for (int mi = 0; mi < 2; mi++)
#pragma unroll
                for (int ni = 0; ni < 4; ni++)
                    wmma::mma_sync(acc[mi][ni], af[mi], bf[ni], acc[mi][ni]);
        }
    }

#pragma unroll
    for (int mi = 0; mi < 2; mi++)
#pragma unroll
        for (int ni = 0; ni < 4; ni++) {
            size_t row = (size_t)(bm + wm * 32 + mi * 16);
            size_t col = (size_t)(bn + wn * 64 + ni * 16);
            float* cp = Cmat + row * N + col;
            if (Res) {
                wmma::fragment<wmma::accumulator, 16, 16, 16, float> rf;
                wmma::load_matrix_sync(rf, Res + row * N + col, N, wmma::mem_row_major);
#pragma unroll
                for (int t = 0; t < rf.num_elements; t++)
                    acc[mi][ni].x[t] = acc[mi][ni].x[t] * alpha + rf.x[t];
            } else if (alpha != 1.f) {
#pragma unroll
                for (int t = 0; t < acc[mi][ni].num_elements; t++)
                    acc[mi][ni].x[t] *= alpha;
            }
            wmma::store_matrix_sync(cp, acc[mi][ni], N, wmma::mem_row_major);
        }
}

// ============================================================
// Grouped (per-expert) BF16 cp.async GEMM with optional row gather.
// ============================================================
template <bool GATHER>
__global__ void gg_tgemm_bf(const __nv_bfloat16* __restrict__ A, const __nv_bfloat16* __restrict__ Bbase,
                            size_t strideB, int K, int N, float* __restrict__ Out)
{
    int e = blockIdx.z;
    int cnt = g_cnt[e];
    int base = blockIdx.x * 128;
    if (base >= cnt) return;
    int o = g_off[e];
    const __nv_bfloat16* B = Bbase + (size_t)e * strideB;

    __shared__ __align__(16) __nv_bfloat16 As[3][128][40];
    __shared__ __align__(16) __nv_bfloat16 Bs[3][32][136];
    __shared__ float stage[8 * 320];
    const int tid  = threadIdx.x;
    const int warp = tid >> 5;
    const int lane = tid & 31;
    const int wm   = warp & 3, wn = warp >> 2;
    const int bn   = blockIdx.y * 128;

    wmma::fragment<wmma::accumulator, 16, 16, 16, float> acc[2][4];
#pragma unroll
    for (int mi = 0; mi < 2; mi++)
#pragma unroll
        for (int ni = 0; ni < 4; ni++) wmma::fill_fragment(acc[mi][ni], 0.f);

    // per-thread A rows (2 chunks)
    int grow[2]; bool gv[2]; int arr[2]; int arc[2];
#pragma unroll
    for (int i = 0; i < 2; i++) {
        int ch = (i << 8) + tid;
        arr[i] = ch >> 2; arc[i] = (ch & 3) << 3;
        int lr = base + arr[i];
        gv[i] = lr < cnt;
        grow[i] = gv[i] ? (GATHER ? g_perm[o + lr] : (o + lr)) : 0;
    }

    const int nch = K >> 5;

    auto issue = [&](int stg, int k0) {
#pragma unroll
        for (int i = 0; i < 2; i++)
            cp16z(&As[stg][arr[i]][arc[i]], A + (size_t)grow[i] * K + k0 + arc[i], gv[i]);
#pragma unroll
        for (int i = 0; i < 2; i++) {
            int ch = (i << 8) + tid;
            int br = ch >> 4, bc = (ch & 15) << 3;
            cp16(&Bs[stg][br][bc], B + (size_t)(k0 + br) * N + bn + bc);
        }
    };

    issue(0, 0);  CP_COMMIT();
    issue(1, 32); CP_COMMIT();

    for (int ch = 0; ch < nch; ch++) {
        CP_WAIT1();
        __syncthreads();
        if (ch + 2 < nch) issue((ch + 2) % 3, (ch + 2) << 5);
        CP_COMMIT();
        int buf = ch % 3;
#pragma unroll
        for (int ks = 0; ks < 2; ks++) {
            int k16 = ks << 4;
            wmma::fragment<wmma::matrix_a, 16, 16, 16, __nv_bfloat16, wmma::row_major> af[2];
            wmma::fragment<wmma::matrix_b, 16, 16, 16, __nv_bfloat16, wmma::row_major> bf[4];
#pragma unroll
            for (int mi = 0; mi < 2; mi++)
                wmma::load_matrix_sync(af[mi], &As[buf][wm * 32 + mi * 16][k16], 40);
#pragma unroll
            for (int ni = 0; ni < 4; ni++)
                wmma::load_matrix_sync(bf[ni], &Bs[buf][k16][wn * 64 + ni * 16], 136);
#pragma unroll
            for (int mi = 0; mi < 2; mi++)
#pragma unroll
                for (int ni = 0; ni < 4; ni++)
                    wmma::mma_sync(acc[mi][ni], af[mi], bf[ni], acc[mi][ni]);
        }
    }

    float* st = stage + warp * 320;
    const int sr = lane >> 1, sc0 = (lane & 1) << 3;
#pragma unroll
    for (int mi = 0; mi < 2; mi++)
#pragma unroll
        for (int ni = 0; ni < 4; ni++) {
            wmma::store_matrix_sync(st, acc[mi][ni], 20, wmma::mem_row_major);
            __syncwarp();
            int lr = base + wm * 32 + mi * 16 + sr;
            if (lr < cnt) {
                size_t row = (size_t)(o + lr);
                int col = bn + wn * 64 + ni * 16 + sc0;
                float4 v0 = *(float4*)(st + sr * 20 + sc0);
                float4 v1 = *(float4*)(st + sr * 20 + sc0 + 4);
                *(float4*)(Out + row * N + col)     = v0;
                *(float4*)(Out + row * N + col + 4) = v1;
            }
            __syncwarp();
        }
}

// ============================================================
// K/V up-projection, bf16 wmma. grid (Nv/128, Hv*2). (fp32 inputs)
// ============================================================
__global__ void kvup_wmma(const float* __restrict__ kv,
                          const float* __restrict__ Wk_up, const float* __restrict__ Wv_up,
                          float* __restrict__ kout, float* __restrict__ vout)
{
    int y = blockIdx.y;
    int h = y >> 1, which = y & 1;
    const float* W = (which ? Wv_up : Wk_up) + (size_t)h * Lv * Dv;
    float* outp = which ? vout : kout;
    int bm = blockIdx.x * 128;

    __shared__ __nv_bfloat16 As[2][128][40];
    __shared__ __nv_bfloat16 Bs[2][32][72];
    const int tid  = threadIdx.x;
    const int warp = tid >> 5;
    const int wm   = warp & 3, wn = warp >> 2;

    wmma::fragment<wmma::accumulator, 16, 16, 16, float> acc[2][2];
#pragma unroll
    for (int mi = 0; mi < 2; mi++)
#pragma unroll
        for (int ni = 0; ni < 2; ni++) wmma::fill_fragment(acc[mi][ni], 0.f);

    const int ar0 = tid >> 3, ac = (tid & 7) << 2;
    const int br0 = tid >> 4, bc = (tid & 15) << 2;

    float4 aR[4], bR[2];
    const int nch = Lv >> 5;   // 8

#pragma unroll
    for (int i = 0; i < 4; i++)
        aR[i] = *(const float4*)(kv + (size_t)(bm + ar0 + (i << 5)) * Lv + ac);
#pragma unroll
    for (int i = 0; i < 2; i++)
        bR[i] = *(const float4*)(W + (size_t)(br0 + (i << 4)) * Dv + bc);
#pragma unroll
    for (int i = 0; i < 4; i++)
        *(uint2*)&As[0][ar0 + (i << 5)][ac] = f4_to_bf4(aR[i]);
#pragma unroll
    for (int i = 0; i < 2; i++)
        *(uint2*)&Bs[0][br0 + (i << 4)][bc] = f4_to_bf4(bR[i]);
    __syncthreads();

    int cur = 0;
    for (int ch = 0; ch < nch; ch++) {
        bool has = (ch + 1) < nch;
        if (has) {
            int k0 = (ch + 1) << 5;
#pragma unroll
            for (int i = 0; i < 4; i++)
                aR[i] = *(const float4*)(kv + (size_t)(bm + ar0 + (i << 5)) * Lv + k0 + ac);
#pragma unroll
            for (int i = 0; i < 2; i++)
                bR[i] = *(const float4*)(W + (size_t)(k0 + br0 + (i << 4)) * Dv + bc);
        }
#pragma unroll
        for (int ks = 0; ks < 2; ks++) {
            int k16 = ks << 4;
            wmma::fragment<wmma::matrix_a, 16, 16, 16, __nv_bfloat16, wmma::row_major> af[2];
            wmma::fragment<wmma::matrix_b, 16, 16, 16, __nv_bfloat16, wmma::row_major> bf[2];
#pragma unroll
            for (int mi = 0; mi < 2; mi++)
                wmma::load_matrix_sync(af[mi], &As[cur][wm * 32 + mi * 16][k16], 40);
#pragma unroll
            for (int ni = 0; ni < 2; ni++)
                wmma::load_matrix_sync(bf[ni], &Bs[cur][k16][wn * 32 + ni * 16], 72);
#pragma unroll
            for (int mi = 0; mi < 2; mi++)
#pragma unroll
                for (int ni = 0; ni < 2; ni++)
                    wmma::mma_sync(acc[mi][ni], af[mi], bf[ni], acc[mi][ni]);
        }
        if (has) {
            int nxt = cur ^ 1;
#pragma unroll
            for (int i = 0; i < 4; i++)
                *(uint2*)&As[nxt][ar0 + (i << 5)][ac] = f4_to_bf4(aR[i]);
#pragma unroll
            for (int i = 0; i < 2; i++)
                *(uint2*)&Bs[nxt][br0 + (i << 4)][bc] = f4_to_bf4(bR[i]);
        }
        __syncthreads();
        cur ^= 1;
    }

#pragma unroll
    for (int mi = 0; mi < 2; mi++) {
        int n0 = bm + wm * 32 + mi * 16;
        int b = n0 >> 10, t0 = n0 & 1023;
        float* bp = outp + ((size_t)(b * Hv + h) * Tv + t0) * Dv;
#pragma unroll
        for (int ni = 0; ni < 2; ni++)
            wmma::store_matrix_sync(bp + wn * 32 + ni * 16, acc[mi][ni], Dv, wmma::mem_row_major);
    }
}

// ============================================================
// RoPE in place on 64-wide head vectors.
// ============================================================
__global__ void rope_kernel(float* __restrict__ xp, int posDiv)
{
    int idx = blockIdx.x * TB + threadIdx.x;
    int outer = idx >> 5;
    int j = idx & 31;
    int pos = (outer / posDiv) & (Tv - 1);
    float invf = powf(100000.0f, -(float)j * (1.0f / 32.0f));
    float f = (float)pos * invf;
    float s, c; sincosf(f, &s, &c);
    float* p = xp + (size_t)outer * Dv;
    float x1 = p[j], x2 = p[j + 32];
    p[j]      = x1 * c - x2 * s;
    p[j + 32] = x1 * s + x2 * c;
}

// ============================================================
// Attention scores via TF32 wmma.
// ============================================================
__global__ void scores_wmma(const float* __restrict__ q, const float* __restrict__ k,
                            float* __restrict__ S)
{
    int bh = blockIdx.z, b = bh >> 4, h = bh & 15;
    int qs = blockIdx.y * 64, ks = blockIdx.x * 64;
    if (ks > qs) return;
    __shared__ float Qs[64][68];
    __shared__ float Ks[64][68];
    const int tid = threadIdx.x;
    const int r = tid >> 2, c0 = (tid & 3) << 4;
    const float* qrow = q + (size_t)(b * Tv + qs + r) * Cv + h * Dv;
    const float* krow = k + ((size_t)bh * Tv + ks + r) * Dv;
#pragma unroll
    for (int i = 0; i < 4; i++) {
        int c = c0 + (i << 2);
        float4 v = *(const float4*)(qrow + c);
        Qs[r][c + 0] = to_tf32(v.x); Qs[r][c + 1] = to_tf32(v.y);
        Qs[r][c + 2] = to_tf32(v.z); Qs[r][c + 3] = to_tf32(v.w);
        float4 w = *(const float4*)(krow + c);
        Ks[r][c + 0] = to_tf32(w.x); Ks[r][c + 1] = to_tf32(w.y);
        Ks[r][c + 2] = to_tf32(w.z); Ks[r][c + 3] = to_tf32(w.w);
    }
    __syncthreads();

    const int warp = tid >> 5;
    const int wm = warp & 3, wn = warp >> 2;
    wmma::fragment<wmma::accumulator, 16, 16, 8, float> acc[2];
    wmma::fill_fragment(acc[0], 0.f);
    wmma::fill_fragment(acc[1], 0.f);
#pragma unroll
    for (int k8 = 0; k8 < 64; k8 += 8) {
        wmma::fragment<wmma::matrix_a, 16, 16, 8, wmma::precision::tf32, wmma::row_major> af;
        wmma::fragment<wmma::matrix_b, 16, 16, 8, wmma::precision::tf32, wmma::col_major> bf0, bf1;
        wmma::load_matrix_sync(af, &Qs[wm * 16][k8], 68);
        wmma::load_matrix_sync(bf0, &Ks[wn * 32][k8], 68);
        wmma::load_matrix_sync(bf1, &Ks[wn * 32 + 16][k8], 68);
        wmma::mma_sync(acc[0], af, bf0, acc[0]);
        wmma::mma_sync(acc[1], af, bf1, acc[1]);
    }
#pragma unroll
    for (int ni = 0; ni < 2; ni++) {
#pragma unroll
        for (int t = 0; t < acc[ni].num_elements; t++) acc[ni].x[t] *= 0.125f;
        size_t idx = ((size_t)bh * Tv + qs + wm * 16) * Tv + ks + wn * 32 + ni * 16;
        wmma::store_matrix_sync(S + idx, acc[ni], Tv, wmma::mem_row_major);
    }
}

// ============================================================
// Causal row softmax in place; zeros masked tail up to next 64 boundary.
// ============================================================
__global__ void softmax_kernel(float* __restrict__ S)
{
    long long row = blockIdx.x;
    int t = (int)(row & (Tv - 1));
    float* Sr = S + row * (long long)Tv;
    int len = t + 1;
    int wlim = (t + 64) & ~63;
    int tid = threadIdx.x;
    __shared__ float red[TB];
    float m = -1e30f;
    for (int s = tid; s < len; s += TB) m = fmaxf(m, Sr[s]);
    red[tid] = m; __syncthreads();
    for (int st = TB / 2; st > 0; st >>= 1) { if (tid < st) red[tid] = fmaxf(red[tid], red[tid + st]); __syncthreads(); }
    float rowmax = red[0];
    __syncthreads();
    float sum = 0.f;
    for (int s = tid; s < len; s += TB) sum += expf(Sr[s] - rowmax);
    red[tid] = sum; __syncthreads();
    for (int st = TB / 2; st > 0; st >>= 1) { if (tid < st) red[tid] += red[tid + st]; __syncthreads(); }
    float inv = 1.f / red[0];
    for (int s = tid; s < wlim; s += TB)
        Sr[s] = (s < len) ? expf(Sr[s] - rowmax) * inv : 0.f;
}

// ============================================================
// O = P @ V via TF32 wmma; causal K-bound.
// ============================================================
__global__ void av_wmma(const float* __restrict__ P, const float* __restrict__ V,
                        float* __restrict__ O)
{
    int bh = blockIdx.z, b = bh >> 4, h = bh & 15;
    int qs = blockIdx.x * 64;
    const float* Pr = P + (size_t)bh * Tv * Tv;
    const float* Vr = V + (size_t)bh * Tv * Dv;
    __shared__ float Ps[64][36];
    __shared__ float Vs[32][68];
    const int tid = threadIdx.x;
    const int warp = tid >> 5;
    const int wm = warp & 3, wn = warp >> 2;

    wmma::fragment<wmma::accumulator, 16, 16, 8, float> acc[2];
    wmma::fill_fragment(acc[0], 0.f);
    wmma::fill_fragment(acc[1], 0.f);

    const int pr = tid >> 2, pc = (tid & 3) << 3;
    const int vr = tid >> 3, vc = (tid & 7) << 3;

    int kend = qs + 64;
    for (int k0 = 0; k0 < kend; k0 += 32) {
#pragma unroll
        for (int i = 0; i < 2; i++) {
            float4 v = *(const float4*)(Pr + (size_t)(qs + pr) * Tv + k0 + pc + (i << 2));
            Ps[pr][pc + (i << 2) + 0] = to_tf32(v.x); Ps[pr][pc + (i << 2) + 1] = to_tf32(v.y);
            Ps[pr][pc + (i << 2) + 2] = to_tf32(v.z); Ps[pr][pc + (i << 2) + 3] = to_tf32(v.w);
        }
#pragma unroll
        for (int i = 0; i < 2; i++) {
            float4 v = *(const float4*)(Vr + (size_t)(k0 + vr) * Dv + vc + (i << 2));
            Vs[vr][vc + (i << 2) + 0] = to_tf32(v.x); Vs[vr][vc + (i << 2) + 1] = to_tf32(v.y);
            Vs[vr][vc + (i << 2) + 2] = to_tf32(v.z); Vs[vr][vc + (i << 2) + 3] = to_tf32(v.w);
        }
        __syncthreads();
#pragma unroll
        for (int k8 = 0; k8 < 32; k8 += 8) {
            wmma::fragment<wmma::matrix_a, 16, 16, 8, wmma::precision::tf32, wmma::row_major> af;
            wmma::fragment<wmma::matrix_b, 16, 16, 8, wmma::precision::tf32, wmma::row_major> bf0, bf1;
            wmma::load_matrix_sync(af, &Ps[wm * 16][k8], 36);
            wmma::load_matrix_sync(bf0, &Vs[k8][wn * 32], 68);
            wmma::load_matrix_sync(bf1, &Vs[k8][wn * 32 + 16], 68);
            wmma::mma_sync(acc[0], af, bf0, acc[0]);
            wmma::mma_sync(acc[1], af, bf1, acc[1]);
        }
        __syncthreads();
    }
#pragma unroll
    for (int ni = 0; ni < 2; ni++) {
        size_t idx = (size_t)(b * Tv + qs + wm * 16) * Cv + h * Dv + wn * 32 + ni * 16;
        wmma::store_matrix_sync(O + idx, acc[ni], Cv, wmma::mem_row_major);
    }
}

// ============================================================
// Router
// ============================================================
__global__ void router_kernel(const float* __restrict__ h2, const float* __restrict__ Wr,
                              const float* __restrict__ rb)
{
    int n = blockIdx.x, tid = threadIdx.x;
    const float* xr = h2 + (size_t)n * Cv;
    float part[Ev];
#pragma unroll
    for (int e = 0; e < Ev; e++) part[e] = 0.f;
    for (int c = tid; c < Cv; c += TB) {
        float xv = xr[c];
#pragma unroll
        for (int e = 0; e < Ev; e++) part[e] += xv * Wr[c * Ev + e];
    }
    __shared__ float sd[Ev][TB];
#pragma unroll
    for (int e = 0; e < Ev; e++) sd[e][tid] = part[e];
    __syncthreads();
    for (int st = TB / 2; st > 0; st >>= 1) {
        if (tid < st)
#pragma unroll
            for (int e = 0; e < Ev; e++) sd[e][tid] += sd[e][tid + st];
        __syncthreads();
    }
    if (tid == 0) {
        int best = 0; float bp = -1.f;
#pragma unroll
        for (int e = 0; e < Ev; e++) {
            float lg = fminf(fmaxf(sd[e][0] + rb[e], -50.f), 50.f);
            float pr = 1.f / (1.f + expf(-lg));
            if (pr > bp) { bp = pr; best = e; }
        }
        g_sel[n] = best;
        g_p[n]   = fminf(fmaxf(bp, 1e-8f), 1.f - 1e-8f);
    }
}

__global__ void zero_kernel() {
    int t = threadIdx.x;
    if (t < Ev) { g_cnt[t] = 0; g_cur[t] = 0; }
}
__global__ void hist_kernel() {
    int n = blockIdx.x * TB + threadIdx.x;
    if (n < Nv) atomicAdd(&g_cnt[g_sel[n]], 1);
}
__global__ void offsets_kernel() {
    int s = 0;
    for (int e = 0; e < Ev; e++) { g_off[e] = s; s += g_cnt[e]; }
}
__global__ void scatter_kernel() {
    int n = blockIdx.x * TB + threadIdx.x;
    if (n < Nv) {
        int e = g_sel[n];
        int pos = atomicAdd(&g_cur[e], 1);
        g_perm[g_off[e] + pos] = n;
    }
}

// silu(a)*b -> bf16 out (vectorized by 4; n multiple of 4)
__global__ void silumul_kernel(const float* __restrict__ a, const float* __restrict__ b,
                               __nv_bfloat16* __restrict__ o)
{
    int i = (blockIdx.x * TB + threadIdx.x) << 2;
    float4 va = *(const float4*)(a + i);
    float4 vb = *(const float4*)(b + i);
    float4 r;
    r.x = (va.x / (1.f + expf(-va.x))) * vb.x;
    r.y = (va.y / (1.f + expf(-va.y))) * vb.y;
    r.z = (va.z / (1.f + expf(-va.z))) * vb.z;
    r.w = (va.w / (1.f + expf(-va.w))) * vb.w;
    *(uint2*)(o + i) = f4_to_bf4(r);
}

__global__ void combine_kernel(const float* __restrict__ x1, const float* __restrict__ sh,
                               const float* __restrict__ yc, float* __restrict__ out)
{
    int s = blockIdx.x;
    int n = g_perm[s];
    float p = g_p[n];
    float tw = fminf(fmaxf(0.5f + p + 1e-8f, 0.5f), 2.0f);
    float wsh = 0.5f / tw, wex = p / tw;
    const float* a = x1 + (size_t)n * Cv;
    const float* b = sh + (size_t)n * Cv;
    const float* c = yc + (size_t)s * Cv;
    float* o = out + (size_t)n * Cv;
    for (int i = threadIdx.x; i < Cv; i += TB)
        o[i] = a[i] + wsh * b[i] + wex * c[i];
}

// ============================================================
// launcher
// ============================================================
extern "C" void kernel_launch(void* const* d_in, const int* in_sizes, int n_in,
                              void* d_out, int out_size)
{
    const float* x    = (const float*)d_in[0];
    const float* ln1  = (const float*)d_in[1];
    const float* ln2  = (const float*)d_in[2];
    const float* Wq   = (const float*)d_in[3];
    const float* Wkv  = (const float*)d_in[4];
    const float* Wk_up= (const float*)d_in[5];
    const float* Wv_up= (const float*)d_in[6];
    const float* Wo   = (const float*)d_in[7];
    const float* Wr   = (const float*)d_in[8];
    const float* rb   = (const float*)d_in[9];
    const float* sw1  = (const float*)d_in[10];
    const float* sw2  = (const float*)d_in[11];
    const float* sw3  = (const float*)d_in[12];
    const float* ew1  = (const float*)d_in[13];
    const float* ew2  = (const float*)d_in[14];
    const float* ew3  = (const float*)d_in[15];
    float* out = (float*)d_out;

    float *pkv, *pq, *pk, *pv, *pS, *pat, *px1, *ph2, *psh, *pc1, *pc3, *pa1, *pa3, *pyc;
    __nv_bfloat16 *phbf, *ph2bf, *patbf, *pubf, *pucbf;
    __nv_bfloat16 *wq, *wkv, *wo, *s1, *s3, *s2, *e1, *e3, *e2;
    cudaGetSymbolAddress((void**)&pkv, g_kv);
    cudaGetSymbolAddress((void**)&pq,  g_q);
    cudaGetSymbolAddress((void**)&pk,  g_k);
    cudaGetSymbolAddress((void**)&pv,  g_v);
    cudaGetSymbolAddress((void**)&pS,  g_S);
    cudaGetSymbolAddress((void**)&pat, g_at);
    cudaGetSymbolAddress((void**)&px1, g_x1);
    cudaGetSymbolAddress((void**)&ph2, g_h2);
    cudaGetSymbolAddress((void**)&psh, g_sh);
    cudaGetSymbolAddress((void**)&pc1, g_c1);
    cudaGetSymbolAddress((void**)&pc3, g_c3);
    cudaGetSymbolAddress((void**)&pa1, g_a1);
    cudaGetSymbolAddress((void**)&pa3, g_a3);
    cudaGetSymbolAddress((void**)&pyc, g_yc);
    cudaGetSymbolAddress((void**)&phbf,  g_hbf);
    cudaGetSymbolAddress((void**)&ph2bf, g_h2bf);
    cudaGetSymbolAddress((void**)&patbf, g_atbf);
    cudaGetSymbolAddress((void**)&pubf,  g_ubf);
    cudaGetSymbolAddress((void**)&pucbf, g_ucbf);
    cudaGetSymbolAddress((void**)&wq,  g_Wq_bf);
    cudaGetSymbolAddress((void**)&wkv, g_Wkv_bf);
    cudaGetSymbolAddress((void**)&wo,  g_Wo_bf);
    cudaGetSymbolAddress((void**)&s1,  g_sw1_bf);
    cudaGetSymbolAddress((void**)&s3,  g_sw3_bf);
    cudaGetSymbolAddress((void**)&s2,  g_sw2_bf);
    cudaGetSymbolAddress((void**)&e1,  g_ew1_bf);
    cudaGetSymbolAddress((void**)&e3,  g_ew3_bf);
    cudaGetSymbolAddress((void**)&e2,  g_ew2_bf);

    auto cvt = [](const float* in, __nv_bfloat16* outp, int n) {
        f2bf_kernel<<<n / (TB * 4), TB>>>(in, outp, n);
    };

    // ---- weight conversion (bf16) ----
    cvt(Wq,  wq,  Cv * Cv);
    cvt(Wkv, wkv, Cv * Lv);
    cvt(Wo,  wo,  Cv * Cv);
    cvt(sw1, s1,  Cv * Iv);
    cvt(sw3, s3,  Cv * Iv);
    cvt(sw2, s2,  Iv * Cv);
    cvt(ew1, e1,  Ev * Cv * Iv);
    cvt(ew3, e3,  Ev * Cv * Iv);
    cvt(ew2, e2,  Ev * Iv * Cv);

    // ---- attention ----
    rmsnorm_kernel<<<Nv, TB>>>(x, ln1, nullptr, phbf);
    tgemm_bf<<<dim3(Cv / 128, Nv / 128), TB>>>(phbf, wq,  pq,  nullptr, Cv, Cv, 1.f);
    tgemm_bf<<<dim3(Lv / 128, Nv / 128), TB>>>(phbf, wkv, pkv, nullptr, Cv, Lv, 0.25f);
    kvup_wmma<<<dim3(Nv / 128, Hv * 2), TB>>>(pkv, Wk_up, Wv_up, pk, pv);
    rope_kernel<<<(Nv * Hv * 32) / TB, TB>>>(pq, Hv);
    rope_kernel<<<(Nv * Hv * 32) / TB, TB>>>(pk, 1);
    scores_wmma<<<dim3(Tv / 64, Tv / 64, BHv), TB>>>(pq, pk, pS);
    softmax_kernel<<<BHv * Tv, TB>>>(pS);
    av_wmma<<<dim3(Tv / 64, 1, BHv), TB>>>(pS, pv, pat);
    f2bf_kernel<<<(Nv * Cv) / (TB * 4), TB>>>(pat, patbf, Nv * Cv);
    tgemm_bf<<<dim3(Cv / 128, Nv / 128), TB>>>(patbf, wo, px1, x, Cv, Cv, 1.f);

    // ---- MoE ----
    rmsnorm_kernel<<<Nv, TB>>>(px1, ln2, ph2, ph2bf);
    router_kernel<<<Nv, TB>>>(ph2, Wr, rb);
    zero_kernel<<<1, 32>>>();
    hist_kernel<<<Nv / TB, TB>>>();
    offsets_kernel<<<1, 1>>>();
    scatter_kernel<<<Nv / TB, TB>>>();

    tgemm_bf<<<dim3(Iv / 128, Nv / 128), TB>>>(ph2bf, s1, pa1, nullptr, Cv, Iv, 1.f);
    tgemm_bf<<<dim3(Iv / 128, Nv / 128), TB>>>(ph2bf, s3, pa3, nullptr, Cv, Iv, 1.f);
    silumul_kernel<<<(Nv * Iv) / (TB * 4), TB>>>(pa1, pa3, pubf);
    tgemm_bf<<<dim3(Cv / 128, Nv / 128), TB>>>(pubf, s2, psh, nullptr, Iv, Cv, 1.f);

    gg_tgemm_bf<true ><<<dim3(Nv / 128, Iv / 128, Ev), TB>>>(ph2bf, e1, (size_t)Cv * Iv, Cv, Iv, pc1);
    gg_tgemm_bf<true ><<<dim3(Nv / 128, Iv / 128, Ev), TB>>>(ph2bf, e3, (size_t)Cv * Iv, Cv, Iv, pc3);
    silumul_kernel<<<(Nv * Iv) / (TB * 4), TB>>>(pc1, pc3, pucbf);
    gg_tgemm_bf<false><<<dim3(Nv / 128, Cv / 128, Ev), TB>>>(pucbf, e2, (size_t)Iv * Cv, Iv, Cv, pyc);

    combine_kernel<<<Nv, TB>>>(px1, psh, pyc, out);
}

// round 6
// speedup vs baseline: 3.8343x; 1.1207x over previous
#include <cuda_runtime.h>
#include <cuda_bf16.h>
#include <mma.h>
#include <cstdint>

using namespace nvcuda;

#define TB 256

// ---- problem constants ----
constexpr int Bv = 8, Tv = 1024, Hv = 16, Dv = 64, Cv = 1024, Lv = 256, Ev = 8, Iv = 2048;
constexpr int Nv  = Bv * Tv;   // 8192 tokens
constexpr int BHv = Bv * Hv;   // 128

// ---- scratch (device globals; allocation-free) ----
__device__ float g_kv [Nv * Lv];
__device__ float g_q  [Nv * Cv];
__device__ float g_k  [Nv * Cv];          // [b,h,t,d]
__device__ float g_v  [Nv * Cv];          // [b,h,t,d]
__device__ float g_x1 [Nv * Cv];
__device__ float g_h2 [Nv * Cv];
__device__ float g_sh [Nv * Cv];
__device__ float g_c1 [Nv * Iv];
__device__ float g_c3 [Nv * Iv];
__device__ float g_a1 [Nv * Iv];
__device__ float g_a3 [Nv * Iv];
__device__ float g_yc [Nv * Cv];
__device__ int   g_sel[Nv];
__device__ float g_p  [Nv];
__device__ int   g_cnt[Ev];
__device__ int   g_off[Ev];
__device__ int   g_cur[Ev];
__device__ int   g_perm[Nv];

// bf16 activation buffers
__device__ __nv_bfloat16 g_hbf  [Nv * Cv];
__device__ __nv_bfloat16 g_h2bf [Nv * Cv];
__device__ __nv_bfloat16 g_atbf [Nv * Cv];
__device__ __nv_bfloat16 g_ubf  [Nv * Iv];
__device__ __nv_bfloat16 g_ucbf [Nv * Iv];

// bf16 weight buffers (converted per launch)
__device__ __nv_bfloat16 g_Wq_bf [Cv * Cv];
__device__ __nv_bfloat16 g_Wkv_bf[Cv * Lv];
__device__ __nv_bfloat16 g_Wo_bf [Cv * Cv];
__device__ __nv_bfloat16 g_sw1_bf[Cv * Iv];
__device__ __nv_bfloat16 g_sw3_bf[Cv * Iv];
__device__ __nv_bfloat16 g_sw2_bf[Iv * Cv];
__device__ __nv_bfloat16 g_ew1_bf[Ev * Cv * Iv];
__device__ __nv_bfloat16 g_ew3_bf[Ev * Cv * Iv];
__device__ __nv_bfloat16 g_ew2_bf[Ev * Iv * Cv];

__device__ __forceinline__ uint2 f4_to_bf4(float4 v) {
    __nv_bfloat162 lo = __floats2bfloat162_rn(v.x, v.y);
    __nv_bfloat162 hi = __floats2bfloat162_rn(v.z, v.w);
    uint2 r;
    r.x = *reinterpret_cast<unsigned int*>(&lo);
    r.y = *reinterpret_cast<unsigned int*>(&hi);
    return r;
}
__device__ __forceinline__ float to_tf32(float x) {
    float r; asm("cvt.rna.tf32.f32 %0, %1;" : "=f"(r) : "f"(x)); return r;
}
__device__ __forceinline__ void cp16(void* sdst, const void* gsrc) {
    uint32_t s = (uint32_t)__cvta_generic_to_shared(sdst);
    asm volatile("cp.async.ca.shared.global [%0], [%1], 16;" :: "r"(s), "l"(gsrc));
}
__device__ __forceinline__ void cp16z(void* sdst, const void* gsrc, bool p) {
    uint32_t s = (uint32_t)__cvta_generic_to_shared(sdst);
    asm volatile("cp.async.ca.shared.global [%0], [%1], 16, %2;" :: "r"(s), "l"(gsrc), "r"(p ? 16 : 0));
}
#define CP_COMMIT() asm volatile("cp.async.commit_group;")
#define CP_WAIT1()  asm volatile("cp.async.wait_group 1;")
#define CP_WAIT0()  asm volatile("cp.async.wait_group 0;")

// ============================================================
// fp32 -> bf16 convert (n multiple of 4)
// ============================================================
__global__ void f2bf_kernel(const float* __restrict__ in, __nv_bfloat16* __restrict__ out, int n)
{
    int i = (blockIdx.x * TB + threadIdx.x) << 2;
    if (i < n) {
        float4 v = *(const float4*)(in + i);
        *(uint2*)(out + i) = f4_to_bf4(v);
    }
}

// ============================================================
// RMSNorm: one block per token; dual fp32 (optional) + bf16 output
// ============================================================
__global__ void rmsnorm_kernel(const float* __restrict__ x, const float* __restrict__ w,
                               float* __restrict__ y, __nv_bfloat16* __restrict__ yb)
{
    int n = blockIdx.x, tid = threadIdx.x;
    const float* xr = x + (size_t)n * Cv;
    __shared__ float red[TB];
    float ss = 0.f;
    for (int c = tid; c < Cv; c += TB) { float v = xr[c]; ss += v * v; }
    red[tid] = ss; __syncthreads();
    for (int s = TB / 2; s > 0; s >>= 1) { if (tid < s) red[tid] += red[tid + s]; __syncthreads(); }
    float rs = rsqrtf(red[0] / (float)Cv + 1e-6f);
    __nv_bfloat16* ybr = yb + (size_t)n * Cv;
    float* yr = y ? y + (size_t)n * Cv : nullptr;
    for (int c = tid; c < Cv; c += TB) {
        float v = xr[c] * rs * w[c];
        ybr[c] = __float2bfloat16(v);
        if (yr) yr[c] = v;
    }
}

// ============================================================
// BF16-native cp.async 3-stage GEMM: C = alpha*A@B (+Res)
// ============================================================
__global__ void tgemm_bf(const __nv_bfloat16* __restrict__ A, const __nv_bfloat16* __restrict__ B,
                         float* __restrict__ Cmat, const float* __restrict__ Res,
                         int K, int N, float alpha)
{
    __shared__ __align__(16) __nv_bfloat16 As[3][128][40];
    __shared__ __align__(16) __nv_bfloat16 Bs[3][32][136];
    const int tid  = threadIdx.x;
    const int warp = tid >> 5;
    const int wm   = warp & 3, wn = warp >> 2;
    const int bm   = blockIdx.y * 128, bn = blockIdx.x * 128;

    wmma::fragment<wmma::accumulator, 16, 16, 16, float> acc[2][4];
#pragma unroll
    for (int mi = 0; mi < 2; mi++)
#pragma unroll
        for (int ni = 0; ni < 4; ni++) wmma::fill_fragment(acc[mi][ni], 0.f);

    const int nch = K >> 5;

    auto issue = [&](int stage, int k0) {
#pragma unroll
        for (int i = 0; i < 2; i++) {
            int ch = (i << 8) + tid;
            int ar = ch >> 2, ac = (ch & 3) << 3;
            cp16(&As[stage][ar][ac], A + (size_t)(bm + ar) * K + k0 + ac);
        }
#pragma unroll
        for (int i = 0; i < 2; i++) {
            int ch = (i << 8) + tid;
            int br = ch >> 4, bc = (ch & 15) << 3;
            cp16(&Bs[stage][br][bc], B + (size_t)(k0 + br) * N + bn + bc);
        }
    };

    issue(0, 0);  CP_COMMIT();
    issue(1, 32); CP_COMMIT();

    for (int ch = 0; ch < nch; ch++) {
        CP_WAIT1();
        __syncthreads();
        if (ch + 2 < nch) issue((ch + 2) % 3, (ch + 2) << 5);
        CP_COMMIT();
        int buf = ch % 3;
#pragma unroll
        for (int ks = 0; ks < 2; ks++) {
            int k16 = ks << 4;
            wmma::fragment<wmma::matrix_a, 16, 16, 16, __nv_bfloat16, wmma::row_major> af[2];
            wmma::fragment<wmma::matrix_b, 16, 16, 16, __nv_bfloat16, wmma::row_major> bf[4];
#pragma unroll
            for (int mi = 0; mi < 2; mi++)
                wmma::load_matrix_sync(af[mi], &As[buf][wm * 32 + mi * 16][k16], 40);
#pragma unroll
            for (int ni = 0; ni < 4; ni++)
                wmma::load_matrix_sync(bf[ni], &Bs[buf][k16][wn * 64 + ni * 16], 136);
#pragma unroll
            for (int mi = 0; mi < 2; mi++)
#pragma unroll
                for (int ni = 0; ni < 4; ni++)
                    wmma::mma_sync(acc[mi][ni], af[mi], bf[ni], acc[mi][ni]);
        }
    }

#pragma unroll
    for (int mi = 0; mi < 2; mi++)
#pragma unroll
        for (int ni = 0; ni < 4; ni++) {
            size_t row = (size_t)(bm + wm * 32 + mi * 16);
            size_t col = (size_t)(bn + wn * 64 + ni * 16);
            float* cp = Cmat + row * N + col;
            if (Res) {
                wmma::fragment<wmma::accumulator, 16, 16, 16, float> rf;
                wmma::load_matrix_sync(rf, Res + row * N + col, N, wmma::mem_row_major);
#pragma unroll
                for (int t = 0; t < rf.num_elements; t++)
                    acc[mi][ni].x[t] = acc[mi][ni].x[t] * alpha + rf.x[t];
            } else if (alpha != 1.f) {
#pragma unroll
                for (int t = 0; t < acc[mi][ni].num_elements; t++)
                    acc[mi][ni].x[t] *= alpha;
            }
            wmma::store_matrix_sync(cp, acc[mi][ni], N, wmma::mem_row_major);
        }
}

// ============================================================
// Grouped (per-expert) BF16 cp.async GEMM with optional row gather.
// ============================================================
template <bool GATHER>
__global__ void gg_tgemm_bf(const __nv_bfloat16* __restrict__ A, const __nv_bfloat16* __restrict__ Bbase,
                            size_t strideB, int K, int N, float* __restrict__ Out)
{
    int e = blockIdx.z;
    int cnt = g_cnt[e];
    int base = blockIdx.x * 128;
    if (base >= cnt) return;
    int o = g_off[e];
    const __nv_bfloat16* B = Bbase + (size_t)e * strideB;

    __shared__ __align__(16) __nv_bfloat16 As[3][128][40];
    __shared__ __align__(16) __nv_bfloat16 Bs[3][32][136];
    __shared__ float stage[8 * 320];
    const int tid  = threadIdx.x;
    const int warp = tid >> 5;
    const int lane = tid & 31;
    const int wm   = warp & 3, wn = warp >> 2;
    const int bn   = blockIdx.y * 128;

    wmma::fragment<wmma::accumulator, 16, 16, 16, float> acc[2][4];
#pragma unroll
    for (int mi = 0; mi < 2; mi++)
#pragma unroll
        for (int ni = 0; ni < 4; ni++) wmma::fill_fragment(acc[mi][ni], 0.f);

    int grow[2]; bool gv[2]; int arr[2]; int arc[2];
#pragma unroll
    for (int i = 0; i < 2; i++) {
        int ch = (i << 8) + tid;
        arr[i] = ch >> 2; arc[i] = (ch & 3) << 3;
        int lr = base + arr[i];
        gv[i] = lr < cnt;
        grow[i] = gv[i] ? (GATHER ? g_perm[o + lr] : (o + lr)) : 0;
    }

    const int nch = K >> 5;

    auto issue = [&](int stg, int k0) {
#pragma unroll
        for (int i = 0; i < 2; i++)
            cp16z(&As[stg][arr[i]][arc[i]], A + (size_t)grow[i] * K + k0 + arc[i], gv[i]);
#pragma unroll
        for (int i = 0; i < 2; i++) {
            int ch = (i << 8) + tid;
            int br = ch >> 4, bc = (ch & 15) << 3;
            cp16(&Bs[stg][br][bc], B + (size_t)(k0 + br) * N + bn + bc);
        }
    };

    issue(0, 0);  CP_COMMIT();
    issue(1, 32); CP_COMMIT();

    for (int ch = 0; ch < nch; ch++) {
        CP_WAIT1();
        __syncthreads();
        if (ch + 2 < nch) issue((ch + 2) % 3, (ch + 2) << 5);
        CP_COMMIT();
        int buf = ch % 3;
#pragma unroll
        for (int ks = 0; ks < 2; ks++) {
            int k16 = ks << 4;
            wmma::fragment<wmma::matrix_a, 16, 16, 16, __nv_bfloat16, wmma::row_major> af[2];
            wmma::fragment<wmma::matrix_b, 16, 16, 16, __nv_bfloat16, wmma::row_major> bf[4];
#pragma unroll
            for (int mi = 0; mi < 2; mi++)
                wmma::load_matrix_sync(af[mi], &As[buf][wm * 32 + mi * 16][k16], 40);
#pragma unroll
            for (int ni = 0; ni < 4; ni++)
                wmma::load_matrix_sync(bf[ni], &Bs[buf][k16][wn * 64 + ni * 16], 136);
#pragma unroll
            for (int mi = 0; mi < 2; mi++)
#pragma unroll
                for (int ni = 0; ni < 4; ni++)
                    wmma::mma_sync(acc[mi][ni], af[mi], bf[ni], acc[mi][ni]);
        }
    }

    float* st = stage + warp * 320;
    const int sr = lane >> 1, sc0 = (lane & 1) << 3;
#pragma unroll
    for (int mi = 0; mi < 2; mi++)
#pragma unroll
        for (int ni = 0; ni < 4; ni++) {
            wmma::store_matrix_sync(st, acc[mi][ni], 20, wmma::mem_row_major);
            __syncwarp();
            int lr = base + wm * 32 + mi * 16 + sr;
            if (lr < cnt) {
                size_t row = (size_t)(o + lr);
                int col = bn + wn * 64 + ni * 16 + sc0;
                float4 v0 = *(float4*)(st + sr * 20 + sc0);
                float4 v1 = *(float4*)(st + sr * 20 + sc0 + 4);
                *(float4*)(Out + row * N + col)     = v0;
                *(float4*)(Out + row * N + col + 4) = v1;
            }
            __syncwarp();
        }
}

// ============================================================
// K/V up-projection, bf16 wmma. grid (Nv/128, Hv*2). (fp32 inputs)
// ============================================================
__global__ void kvup_wmma(const float* __restrict__ kv,
                          const float* __restrict__ Wk_up, const float* __restrict__ Wv_up,
                          float* __restrict__ kout, float* __restrict__ vout)
{
    int y = blockIdx.y;
    int h = y >> 1, which = y & 1;
    const float* W = (which ? Wv_up : Wk_up) + (size_t)h * Lv * Dv;
    float* outp = which ? vout : kout;
    int bm = blockIdx.x * 128;

    __shared__ __nv_bfloat16 As[2][128][40];
    __shared__ __nv_bfloat16 Bs[2][32][72];
    const int tid  = threadIdx.x;
    const int warp = tid >> 5;
    const int wm   = warp & 3, wn = warp >> 2;

    wmma::fragment<wmma::accumulator, 16, 16, 16, float> acc[2][2];
#pragma unroll
    for (int mi = 0; mi < 2; mi++)
#pragma unroll
        for (int ni = 0; ni < 2; ni++) wmma::fill_fragment(acc[mi][ni], 0.f);

    const int ar0 = tid >> 3, ac = (tid & 7) << 2;
    const int br0 = tid >> 4, bc = (tid & 15) << 2;

    float4 aR[4], bR[2];
    const int nch = Lv >> 5;   // 8

#pragma unroll
    for (int i = 0; i < 4; i++)
        aR[i] = *(const float4*)(kv + (size_t)(bm + ar0 + (i << 5)) * Lv + ac);
#pragma unroll
    for (int i = 0; i < 2; i++)
        bR[i] = *(const float4*)(W + (size_t)(br0 + (i << 4)) * Dv + bc);
#pragma unroll
    for (int i = 0; i < 4; i++)
        *(uint2*)&As[0][ar0 + (i << 5)][ac] = f4_to_bf4(aR[i]);
#pragma unroll
    for (int i = 0; i < 2; i++)
        *(uint2*)&Bs[0][br0 + (i << 4)][bc] = f4_to_bf4(bR[i]);
    __syncthreads();

    int cur = 0;
    for (int ch = 0; ch < nch; ch++) {
        bool has = (ch + 1) < nch;
        if (has) {
            int k0 = (ch + 1) << 5;
#pragma unroll
            for (int i = 0; i < 4; i++)
                aR[i] = *(const float4*)(kv + (size_t)(bm + ar0 + (i << 5)) * Lv + k0 + ac);
#pragma unroll
            for (int i = 0; i < 2; i++)
                bR[i] = *(const float4*)(W + (size_t)(k0 + br0 + (i << 4)) * Dv + bc);
        }
#pragma unroll
        for (int ks = 0; ks < 2; ks++) {
            int k16 = ks << 4;
            wmma::fragment<wmma::matrix_a, 16, 16, 16, __nv_bfloat16, wmma::row_major> af[2];
            wmma::fragment<wmma::matrix_b, 16, 16, 16, __nv_bfloat16, wmma::row_major> bf[2];
#pragma unroll
            for (int mi = 0; mi < 2; mi++)
                wmma::load_matrix_sync(af[mi], &As[cur][wm * 32 + mi * 16][k16], 40);
#pragma unroll
            for (int ni = 0; ni < 2; ni++)
                wmma::load_matrix_sync(bf[ni], &Bs[cur][k16][wn * 32 + ni * 16], 72);
#pragma unroll
            for (int mi = 0; mi < 2; mi++)
#pragma unroll
                for (int ni = 0; ni < 2; ni++)
                    wmma::mma_sync(acc[mi][ni], af[mi], bf[ni], acc[mi][ni]);
        }
        if (has) {
            int nxt = cur ^ 1;
#pragma unroll
            for (int i = 0; i < 4; i++)
                *(uint2*)&As[nxt][ar0 + (i << 5)][ac] = f4_to_bf4(aR[i]);
#pragma unroll
            for (int i = 0; i < 2; i++)
                *(uint2*)&Bs[nxt][br0 + (i << 4)][bc] = f4_to_bf4(bR[i]);
        }
        __syncthreads();
        cur ^= 1;
    }

#pragma unroll
    for (int mi = 0; mi < 2; mi++) {
        int n0 = bm + wm * 32 + mi * 16;
        int b = n0 >> 10, t0 = n0 & 1023;
        float* bp = outp + ((size_t)(b * Hv + h) * Tv + t0) * Dv;
#pragma unroll
        for (int ni = 0; ni < 2; ni++)
            wmma::store_matrix_sync(bp + wn * 32 + ni * 16, acc[mi][ni], Dv, wmma::mem_row_major);
    }
}

// ============================================================
// RoPE in place on 64-wide head vectors.
// ============================================================
__global__ void rope_kernel(float* __restrict__ xp, int posDiv)
{
    int idx = blockIdx.x * TB + threadIdx.x;
    int outer = idx >> 5;
    int j = idx & 31;
    int pos = (outer / posDiv) & (Tv - 1);
    float invf = powf(100000.0f, -(float)j * (1.0f / 32.0f));
    float f = (float)pos * invf;
    float s, c; sincosf(f, &s, &c);
    float* p = xp + (size_t)outer * Dv;
    float x1 = p[j], x2 = p[j + 32];
    p[j]      = x1 * c - x2 * s;
    p[j + 32] = x1 * s + x2 * c;
}

// ============================================================
// Flash attention: per (q-tile 64, bh). Online softmax, tf32 wmma.
// q token-major [n][C] (head slice), k/v [bh][t][d]. Out bf16 token-major.
// Dyn smem: Qs,Ks,Vs,Ss,Os (64x68 f32) + m,l,scale rows.
// ============================================================
constexpr int FLASH_SMEM = (5 * 64 * 68 + 3 * 64) * 4;

__global__ void __launch_bounds__(256) flash_kernel(
    const float* __restrict__ q, const float* __restrict__ k,
    const float* __restrict__ v, __nv_bfloat16* __restrict__ obf)
{
    extern __shared__ float fs[];
    float (*Qs)[68] = (float(*)[68])fs;
    float (*Ks)[68] = (float(*)[68])(fs + 64 * 68);
    float (*Vs)[68] = (float(*)[68])(fs + 2 * 64 * 68);
    float (*Ss)[68] = (float(*)[68])(fs + 3 * 64 * 68);
    float (*Os)[68] = (float(*)[68])(fs + 4 * 64 * 68);
    float* mrow = fs + 5 * 64 * 68;
    float* lrow = mrow + 64;
    float* srow = lrow + 64;

    const int qt = blockIdx.x, bh = blockIdx.y;
    const int b = bh >> 4, h = bh & 15;
    const int qs = qt * 64;
    const int tid = threadIdx.x;
    const int warp = tid >> 5;
    const int wm = warp & 3, wn = warp >> 2;
    const int row = tid >> 2, qd = tid & 3;

    // load Q tile; init O, m, l
#pragma unroll
    for (int i = 0; i < 4; i++) {
        int ch = (i << 8) + tid;
        int r = ch >> 4, c = (ch & 15) << 2;
        cp16(&Qs[r][c], q + (size_t)(b * Tv + qs + r) * Cv + h * Dv + c);
    }
    CP_COMMIT();
    for (int i = tid; i < 64 * 68; i += 256) fs[4 * 64 * 68 + i] = 0.f;
    if (tid < 64) { mrow[tid] = -1e30f; lrow[tid] = 0.f; }
    CP_WAIT0();
    __syncthreads();

    for (int kt = 0; kt <= qt; kt++) {
        int ks = kt * 64;
        // load K, V tiles
#pragma unroll
        for (int i = 0; i < 4; i++) {
            int ch = (i << 8) + tid;
            int r = ch >> 4, c = (ch & 15) << 2;
            cp16(&Ks[r][c], k + (size_t)(bh * Tv + ks + r) * Dv + c);
            cp16(&Vs[r][c], v + (size_t)(bh * Tv + ks + r) * Dv + c);
        }
        CP_COMMIT();
        CP_WAIT0();
        __syncthreads();

        // S = Q K^T / 8 -> Ss
        {
            wmma::fragment<wmma::accumulator, 16, 16, 8, float> a0, a1;
            wmma::fill_fragment(a0, 0.f); wmma::fill_fragment(a1, 0.f);
#pragma unroll
            for (int k8 = 0; k8 < 64; k8 += 8) {
                wmma::fragment<wmma::matrix_a, 16, 16, 8, wmma::precision::tf32, wmma::row_major> af;
                wmma::fragment<wmma::matrix_b, 16, 16, 8, wmma::precision::tf32, wmma::col_major> bf0, bf1;
                wmma::load_matrix_sync(af, &Qs[wm * 16][k8], 68);
                wmma::load_matrix_sync(bf0, &Ks[wn * 32][k8], 68);
                wmma::load_matrix_sync(bf1, &Ks[wn * 32 + 16][k8], 68);
                wmma::mma_sync(a0, af, bf0, a0);
                wmma::mma_sync(a1, af, bf1, a1);
            }
#pragma unroll
            for (int t = 0; t < a0.num_elements; t++) { a0.x[t] *= 0.125f; a1.x[t] *= 0.125f; }
            wmma::store_matrix_sync(&Ss[wm * 16][wn * 32], a0, 68, wmma::mem_row_major);
            wmma::store_matrix_sync(&Ss[wm * 16][wn * 32 + 16], a1, 68, wmma::mem_row_major);
        }
        __syncthreads();

        // online softmax row update (4 threads per row, strided cols)
        {
            const bool diag = (kt == qt);
            float sv[16];
            float mloc = -1e30f;
#pragma unroll
            for (int i = 0; i < 16; i++) {
                int j = qd + (i << 2);
                float s = Ss[row][j];
                if (diag && j > row) s = -1e30f;
                sv[i] = s;
                mloc = fmaxf(mloc, s);
            }
            mloc = fmaxf(mloc, __shfl_xor_sync(0xffffffffu, mloc, 1));
            mloc = fmaxf(mloc, __shfl_xor_sync(0xffffffffu, mloc, 2));
            float mold = mrow[row];
            float mnew = fmaxf(mold, mloc);
            float psum = 0.f;
#pragma unroll
            for (int i = 0; i < 16; i++) {
                int j = qd + (i << 2);
                float p = (sv[i] > -1e29f) ? expf(sv[i] - mnew) : 0.f;
                Ss[row][j] = to_tf32(p);
                psum += p;
            }
            psum += __shfl_xor_sync(0xffffffffu, psum, 1);
            psum += __shfl_xor_sync(0xffffffffu, psum, 2);
            if (qd == 0) {
                float scl = expf(mold - mnew);
                mrow[row] = mnew;
                lrow[row] = lrow[row] * scl + psum;
                srow[row] = scl;
            }
        }
        __syncthreads();

        // PV -> Ss (reuse; P fragments preloaded before overwrite)
        {
            wmma::fragment<wmma::matrix_a, 16, 16, 8, wmma::precision::tf32, wmma::row_major> af[8];
#pragma unroll
            for (int kk = 0; kk < 8; kk++)
                wmma::load_matrix_sync(af[kk], &Ss[wm * 16][kk * 8], 68);
            __syncthreads();
            wmma::fragment<wmma::accumulator, 16, 16, 8, float> a0, a1;
            wmma::fill_fragment(a0, 0.f); wmma::fill_fragment(a1, 0.f);
#pragma unroll
            for (int kk = 0; kk < 8; kk++) {
                wmma::fragment<wmma::matrix_b, 16, 16, 8, wmma::precision::tf32, wmma::row_major> bf0, bf1;
                wmma::load_matrix_sync(bf0, &Vs[kk * 8][wn * 32], 68);
                wmma::load_matrix_sync(bf1, &Vs[kk * 8][wn * 32 + 16], 68);
                wmma::mma_sync(a0, af[kk], bf0, a0);
                wmma::mma_sync(a1, af[kk], bf1, a1);
            }
            wmma::store_matrix_sync(&Ss[wm * 16][wn * 32], a0, 68, wmma::mem_row_major);
            wmma::store_matrix_sync(&Ss[wm * 16][wn * 32 + 16], a1, 68, wmma::mem_row_major);
        }
        __syncthreads();

        // O = O*scale + PV
        {
            float scl = srow[row];
#pragma unroll
            for (int i = 0; i < 16; i++) {
                int j = qd + (i << 2);
                Os[row][j] = Os[row][j] * scl + Ss[row][j];
            }
        }
        __syncthreads();
    }

    // epilogue: normalize, write bf16 token-major
    {
        float inv = 1.f / lrow[row];
        __nv_bfloat16* op = obf + (size_t)(b * Tv + qs + row) * Cv + h * Dv;
#pragma unroll
        for (int i = 0; i < 16; i++) {
            int j = qd + (i << 2);
            op[j] = __float2bfloat16(Os[row][j] * inv);
        }
    }
}

// ============================================================
// Router
// ============================================================
__global__ void router_kernel(const float* __restrict__ h2, const float* __restrict__ Wr,
                              const float* __restrict__ rb)
{
    int n = blockIdx.x, tid = threadIdx.x;
    const float* xr = h2 + (size_t)n * Cv;
    float part[Ev];
#pragma unroll
    for (int e = 0; e < Ev; e++) part[e] = 0.f;
    for (int c = tid; c < Cv; c += TB) {
        float xv = xr[c];
#pragma unroll
        for (int e = 0; e < Ev; e++) part[e] += xv * Wr[c * Ev + e];
    }
    __shared__ float sd[Ev][TB];
#pragma unroll
    for (int e = 0; e < Ev; e++) sd[e][tid] = part[e];
    __syncthreads();
    for (int st = TB / 2; st > 0; st >>= 1) {
        if (tid < st)
#pragma unroll
            for (int e = 0; e < Ev; e++) sd[e][tid] += sd[e][tid + st];
        __syncthreads();
    }
    if (tid == 0) {
        int best = 0; float bp = -1.f;
#pragma unroll
        for (int e = 0; e < Ev; e++) {
            float lg = fminf(fmaxf(sd[e][0] + rb[e], -50.f), 50.f);
            float pr = 1.f / (1.f + expf(-lg));
            if (pr > bp) { bp = pr; best = e; }
        }
        g_sel[n] = best;
        g_p[n]   = fminf(fmaxf(bp, 1e-8f), 1.f - 1e-8f);
    }
}

__global__ void zero_kernel() {
    int t = threadIdx.x;
    if (t < Ev) { g_cnt[t] = 0; g_cur[t] = 0; }
}
__global__ void hist_kernel() {
    int n = blockIdx.x * TB + threadIdx.x;
    if (n < Nv) atomicAdd(&g_cnt[g_sel[n]], 1);
}
__global__ void offsets_kernel() {
    int s = 0;
    for (int e = 0; e < Ev; e++) { g_off[e] = s; s += g_cnt[e]; }
}
__global__ void scatter_kernel() {
    int n = blockIdx.x * TB + threadIdx.x;
    if (n < Nv) {
        int e = g_sel[n];
        int pos = atomicAdd(&g_cur[e], 1);
        g_perm[g_off[e] + pos] = n;
    }
}

// silu(a)*b -> bf16 out (vectorized by 4; n multiple of 4)
__global__ void silumul_kernel(const float* __restrict__ a, const float* __restrict__ b,
                               __nv_bfloat16* __restrict__ o)
{
    int i = (blockIdx.x * TB + threadIdx.x) << 2;
    float4 va = *(const float4*)(a + i);
    float4 vb = *(const float4*)(b + i);
    float4 r;
    r.x = (va.x / (1.f + expf(-va.x))) * vb.x;
    r.y = (va.y / (1.f + expf(-va.y))) * vb.y;
    r.z = (va.z / (1.f + expf(-va.z))) * vb.z;
    r.w = (va.w / (1.f + expf(-va.w))) * vb.w;
    *(uint2*)(o + i) = f4_to_bf4(r);
}

__global__ void combine_kernel(const float* __restrict__ x1, const float* __restrict__ sh,
                               const float* __restrict__ yc, float* __restrict__ out)
{
    int s = blockIdx.x;
    int n = g_perm[s];
    float p = g_p[n];
    float tw = fminf(fmaxf(0.5f + p + 1e-8f, 0.5f), 2.0f);
    float wsh = 0.5f / tw, wex = p / tw;
    const float* a = x1 + (size_t)n * Cv;
    const float* b = sh + (size_t)n * Cv;
    const float* c = yc + (size_t)s * Cv;
    float* o = out + (size_t)n * Cv;
    for (int i = threadIdx.x; i < Cv; i += TB)
        o[i] = a[i] + wsh * b[i] + wex * c[i];
}

// ============================================================
// launcher
// ============================================================
extern "C" void kernel_launch(void* const* d_in, const int* in_sizes, int n_in,
                              void* d_out, int out_size)
{
    const float* x    = (const float*)d_in[0];
    const float* ln1  = (const float*)d_in[1];
    const float* ln2  = (const float*)d_in[2];
    const float* Wq   = (const float*)d_in[3];
    const float* Wkv  = (const float*)d_in[4];
    const float* Wk_up= (const float*)d_in[5];
    const float* Wv_up= (const float*)d_in[6];
    const float* Wo   = (const float*)d_in[7];
    const float* Wr   = (const float*)d_in[8];
    const float* rb   = (const float*)d_in[9];
    const float* sw1  = (const float*)d_in[10];
    const float* sw2  = (const float*)d_in[11];
    const float* sw3  = (const float*)d_in[12];
    const float* ew1  = (const float*)d_in[13];
    const float* ew2  = (const float*)d_in[14];
    const float* ew3  = (const float*)d_in[15];
    float* out = (float*)d_out;

    float *pkv, *pq, *pk, *pv, *px1, *ph2, *psh, *pc1, *pc3, *pa1, *pa3, *pyc;
    __nv_bfloat16 *phbf, *ph2bf, *patbf, *pubf, *pucbf;
    __nv_bfloat16 *wq, *wkv, *wo, *s1, *s3, *s2, *e1, *e3, *e2;
    cudaGetSymbolAddress((void**)&pkv, g_kv);
    cudaGetSymbolAddress((void**)&pq,  g_q);
    cudaGetSymbolAddress((void**)&pk,  g_k);
    cudaGetSymbolAddress((void**)&pv,  g_v);
    cudaGetSymbolAddress((void**)&px1, g_x1);
    cudaGetSymbolAddress((void**)&ph2, g_h2);
    cudaGetSymbolAddress((void**)&psh, g_sh);
    cudaGetSymbolAddress((void**)&pc1, g_c1);
    cudaGetSymbolAddress((void**)&pc3, g_c3);
    cudaGetSymbolAddress((void**)&pa1, g_a1);
    cudaGetSymbolAddress((void**)&pa3, g_a3);
    cudaGetSymbolAddress((void**)&pyc, g_yc);
    cudaGetSymbolAddress((void**)&phbf,  g_hbf);
    cudaGetSymbolAddress((void**)&ph2bf, g_h2bf);
    cudaGetSymbolAddress((void**)&patbf, g_atbf);
    cudaGetSymbolAddress((void**)&pubf,  g_ubf);
    cudaGetSymbolAddress((void**)&pucbf, g_ucbf);
    cudaGetSymbolAddress((void**)&wq,  g_Wq_bf);
    cudaGetSymbolAddress((void**)&wkv, g_Wkv_bf);
    cudaGetSymbolAddress((void**)&wo,  g_Wo_bf);
    cudaGetSymbolAddress((void**)&s1,  g_sw1_bf);
    cudaGetSymbolAddress((void**)&s3,  g_sw3_bf);
    cudaGetSymbolAddress((void**)&s2,  g_sw2_bf);
    cudaGetSymbolAddress((void**)&e1,  g_ew1_bf);
    cudaGetSymbolAddress((void**)&e3,  g_ew3_bf);
    cudaGetSymbolAddress((void**)&e2,  g_ew2_bf);

    static bool attr_done = false;
    if (!attr_done) {
        cudaFuncSetAttribute(flash_kernel, cudaFuncAttributeMaxDynamicSharedMemorySize, FLASH_SMEM);
        attr_done = true;
    }

    auto cvt = [](const float* in, __nv_bfloat16* outp, int n) {
        f2bf_kernel<<<n / (TB * 4), TB>>>(in, outp, n);
    };

    // ---- weight conversion (bf16) ----
    cvt(Wq,  wq,  Cv * Cv);
    cvt(Wkv, wkv, Cv * Lv);
    cvt(Wo,  wo,  Cv * Cv);
    cvt(sw1, s1,  Cv * Iv);
    cvt(sw3, s3,  Cv * Iv);
    cvt(sw2, s2,  Iv * Cv);
    cvt(ew1, e1,  Ev * Cv * Iv);
    cvt(ew3, e3,  Ev * Cv * Iv);
    cvt(ew2, e2,  Ev * Iv * Cv);

    // ---- attention ----
    rmsnorm_kernel<<<Nv, TB>>>(x, ln1, nullptr, phbf);
    tgemm_bf<<<dim3(Cv / 128, Nv / 128), TB>>>(phbf, wq,  pq,  nullptr, Cv, Cv, 1.f);
    tgemm_bf<<<dim3(Lv / 128, Nv / 128), TB>>>(phbf, wkv, pkv, nullptr, Cv, Lv, 0.25f);
    kvup_wmma<<<dim3(Nv / 128, Hv * 2), TB>>>(pkv, Wk_up, Wv_up, pk, pv);
    rope_kernel<<<(Nv * Hv * 32) / TB, TB>>>(pq, Hv);
    rope_kernel<<<(Nv * Hv * 32) / TB, TB>>>(pk, 1);
    flash_kernel<<<dim3(Tv / 64, BHv), TB, FLASH_SMEM>>>(pq, pk, pv, patbf);
    tgemm_bf<<<dim3(Cv / 128, Nv / 128), TB>>>(patbf, wo, px1, x, Cv, Cv, 1.f);

    // ---- MoE ----
    rmsnorm_kernel<<<Nv, TB>>>(px1, ln2, ph2, ph2bf);
    router_kernel<<<Nv, TB>>>(ph2, Wr, rb);
    zero_kernel<<<1, 32>>>();
    hist_kernel<<<Nv / TB, TB>>>();
    offsets_kernel<<<1, 1>>>();
    scatter_kernel<<<Nv / TB, TB>>>();

    tgemm_bf<<<dim3(Iv / 128, Nv / 128), TB>>>(ph2bf, s1, pa1, nullptr, Cv, Iv, 1.f);
    tgemm_bf<<<dim3(Iv / 128, Nv / 128), TB>>>(ph2bf, s3, pa3, nullptr, Cv, Iv, 1.f);
    silumul_kernel<<<(Nv * Iv) / (TB * 4), TB>>>(pa1, pa3, pubf);
    tgemm_bf<<<dim3(Cv / 128, Nv / 128), TB>>>(pubf, s2, psh, nullptr, Iv, Cv, 1.f);

    gg_tgemm_bf<true ><<<dim3(Nv / 128, Iv / 128, Ev), TB>>>(ph2bf, e1, (size_t)Cv * Iv, Cv, Iv, pc1);
    gg_tgemm_bf<true ><<<dim3(Nv / 128, Iv / 128, Ev), TB>>>(ph2bf, e3, (size_t)Cv * Iv, Cv, Iv, pc3);
    silumul_kernel<<<(Nv * Iv) / (TB * 4), TB>>>(pc1, pc3, pucbf);
    gg_tgemm_bf<false><<<dim3(Nv / 128, Cv / 128, Ev), TB>>>(pucbf, e2, (size_t)Iv * Cv, Iv, Cv, pyc);

    combine_kernel<<<Nv, TB>>>(px1, psh, pyc, out);
}

// round 8
// speedup vs baseline: 4.1576x; 1.0843x over previous
#include <cuda_runtime.h>
#include <cuda_bf16.h>
#include <mma.h>
#include <cstdint>

using namespace nvcuda;

#define TB 256

// ---- problem constants ----
constexpr int Bv = 8, Tv = 1024, Hv = 16, Dv = 64, Cv = 1024, Lv = 256, Ev = 8, Iv = 2048;
constexpr int Nv  = Bv * Tv;   // 8192 tokens
constexpr int BHv = Bv * Hv;   // 128

// ---- scratch (device globals; allocation-free) ----
__device__ float g_kv [Nv * Lv];
__device__ float g_q  [Nv * Cv];
__device__ float g_k  [Nv * Cv];          // [b,h,t,d]
__device__ float g_v  [Nv * Cv];          // [b,h,t,d]
__device__ float g_x1 [Nv * Cv];
__device__ float g_h2 [Nv * Cv];
__device__ float g_sh [Nv * Cv];
__device__ float g_a13[Nv * 2 * Iv];      // fused a1|a3
__device__ float g_c13[Nv * 2 * Iv];      // fused c1|c3 (compact)
__device__ float g_yc [Nv * Cv];
__device__ int   g_sel[Nv];
__device__ float g_p  [Nv];
__device__ int   g_cnt[Ev];
__device__ int   g_off[Ev];
__device__ int   g_cur[Ev];
__device__ int   g_perm[Nv];

// bf16 activation buffers
__device__ __nv_bfloat16 g_hbf  [Nv * Cv];
__device__ __nv_bfloat16 g_h2bf [Nv * Cv];
__device__ __nv_bfloat16 g_atbf [Nv * Cv];
__device__ __nv_bfloat16 g_ubf  [Nv * Iv];
__device__ __nv_bfloat16 g_ucbf [Nv * Iv];

// bf16 weight buffers (converted per launch); row-major [K, N]
__device__ __nv_bfloat16 g_Wq_bf [Cv * Cv];
__device__ __nv_bfloat16 g_Wkv_bf[Cv * Lv];
__device__ __nv_bfloat16 g_Wo_bf [Cv * Cv];
__device__ __nv_bfloat16 g_s13_bf[Cv * 2 * Iv];        // sw1|sw3 concat on N
__device__ __nv_bfloat16 g_sw2_bf[Iv * Cv];
__device__ __nv_bfloat16 g_e13_bf[Ev * Cv * 2 * Iv];   // ew1|ew3 concat on N
__device__ __nv_bfloat16 g_ew2_bf[Ev * Iv * Cv];

__device__ __forceinline__ uint2 f4_to_bf4(float4 v) {
    __nv_bfloat162 lo = __floats2bfloat162_rn(v.x, v.y);
    __nv_bfloat162 hi = __floats2bfloat162_rn(v.z, v.w);
    uint2 r;
    r.x = *reinterpret_cast<unsigned int*>(&lo);
    r.y = *reinterpret_cast<unsigned int*>(&hi);
    return r;
}
__device__ __forceinline__ float to_tf32(float x) {
    float r; asm("cvt.rna.tf32.f32 %0, %1;" : "=f"(r) : "f"(x)); return r;
}
__device__ __forceinline__ void cp16(void* sdst, const void* gsrc) {
    uint32_t s = (uint32_t)__cvta_generic_to_shared(sdst);
    asm volatile("cp.async.ca.shared.global [%0], [%1], 16;" :: "r"(s), "l"(gsrc));
}
__device__ __forceinline__ void cp16z(void* sdst, const void* gsrc, bool p) {
    uint32_t s = (uint32_t)__cvta_generic_to_shared(sdst);
    asm volatile("cp.async.ca.shared.global [%0], [%1], 16, %2;" :: "r"(s), "l"(gsrc), "r"(p ? 16 : 0));
}
#define CP_COMMIT() asm volatile("cp.async.commit_group;")
#define CP_WAIT1()  asm volatile("cp.async.wait_group 1;")
#define CP_WAIT0()  asm volatile("cp.async.wait_group 0;")

// GEMM dynamic smem: As[3][128][40] + Bs[3][32][264] bf16
constexpr int TG_AS_BYTES = 3 * 128 * 40 * 2;   // 30720
constexpr int TG_SMEM = TG_AS_BYTES + 3 * 32 * 264 * 2;  // 81408

// ============================================================
// fp32 -> bf16 convert (n multiple of 4)
// ============================================================
__global__ void f2bf_kernel(const float* __restrict__ in, __nv_bfloat16* __restrict__ out, int n)
{
    int i = (blockIdx.x * TB + threadIdx.x) << 2;
    if (i < n) {
        float4 v = *(const float4*)(in + i);
        *(uint2*)(out + i) = f4_to_bf4(v);
    }
}

// ============================================================
// Paired convert: in1/in2 [Cv][Iv] fp32 -> out [Cv][2*Iv] bf16 (cols 0..Iv-1 = in1).
// Grid x covers Cv*Iv/4 per z; z = expert (batch) index.
// ============================================================
__global__ void f2bf_pair(const float* __restrict__ in1, const float* __restrict__ in2,
                          __nv_bfloat16* __restrict__ out)
{
    size_t zi = (size_t)blockIdx.z * Cv * Iv;
    size_t zo = (size_t)blockIdx.z * Cv * 2 * Iv;
    int i = (blockIdx.x * TB + threadIdx.x) << 2;   // exact grid: Cv*Iv/4 threads
    int r = i >> 11;            // / Iv (2048)
    int c = i & (Iv - 1);
    float4 v1 = *(const float4*)(in1 + zi + i);
    float4 v2 = *(const float4*)(in2 + zi + i);
    size_t ob = zo + (size_t)r * (2 * Iv) + c;
    *(uint2*)(out + ob)      = f4_to_bf4(v1);
    *(uint2*)(out + ob + Iv) = f4_to_bf4(v2);
}

// ============================================================
// RMSNorm: one block per token; dual fp32 (optional) + bf16 output
// ============================================================
__global__ void rmsnorm_kernel(const float* __restrict__ x, const float* __restrict__ w,
                               float* __restrict__ y, __nv_bfloat16* __restrict__ yb)
{
    int n = blockIdx.x, tid = threadIdx.x;
    const float* xr = x + (size_t)n * Cv;
    __shared__ float red[TB];
    float ss = 0.f;
    for (int c = tid; c < Cv; c += TB) { float v = xr[c]; ss += v * v; }
    red[tid] = ss; __syncthreads();
    for (int s = TB / 2; s > 0; s >>= 1) { if (tid < s) red[tid] += red[tid + s]; __syncthreads(); }
    float rs = rsqrtf(red[0] / (float)Cv + 1e-6f);
    __nv_bfloat16* ybr = yb + (size_t)n * Cv;
    float* yr = y ? y + (size_t)n * Cv : nullptr;
    for (int c = tid; c < Cv; c += TB) {
        float v = xr[c] * rs * w[c];
        ybr[c] = __float2bfloat16(v);
        if (yr) yr[c] = v;
    }
}

// ============================================================
// BF16 cp.async 3-stage GEMM, 128x256 block tile, 64x64 warp tile.
// C = alpha*A[M,K]@B[K,N] (+Res). M mult 128, N mult 256, K mult 96.
// ============================================================
__global__ void __launch_bounds__(256) tgemm_bf(
    const __nv_bfloat16* __restrict__ A, const __nv_bfloat16* __restrict__ B,
    float* __restrict__ Cmat, const float* __restrict__ Res,
    int K, int N, float alpha)
{
    extern __shared__ char sm[];
    auto As = (__nv_bfloat16 (*)[128][40])sm;
    auto Bs = (__nv_bfloat16 (*)[32][264])(sm + TG_AS_BYTES);
    const int tid  = threadIdx.x;
    const int warp = tid >> 5;
    const int wm   = warp & 1, wn = warp >> 1;
    const int bm   = blockIdx.y * 128, bn = blockIdx.x * 256;

    wmma::fragment<wmma::accumulator, 16, 16, 16, float> acc[4][4];
#pragma unroll
    for (int mi = 0; mi < 4; mi++)
#pragma unroll
        for (int ni = 0; ni < 4; ni++) wmma::fill_fragment(acc[mi][ni], 0.f);

    const int nch = K >> 5;

    auto issue = [&](int stage, int k0) {
#pragma unroll
        for (int i = 0; i < 2; i++) {
            int ch = (i << 8) + tid;
            int ar = ch >> 2, ac = (ch & 3) << 3;
            cp16(&As[stage][ar][ac], A + (size_t)(bm + ar) * K + k0 + ac);
        }
#pragma unroll
        for (int i = 0; i < 4; i++) {
            int ch = (i << 8) + tid;
            int br = ch >> 5, bc = (ch & 31) << 3;
            cp16(&Bs[stage][br][bc], B + (size_t)(k0 + br) * N + bn + bc);
        }
    };

    issue(0, 0);  CP_COMMIT();
    issue(1, 32); CP_COMMIT();

    for (int ch = 0; ch < nch; ch++) {
        CP_WAIT1();
        __syncthreads();
        if (ch + 2 < nch) issue((ch + 2) % 3, (ch + 2) << 5);
        CP_COMMIT();
        int buf = ch % 3;
#pragma unroll
        for (int ks = 0; ks < 2; ks++) {
            int k16 = ks << 4;
            wmma::fragment<wmma::matrix_a, 16, 16, 16, __nv_bfloat16, wmma::row_major> af[4];
            wmma::fragment<wmma::matrix_b, 16, 16, 16, __nv_bfloat16, wmma::row_major> bf[4];
#pragma unroll
            for (int mi = 0; mi < 4; mi++)
                wmma::load_matrix_sync(af[mi], &As[buf][wm * 64 + mi * 16][k16], 40);
#pragma unroll
            for (int ni = 0; ni < 4; ni++)
                wmma::load_matrix_sync(bf[ni], &Bs[buf][k16][wn * 64 + ni * 16], 264);
#pragma unroll
            for (int mi = 0; mi < 4; mi++)
#pragma unroll
                for (int ni = 0; ni < 4; ni++)
                    wmma::mma_sync(acc[mi][ni], af[mi], bf[ni], acc[mi][ni]);
        }
    }

#pragma unroll
    for (int mi = 0; mi < 4; mi++)
#pragma unroll
        for (int ni = 0; ni < 4; ni++) {
            size_t row = (size_t)(bm + wm * 64 + mi * 16);
            size_t col = (size_t)(bn + wn * 64 + ni * 16);
            float* cp = Cmat + row * N + col;
            if (Res) {
                wmma::fragment<wmma::accumulator, 16, 16, 16, float> rf;
                wmma::load_matrix_sync(rf, Res + row * N + col, N, wmma::mem_row_major);
#pragma unroll
                for (int t = 0; t < rf.num_elements; t++)
                    acc[mi][ni].x[t] = acc[mi][ni].x[t] * alpha + rf.x[t];
            } else if (alpha != 1.f) {
#pragma unroll
                for (int t = 0; t < acc[mi][ni].num_elements; t++)
                    acc[mi][ni].x[t] *= alpha;
            }
            wmma::store_matrix_sync(cp, acc[mi][ni], N, wmma::mem_row_major);
        }
}

// ============================================================
// Grouped (per-expert) BF16 GEMM, 128x256 tile, optional gather.
// ============================================================
template <bool GATHER>
__global__ void __launch_bounds__(256) gg_tgemm_bf(
    const __nv_bfloat16* __restrict__ A, const __nv_bfloat16* __restrict__ Bbase,
    size_t strideB, int K, int N, float* __restrict__ Out)
{
    int e = blockIdx.z;
    int cnt = g_cnt[e];
    int base = blockIdx.x * 128;
    if (base >= cnt) return;
    int o = g_off[e];
    const __nv_bfloat16* B = Bbase + (size_t)e * strideB;

    extern __shared__ char sm[];
    auto As = (__nv_bfloat16 (*)[128][40])sm;
    auto Bs = (__nv_bfloat16 (*)[32][264])(sm + TG_AS_BYTES);
    const int tid  = threadIdx.x;
    const int warp = tid >> 5;
    const int lane = tid & 31;
    const int wm   = warp & 1, wn = warp >> 1;
    const int bn   = blockIdx.y * 256;

    wmma::fragment<wmma::accumulator, 16, 16, 16, float> acc[4][4];
#pragma unroll
    for (int mi = 0; mi < 4; mi++)
#pragma unroll
        for (int ni = 0; ni < 4; ni++) wmma::fill_fragment(acc[mi][ni], 0.f);

    int grow[2]; bool gv[2]; int arr[2]; int arc[2];
#pragma unroll
    for (int i = 0; i < 2; i++) {
        int ch = (i << 8) + tid;
        arr[i] = ch >> 2; arc[i] = (ch & 3) << 3;
        int lr = base + arr[i];
        gv[i] = lr < cnt;
        grow[i] = gv[i] ? (GATHER ? g_perm[o + lr] : (o + lr)) : 0;
    }

    const int nch = K >> 5;

    auto issue = [&](int stg, int k0) {
#pragma unroll
        for (int i = 0; i < 2; i++)
            cp16z(&As[stg][arr[i]][arc[i]], A + (size_t)grow[i] * K + k0 + arc[i], gv[i]);
#pragma unroll
        for (int i = 0; i < 4; i++) {
            int ch = (i << 8) + tid;
            int br = ch >> 5, bc = (ch & 31) << 3;
            cp16(&Bs[stg][br][bc], B + (size_t)(k0 + br) * N + bn + bc);
        }
    };

    issue(0, 0);  CP_COMMIT();
    issue(1, 32); CP_COMMIT();

    for (int ch = 0; ch < nch; ch++) {
        CP_WAIT1();
        __syncthreads();
        if (ch + 2 < nch) issue((ch + 2) % 3, (ch + 2) << 5);
        CP_COMMIT();
        int buf = ch % 3;
#pragma unroll
        for (int ks = 0; ks < 2; ks++) {
            int k16 = ks << 4;
            wmma::fragment<wmma::matrix_a, 16, 16, 16, __nv_bfloat16, wmma::row_major> af[4];
            wmma::fragment<wmma::matrix_b, 16, 16, 16, __nv_bfloat16, wmma::row_major> bf[4];
#pragma unroll
            for (int mi = 0; mi < 4; mi++)
                wmma::load_matrix_sync(af[mi], &As[buf][wm * 64 + mi * 16][k16], 40);
#pragma unroll
            for (int ni = 0; ni < 4; ni++)
                wmma::load_matrix_sync(bf[ni], &Bs[buf][k16][wn * 64 + ni * 16], 264);
#pragma unroll
            for (int mi = 0; mi < 4; mi++)
#pragma unroll
                for (int ni = 0; ni < 4; ni++)
                    wmma::mma_sync(acc[mi][ni], af[mi], bf[ni], acc[mi][ni]);
        }
    }

    __syncthreads();   // done with As/Bs; reuse smem as epilogue stage
    float* stg = (float*)sm + warp * 320;   // 16 rows x ldm 20
    const int sr = lane >> 1, sc0 = (lane & 1) << 3;
#pragma unroll
    for (int mi = 0; mi < 4; mi++)
#pragma unroll
        for (int ni = 0; ni < 4; ni++) {
            wmma::store_matrix_sync(stg, acc[mi][ni], 20, wmma::mem_row_major);
            __syncwarp();
            int lr = base + wm * 64 + mi * 16 + sr;
            if (lr < cnt) {
                size_t row = (size_t)(o + lr);
                int col = bn + wn * 64 + ni * 16 + sc0;
                float4 v0 = *(float4*)(stg + sr * 20 + sc0);
                float4 v1 = *(float4*)(stg + sr * 20 + sc0 + 4);
                *(float4*)(Out + row * N + col)     = v0;
                *(float4*)(Out + row * N + col + 4) = v1;
            }
            __syncwarp();
        }
}

// ============================================================
// K/V up-projection, bf16 wmma. grid (Nv/128, Hv*2). (fp32 inputs)
// ============================================================
__global__ void kvup_wmma(const float* __restrict__ kv,
                          const float* __restrict__ Wk_up, const float* __restrict__ Wv_up,
                          float* __restrict__ kout, float* __restrict__ vout)
{
    int y = blockIdx.y;
    int h = y >> 1, which = y & 1;
    const float* W = (which ? Wv_up : Wk_up) + (size_t)h * Lv * Dv;
    float* outp = which ? vout : kout;
    int bm = blockIdx.x * 128;

    __shared__ __nv_bfloat16 As[2][128][40];
    __shared__ __nv_bfloat16 Bs[2][32][72];
    const int tid  = threadIdx.x;
    const int warp = tid >> 5;
    const int wm   = warp & 3, wn = warp >> 2;

    wmma::fragment<wmma::accumulator, 16, 16, 16, float> acc[2][2];
#pragma unroll
    for (int mi = 0; mi < 2; mi++)
#pragma unroll
        for (int ni = 0; ni < 2; ni++) wmma::fill_fragment(acc[mi][ni], 0.f);

    const int ar0 = tid >> 3, ac = (tid & 7) << 2;
    const int br0 = tid >> 4, bc = (tid & 15) << 2;

    float4 aR[4], bR[2];
    const int nch = Lv >> 5;

#pragma unroll
    for (int i = 0; i < 4; i++)
        aR[i] = *(const float4*)(kv + (size_t)(bm + ar0 + (i << 5)) * Lv + ac);
#pragma unroll
    for (int i = 0; i < 2; i++)
        bR[i] = *(const float4*)(W + (size_t)(br0 + (i << 4)) * Dv + bc);
#pragma unroll
    for (int i = 0; i < 4; i++)
        *(uint2*)&As[0][ar0 + (i << 5)][ac] = f4_to_bf4(aR[i]);
#pragma unroll
    for (int i = 0; i < 2; i++)
        *(uint2*)&Bs[0][br0 + (i << 4)][bc] = f4_to_bf4(bR[i]);
    __syncthreads();

    int cur = 0;
    for (int ch = 0; ch < nch; ch++) {
        bool has = (ch + 1) < nch;
        if (has) {
            int k0 = (ch + 1) << 5;
#pragma unroll
            for (int i = 0; i < 4; i++)
                aR[i] = *(const float4*)(kv + (size_t)(bm + ar0 + (i << 5)) * Lv + k0 + ac);
#pragma unroll
            for (int i = 0; i < 2; i++)
                bR[i] = *(const float4*)(W + (size_t)(k0 + br0 + (i << 4)) * Dv + bc);
        }
#pragma unroll
        for (int ks = 0; ks < 2; ks++) {
            int k16 = ks << 4;
            wmma::fragment<wmma::matrix_a, 16, 16, 16, __nv_bfloat16, wmma::row_major> af[2];
            wmma::fragment<wmma::matrix_b, 16, 16, 16, __nv_bfloat16, wmma::row_major> bf[2];
#pragma unroll
            for (int mi = 0; mi < 2; mi++)
                wmma::load_matrix_sync(af[mi], &As[cur][wm * 32 + mi * 16][k16], 40);
#pragma unroll
            for (int ni = 0; ni < 2; ni++)
                wmma::load_matrix_sync(bf[ni], &Bs[cur][k16][wn * 32 + ni * 16], 72);
#pragma unroll
            for (int mi = 0; mi < 2; mi++)
#pragma unroll
                for (int ni = 0; ni < 2; ni++)
                    wmma::mma_sync(acc[mi][ni], af[mi], bf[ni], acc[mi][ni]);
        }
        if (has) {
            int nxt = cur ^ 1;
#pragma unroll
            for (int i = 0; i < 4; i++)
                *(uint2*)&As[nxt][ar0 + (i << 5)][ac] = f4_to_bf4(aR[i]);
#pragma unroll
            for (int i = 0; i < 2; i++)
                *(uint2*)&Bs[nxt][br0 + (i << 4)][bc] = f4_to_bf4(bR[i]);
        }
        __syncthreads();
        cur ^= 1;
    }

#pragma unroll
    for (int mi = 0; mi < 2; mi++) {
        int n0 = bm + wm * 32 + mi * 16;
        int b = n0 >> 10, t0 = n0 & 1023;
        float* bp = outp + ((size_t)(b * Hv + h) * Tv + t0) * Dv;
#pragma unroll
        for (int ni = 0; ni < 2; ni++)
            wmma::store_matrix_sync(bp + wn * 32 + ni * 16, acc[mi][ni], Dv, wmma::mem_row_major);
    }
}

// ============================================================
// RoPE in place on 64-wide head vectors.
// ============================================================
__global__ void rope_kernel(float* __restrict__ xp, int posDiv)
{
    int idx = blockIdx.x * TB + threadIdx.x;
    int outer = idx >> 5;
    int j = idx & 31;
    int pos = (outer / posDiv) & (Tv - 1);
    float invf = powf(100000.0f, -(float)j * (1.0f / 32.0f));
    float f = (float)pos * invf;
    float s, c; sincosf(f, &s, &c);
    float* p = xp + (size_t)outer * Dv;
    float x1 = p[j], x2 = p[j + 32];
    p[j]      = x1 * c - x2 * s;
    p[j + 32] = x1 * s + x2 * c;
}

// ============================================================
// Flash attention (tf32 wmma, online softmax). Out bf16 token-major.
// ============================================================
constexpr int FLASH_SMEM = (5 * 64 * 68 + 3 * 64) * 4;

__global__ void __launch_bounds__(256) flash_kernel(
    const float* __restrict__ q, const float* __restrict__ k,
    const float* __restrict__ v, __nv_bfloat16* __restrict__ obf)
{
    extern __shared__ float fs[];
    float (*Qs)[68] = (float(*)[68])fs;
    float (*Ks)[68] = (float(*)[68])(fs + 64 * 68);
    float (*Vs)[68] = (float(*)[68])(fs + 2 * 64 * 68);
    float (*Ss)[68] = (float(*)[68])(fs + 3 * 64 * 68);
    float (*Os)[68] = (float(*)[68])(fs + 4 * 64 * 68);
    float* mrow = fs + 5 * 64 * 68;
    float* lrow = mrow + 64;
    float* srow = lrow + 64;

    const int qt = blockIdx.x, bh = blockIdx.y;
    const int b = bh >> 4, h = bh & 15;
    const int qs = qt * 64;
    const int tid = threadIdx.x;
    const int warp = tid >> 5;
    const int wm = warp & 3, wn = warp >> 2;
    const int row = tid >> 2, qd = tid & 3;

#pragma unroll
    for (int i = 0; i < 4; i++) {
        int ch = (i << 8) + tid;
        int r = ch >> 4, c = (ch & 15) << 2;
        cp16(&Qs[r][c], q + (size_t)(b * Tv + qs + r) * Cv + h * Dv + c);
    }
    CP_COMMIT();
    for (int i = tid; i < 64 * 68; i += 256) fs[4 * 64 * 68 + i] = 0.f;
    if (tid < 64) { mrow[tid] = -1e30f; lrow[tid] = 0.f; }
    CP_WAIT0();
    __syncthreads();

    for (int kt = 0; kt <= qt; kt++) {
        int ks = kt * 64;
#pragma unroll
        for (int i = 0; i < 4; i++) {
            int ch = (i << 8) + tid;
            int r = ch >> 4, c = (ch & 15) << 2;
            cp16(&Ks[r][c], k + (size_t)(bh * Tv + ks + r) * Dv + c);
            cp16(&Vs[r][c], v + (size_t)(bh * Tv + ks + r) * Dv + c);
        }
        CP_COMMIT();
        CP_WAIT0();
        __syncthreads();

        {
            wmma::fragment<wmma::accumulator, 16, 16, 8, float> a0, a1;
            wmma::fill_fragment(a0, 0.f); wmma::fill_fragment(a1, 0.f);
#pragma unroll
            for (int k8 = 0; k8 < 64; k8 += 8) {
                wmma::fragment<wmma::matrix_a, 16, 16, 8, wmma::precision::tf32, wmma::row_major> af;
                wmma::fragment<wmma::matrix_b, 16, 16, 8, wmma::precision::tf32, wmma::col_major> bf0, bf1;
                wmma::load_matrix_sync(af, &Qs[wm * 16][k8], 68);
                wmma::load_matrix_sync(bf0, &Ks[wn * 32][k8], 68);
                wmma::load_matrix_sync(bf1, &Ks[wn * 32 + 16][k8], 68);
                wmma::mma_sync(a0, af, bf0, a0);
                wmma::mma_sync(a1, af, bf1, a1);
            }
#pragma unroll
            for (int t = 0; t < a0.num_elements; t++) { a0.x[t] *= 0.125f; a1.x[t] *= 0.125f; }
            wmma::store_matrix_sync(&Ss[wm * 16][wn * 32], a0, 68, wmma::mem_row_major);
            wmma::store_matrix_sync(&Ss[wm * 16][wn * 32 + 16], a1, 68, wmma::mem_row_major);
        }
        __syncthreads();

        {
            const bool diag = (kt == qt);
            float sv[16];
            float mloc = -1e30f;
#pragma unroll
            for (int i = 0; i < 16; i++) {
                int j = qd + (i << 2);
                float s = Ss[row][j];
                if (diag && j > row) s = -1e30f;
                sv[i] = s;
                mloc = fmaxf(mloc, s);
            }
            mloc = fmaxf(mloc, __shfl_xor_sync(0xffffffffu, mloc, 1));
            mloc = fmaxf(mloc, __shfl_xor_sync(0xffffffffu, mloc, 2));
            float mold = mrow[row];
            float mnew = fmaxf(mold, mloc);
            float psum = 0.f;
#pragma unroll
            for (int i = 0; i < 16; i++) {
                int j = qd + (i << 2);
                float p = (sv[i] > -1e29f) ? expf(sv[i] - mnew) : 0.f;
                Ss[row][j] = to_tf32(p);
                psum += p;
            }
            psum += __shfl_xor_sync(0xffffffffu, psum, 1);
            psum += __shfl_xor_sync(0xffffffffu, psum, 2);
            if (qd == 0) {
                float scl = expf(mold - mnew);
                mrow[row] = mnew;
                lrow[row] = lrow[row] * scl + psum;
                srow[row] = scl;
            }
        }
        __syncthreads();

        {
            wmma::fragment<wmma::matrix_a, 16, 16, 8, wmma::precision::tf32, wmma::row_major> af[8];
#pragma unroll
            for (int kk = 0; kk < 8; kk++)
                wmma::load_matrix_sync(af[kk], &Ss[wm * 16][kk * 8], 68);
            __syncthreads();
            wmma::fragment<wmma::accumulator, 16, 16, 8, float> a0, a1;
            wmma::fill_fragment(a0, 0.f); wmma::fill_fragment(a1, 0.f);
#pragma unroll
            for (int kk = 0; kk < 8; kk++) {
                wmma::fragment<wmma::matrix_b, 16, 16, 8, wmma::precision::tf32, wmma::row_major> bf0, bf1;
                wmma::load_matrix_sync(bf0, &Vs[kk * 8][wn * 32], 68);
                wmma::load_matrix_sync(bf1, &Vs[kk * 8][wn * 32 + 16], 68);
                wmma::mma_sync(a0, af[kk], bf0, a0);
                wmma::mma_sync(a1, af[kk], bf1, a1);
            }
            wmma::store_matrix_sync(&Ss[wm * 16][wn * 32], a0, 68, wmma::mem_row_major);
            wmma::store_matrix_sync(&Ss[wm * 16][wn * 32 + 16], a1, 68, wmma::mem_row_major);
        }
        __syncthreads();

        {
            float scl = srow[row];
#pragma unroll
            for (int i = 0; i < 16; i++) {
                int j = qd + (i << 2);
                Os[row][j] = Os[row][j] * scl + Ss[row][j];
            }
        }
        __syncthreads();
    }

    {
        float inv = 1.f / lrow[row];
        __nv_bfloat16* op = obf + (size_t)(b * Tv + qs + row) * Cv + h * Dv;
#pragma unroll
        for (int i = 0; i < 16; i++) {
            int j = qd + (i << 2);
            op[j] = __float2bfloat16(Os[row][j] * inv);
        }
    }
}

// ============================================================
// Router
// ============================================================
__global__ void router_kernel(const float* __restrict__ h2, const float* __restrict__ Wr,
                              const float* __restrict__ rb)
{
    int n = blockIdx.x, tid = threadIdx.x;
    const float* xr = h2 + (size_t)n * Cv;
    float part[Ev];
#pragma unroll
    for (int e = 0; e < Ev; e++) part[e] = 0.f;
    for (int c = tid; c < Cv; c += TB) {
        float xv = xr[c];
#pragma unroll
        for (int e = 0; e < Ev; e++) part[e] += xv * Wr[c * Ev + e];
    }
    __shared__ float sd[Ev][TB];
#pragma unroll
    for (int e = 0; e < Ev; e++) sd[e][tid] = part[e];
    __syncthreads();
    for (int st = TB / 2; st > 0; st >>= 1) {
        if (tid < st)
#pragma unroll
            for (int e = 0; e < Ev; e++) sd[e][tid] += sd[e][tid + st];
        __syncthreads();
    }
    if (tid == 0) {
        int best = 0; float bp = -1.f;
#pragma unroll
        for (int e = 0; e < Ev; e++) {
            float lg = fminf(fmaxf(sd[e][0] + rb[e], -50.f), 50.f);
            float pr = 1.f / (1.f + expf(-lg));
            if (pr > bp) { bp = pr; best = e; }
        }
        g_sel[n] = best;
        g_p[n]   = fminf(fmaxf(bp, 1e-8f), 1.f - 1e-8f);
    }
}

__global__ void zero_kernel() {
    int t = threadIdx.x;
    if (t < Ev) { g_cnt[t] = 0; g_cur[t] = 0; }
}
__global__ void hist_kernel() {
    int n = blockIdx.x * TB + threadIdx.x;
    if (n < Nv) atomicAdd(&g_cnt[g_sel[n]], 1);
}
__global__ void offsets_kernel() {
    int s = 0;
    for (int e = 0; e < Ev; e++) { g_off[e] = s; s += g_cnt[e]; }
}
__global__ void scatter_kernel() {
    int n = blockIdx.x * TB + threadIdx.x;
    if (n < Nv) {
        int e = g_sel[n];
        int pos = atomicAdd(&g_cur[e], 1);
        g_perm[g_off[e] + pos] = n;
    }
}

// silu on fused a|b rows: in [rows][2*Iv] fp32, out [rows][Iv] bf16.
// i indexes output (rows*Iv), vectorized by 4.
__global__ void silumul2_kernel(const float* __restrict__ ab, __nv_bfloat16* __restrict__ o)
{
    int i = (blockIdx.x * TB + threadIdx.x) << 2;
    int r = i >> 11;            // / Iv
    int c = i & (Iv - 1);
    const float* rowp = ab + (size_t)r * (2 * Iv);
    float4 va = *(const float4*)(rowp + c);
    float4 vb = *(const float4*)(rowp + Iv + c);
    float4 rr;
    rr.x = (va.x / (1.f + expf(-va.x))) * vb.x;
    rr.y = (va.y / (1.f + expf(-va.y))) * vb.y;
    rr.z = (va.z / (1.f + expf(-va.z))) * vb.z;
    rr.w = (va.w / (1.f + expf(-va.w))) * vb.w;
    *(uint2*)(o + i) = f4_to_bf4(rr);
}

__global__ void combine_kernel(const float* __restrict__ x1, const float* __restrict__ sh,
                               const float* __restrict__ yc, float* __restrict__ out)
{
    int s = blockIdx.x;
    int n = g_perm[s];
    float p = g_p[n];
    float tw = fminf(fmaxf(0.5f + p + 1e-8f, 0.5f), 2.0f);
    float wsh = 0.5f / tw, wex = p / tw;
    const float* a = x1 + (size_t)n * Cv;
    const float* b = sh + (size_t)n * Cv;
    const float* c = yc + (size_t)s * Cv;
    float* o = out + (size_t)n * Cv;
    for (int i = threadIdx.x; i < Cv; i += TB)
        o[i] = a[i] + wsh * b[i] + wex * c[i];
}

// ============================================================
// launcher
// ============================================================
extern "C" void kernel_launch(void* const* d_in, const int* in_sizes, int n_in,
                              void* d_out, int out_size)
{
    const float* x    = (const float*)d_in[0];
    const float* ln1  = (const float*)d_in[1];
    const float* ln2  = (const float*)d_in[2];
    const float* Wq   = (const float*)d_in[3];
    const float* Wkv  = (const float*)d_in[4];
    const float* Wk_up= (const float*)d_in[5];
    const float* Wv_up= (const float*)d_in[6];
    const float* Wo   = (const float*)d_in[7];
    const float* Wr   = (const float*)d_in[8];
    const float* rb   = (const float*)d_in[9];
    const float* sw1  = (const float*)d_in[10];
    const float* sw2  = (const float*)d_in[11];
    const float* sw3  = (const float*)d_in[12];
    const float* ew1  = (const float*)d_in[13];
    const float* ew2  = (const float*)d_in[14];
    const float* ew3  = (const float*)d_in[15];
    float* out = (float*)d_out;

    float *pkv, *pq, *pk, *pv, *px1, *ph2, *psh, *pa13, *pc13, *pyc;
    __nv_bfloat16 *phbf, *ph2bf, *patbf, *pubf, *pucbf;
    __nv_bfloat16 *wq, *wkv, *wo, *s13, *s2, *e13, *e2;
    cudaGetSymbolAddress((void**)&pkv, g_kv);
    cudaGetSymbolAddress((void**)&pq,  g_q);
    cudaGetSymbolAddress((void**)&pk,  g_k);
    cudaGetSymbolAddress((void**)&pv,  g_v);
    cudaGetSymbolAddress((void**)&px1, g_x1);
    cudaGetSymbolAddress((void**)&ph2, g_h2);
    cudaGetSymbolAddress((void**)&psh, g_sh);
    cudaGetSymbolAddress((void**)&pa13, g_a13);
    cudaGetSymbolAddress((void**)&pc13, g_c13);
    cudaGetSymbolAddress((void**)&pyc, g_yc);
    cudaGetSymbolAddress((void**)&phbf,  g_hbf);
    cudaGetSymbolAddress((void**)&ph2bf, g_h2bf);
    cudaGetSymbolAddress((void**)&patbf, g_atbf);
    cudaGetSymbolAddress((void**)&pubf,  g_ubf);
    cudaGetSymbolAddress((void**)&pucbf, g_ucbf);
    cudaGetSymbolAddress((void**)&wq,  g_Wq_bf);
    cudaGetSymbolAddress((void**)&wkv, g_Wkv_bf);
    cudaGetSymbolAddress((void**)&wo,  g_Wo_bf);
    cudaGetSymbolAddress((void**)&s13, g_s13_bf);
    cudaGetSymbolAddress((void**)&s2,  g_sw2_bf);
    cudaGetSymbolAddress((void**)&e13, g_e13_bf);
    cudaGetSymbolAddress((void**)&e2,  g_ew2_bf);

    cudaFuncSetAttribute(flash_kernel, cudaFuncAttributeMaxDynamicSharedMemorySize, FLASH_SMEM);
    cudaFuncSetAttribute(tgemm_bf, cudaFuncAttributeMaxDynamicSharedMemorySize, TG_SMEM);
    cudaFuncSetAttribute(gg_tgemm_bf<true>,  cudaFuncAttributeMaxDynamicSharedMemorySize, TG_SMEM);
    cudaFuncSetAttribute(gg_tgemm_bf<false>, cudaFuncAttributeMaxDynamicSharedMemorySize, TG_SMEM);

    // ---- weight conversion (bf16; s13/e13 fused on N) ----
    f2bf_kernel<<<(Cv * Cv) / (TB * 4), TB>>>(Wq,  wq,  Cv * Cv);
    f2bf_kernel<<<(Cv * Lv) / (TB * 4), TB>>>(Wkv, wkv, Cv * Lv);
    f2bf_kernel<<<(Cv * Cv) / (TB * 4), TB>>>(Wo,  wo,  Cv * Cv);
    f2bf_pair<<<dim3((Cv * Iv) / (TB * 4), 1, 1),  TB>>>(sw1, sw3, s13);
    f2bf_kernel<<<(Iv * Cv) / (TB * 4), TB>>>(sw2, s2, Iv * Cv);
    f2bf_pair<<<dim3((Cv * Iv) / (TB * 4), 1, Ev), TB>>>(ew1, ew3, e13);
    f2bf_kernel<<<(Ev * Iv * Cv) / (TB * 4), TB>>>(ew2, e2, Ev * Iv * Cv);

    // ---- attention ----
    rmsnorm_kernel<<<Nv, TB>>>(x, ln1, nullptr, phbf);
    tgemm_bf<<<dim3(Cv / 256, Nv / 128), TB, TG_SMEM>>>(phbf, wq,  pq,  nullptr, Cv, Cv, 1.f);
    tgemm_bf<<<dim3(Lv / 256, Nv / 128), TB, TG_SMEM>>>(phbf, wkv, pkv, nullptr, Cv, Lv, 0.25f);
    kvup_wmma<<<dim3(Nv / 128, Hv * 2), TB>>>(pkv, Wk_up, Wv_up, pk, pv);
    rope_kernel<<<(Nv * Hv * 32) / TB, TB>>>(pq, Hv);
    rope_kernel<<<(Nv * Hv * 32) / TB, TB>>>(pk, 1);
    flash_kernel<<<dim3(Tv / 64, BHv), TB, FLASH_SMEM>>>(pq, pk, pv, patbf);
    tgemm_bf<<<dim3(Cv / 256, Nv / 128), TB, TG_SMEM>>>(patbf, wo, px1, x, Cv, Cv, 1.f);

    // ---- MoE ----
    rmsnorm_kernel<<<Nv, TB>>>(px1, ln2, ph2, ph2bf);
    router_kernel<<<Nv, TB>>>(ph2, Wr, rb);
    zero_kernel<<<1, 32>>>();
    hist_kernel<<<Nv / TB, TB>>>();
    offsets_kernel<<<1, 1>>>();
    scatter_kernel<<<Nv / TB, TB>>>();

    // shared expert: fused w1|w3 GEMM (N = 2*Iv = 4096)
    tgemm_bf<<<dim3((2 * Iv) / 256, Nv / 128), TB, TG_SMEM>>>(ph2bf, s13, pa13, nullptr, Cv, 2 * Iv, 1.f);
    silumul2_kernel<<<(Nv * Iv) / (TB * 4), TB>>>(pa13, pubf);
    tgemm_bf<<<dim3(Cv / 256, Nv / 128), TB, TG_SMEM>>>(pubf, s2, psh, nullptr, Iv, Cv, 1.f);

    // routed experts: fused w1|w3 grouped GEMM
    gg_tgemm_bf<true ><<<dim3(Nv / 128, (2 * Iv) / 256, Ev), TB, TG_SMEM>>>(ph2bf, e13, (size_t)Cv * 2 * Iv, Cv, 2 * Iv, pc13);
    silumul2_kernel<<<(Nv * Iv) / (TB * 4), TB>>>(pc13, pucbf);
    gg_tgemm_bf<false><<<dim3(Nv / 128, Cv / 256, Ev), TB, TG_SMEM>>>(pucbf, e2, (size_t)Iv * Cv, Iv, Cv, pyc);

    combine_kernel<<<Nv, TB>>>(px1, psh, pyc, out);
}

// round 9
// speedup vs baseline: 4.2454x; 1.0211x over previous
#include <cuda_runtime.h>
#include <cuda_bf16.h>
#include <mma.h>
#include <cstdint>

using namespace nvcuda;

#define TB 256

// ---- problem constants ----
constexpr int Bv = 8, Tv = 1024, Hv = 16, Dv = 64, Cv = 1024, Lv = 256, Ev = 8, Iv = 2048;
constexpr int Nv  = Bv * Tv;   // 8192 tokens
constexpr int BHv = Bv * Hv;   // 128

// ---- scratch (device globals; allocation-free) ----
__device__ float g_kv [Nv * Lv];
__device__ float g_q  [Nv * Cv];
__device__ float g_k  [Nv * Cv];          // [b,h,t,d]
__device__ float g_v  [Nv * Cv];          // [b,h,t,d]
__device__ float g_x1 [Nv * Cv];
__device__ float g_h2 [Nv * Cv];
__device__ float g_sh [Nv * Cv];
__device__ float g_yc [Nv * Cv];
__device__ int   g_sel[Nv];
__device__ float g_p  [Nv];
__device__ int   g_cnt[Ev];
__device__ int   g_off[Ev];
__device__ int   g_cur[Ev];
__device__ int   g_perm[Nv];

// bf16 activation buffers
__device__ __nv_bfloat16 g_hbf  [Nv * Cv];
__device__ __nv_bfloat16 g_h2bf [Nv * Cv];
__device__ __nv_bfloat16 g_atbf [Nv * Cv];
__device__ __nv_bfloat16 g_ubf  [Nv * Iv];
__device__ __nv_bfloat16 g_ucbf [Nv * Iv];

// bf16 weight buffers (converted per launch); row-major [K, N]
__device__ __nv_bfloat16 g_Wq_bf [Cv * Cv];
__device__ __nv_bfloat16 g_Wkv_bf[Cv * Lv];
__device__ __nv_bfloat16 g_Wo_bf [Cv * Cv];
__device__ __nv_bfloat16 g_s13_bf[Cv * 2 * Iv];        // sw1|sw3 interleaved 128-col blocks
__device__ __nv_bfloat16 g_sw2_bf[Iv * Cv];
__device__ __nv_bfloat16 g_e13_bf[Ev * Cv * 2 * Iv];   // ew1|ew3 interleaved 128-col blocks
__device__ __nv_bfloat16 g_ew2_bf[Ev * Iv * Cv];

__device__ __forceinline__ uint2 f4_to_bf4(float4 v) {
    __nv_bfloat162 lo = __floats2bfloat162_rn(v.x, v.y);
    __nv_bfloat162 hi = __floats2bfloat162_rn(v.z, v.w);
    uint2 r;
    r.x = *reinterpret_cast<unsigned int*>(&lo);
    r.y = *reinterpret_cast<unsigned int*>(&hi);
    return r;
}
__device__ __forceinline__ float to_tf32(float x) {
    float r; asm("cvt.rna.tf32.f32 %0, %1;" : "=f"(r) : "f"(x)); return r;
}
__device__ __forceinline__ void cp16(void* sdst, const void* gsrc) {
    uint32_t s = (uint32_t)__cvta_generic_to_shared(sdst);
    asm volatile("cp.async.ca.shared.global [%0], [%1], 16;" :: "r"(s), "l"(gsrc));
}
__device__ __forceinline__ void cp16z(void* sdst, const void* gsrc, bool p) {
    uint32_t s = (uint32_t)__cvta_generic_to_shared(sdst);
    asm volatile("cp.async.ca.shared.global [%0], [%1], 16, %2;" :: "r"(s), "l"(gsrc), "r"(p ? 16 : 0));
}
#define CP_COMMIT() asm volatile("cp.async.commit_group;")
#define CP_WAIT1()  asm volatile("cp.async.wait_group 1;")
#define CP_WAIT0()  asm volatile("cp.async.wait_group 0;")

__device__ __forceinline__ float4 silu4(float4 a, float4 b) {
    float4 r;
    r.x = (a.x / (1.f + expf(-a.x))) * b.x;
    r.y = (a.y / (1.f + expf(-a.y))) * b.y;
    r.z = (a.z / (1.f + expf(-a.z))) * b.z;
    r.w = (a.w / (1.f + expf(-a.w))) * b.w;
    return r;
}

// GEMM dynamic smem: As[3][128][40] + Bs[3][32][264] bf16
constexpr int TG_AS_BYTES = 3 * 128 * 40 * 2;   // 30720
constexpr int TG_SMEM = TG_AS_BYTES + 3 * 32 * 264 * 2;  // 81408

// ============================================================
// fp32 -> bf16 convert (n multiple of 8)
// ============================================================
__global__ void f2bf_kernel(const float* __restrict__ in, __nv_bfloat16* __restrict__ out, int n)
{
    int i = (blockIdx.x * TB + threadIdx.x) << 3;
    if (i < n) {
        float4 v0 = *(const float4*)(in + i);
        float4 v1 = *(const float4*)(in + i + 4);
        *(uint2*)(out + i)     = f4_to_bf4(v0);
        *(uint2*)(out + i + 4) = f4_to_bf4(v1);
    }
}

// ============================================================
// Paired convert, 128-col interleaved: in1/in2 [Cv][Iv] fp32 ->
// out [Cv][2*Iv] bf16 with out[r][blk*256 + c] = in1[r][blk*128+c],
// out[r][blk*256 + 128 + c] = in2[r][blk*128+c]. z = expert index.
// ============================================================
__global__ void f2bf_pair(const float* __restrict__ in1, const float* __restrict__ in2,
                          __nv_bfloat16* __restrict__ out)
{
    size_t zi = (size_t)blockIdx.z * Cv * Iv;
    size_t zo = (size_t)blockIdx.z * Cv * 2 * Iv;
    int i = (blockIdx.x * TB + threadIdx.x) << 2;   // exact grid: Cv*Iv/4 threads
    int r = i >> 11;            // / Iv (2048)
    int c = i & (Iv - 1);
    int blk = c >> 7, cc = c & 127;
    float4 v1 = *(const float4*)(in1 + zi + i);
    float4 v2 = *(const float4*)(in2 + zi + i);
    size_t ob = zo + (size_t)r * (2 * Iv) + blk * 256 + cc;
    *(uint2*)(out + ob)       = f4_to_bf4(v1);
    *(uint2*)(out + ob + 128) = f4_to_bf4(v2);
}

// ============================================================
// RMSNorm: one block per token; dual fp32 (optional) + bf16 output
// ============================================================
__global__ void rmsnorm_kernel(const float* __restrict__ x, const float* __restrict__ w,
                               float* __restrict__ y, __nv_bfloat16* __restrict__ yb)
{
    int n = blockIdx.x, tid = threadIdx.x;
    const float* xr = x + (size_t)n * Cv;
    __shared__ float red[TB];
    float ss = 0.f;
    for (int c = tid; c < Cv; c += TB) { float v = xr[c]; ss += v * v; }
    red[tid] = ss; __syncthreads();
    for (int s = TB / 2; s > 0; s >>= 1) { if (tid < s) red[tid] += red[tid + s]; __syncthreads(); }
    float rs = rsqrtf(red[0] / (float)Cv + 1e-6f);
    __nv_bfloat16* ybr = yb + (size_t)n * Cv;
    float* yr = y ? y + (size_t)n * Cv : nullptr;
    for (int c = tid; c < Cv; c += TB) {
        float v = xr[c] * rs * w[c];
        ybr[c] = __float2bfloat16(v);
        if (yr) yr[c] = v;
    }
}

// ============================================================
// BF16 cp.async 3-stage GEMM, 128x256 block tile, 64x64 warp tile.
// C = alpha*A[M,K]@B[K,N] (+Res). M mult 128, N mult 256, K mult 96.
// ============================================================
__global__ void __launch_bounds__(256) tgemm_bf(
    const __nv_bfloat16* __restrict__ A, const __nv_bfloat16* __restrict__ B,
    float* __restrict__ Cmat, const float* __restrict__ Res,
    int K, int N, float alpha)
{
    extern __shared__ char sm[];
    auto As = (__nv_bfloat16 (*)[128][40])sm;
    auto Bs = (__nv_bfloat16 (*)[32][264])(sm + TG_AS_BYTES);
    const int tid  = threadIdx.x;
    const int warp = tid >> 5;
    const int wm   = warp & 1, wn = warp >> 1;
    const int bm   = blockIdx.y * 128, bn = blockIdx.x * 256;

    wmma::fragment<wmma::accumulator, 16, 16, 16, float> acc[4][4];
#pragma unroll
    for (int mi = 0; mi < 4; mi++)
#pragma unroll
        for (int ni = 0; ni < 4; ni++) wmma::fill_fragment(acc[mi][ni], 0.f);

    const int nch = K >> 5;

    auto issue = [&](int stage, int k0) {
#pragma unroll
        for (int i = 0; i < 2; i++) {
            int ch = (i << 8) + tid;
            int ar = ch >> 2, ac = (ch & 3) << 3;
            cp16(&As[stage][ar][ac], A + (size_t)(bm + ar) * K + k0 + ac);
        }
#pragma unroll
        for (int i = 0; i < 4; i++) {
            int ch = (i << 8) + tid;
            int br = ch >> 5, bc = (ch & 31) << 3;
            cp16(&Bs[stage][br][bc], B + (size_t)(k0 + br) * N + bn + bc);
        }
    };

    issue(0, 0);  CP_COMMIT();
    issue(1, 32); CP_COMMIT();

    for (int ch = 0; ch < nch; ch++) {
        CP_WAIT1();
        __syncthreads();
        if (ch + 2 < nch) issue((ch + 2) % 3, (ch + 2) << 5);
        CP_COMMIT();
        int buf = ch % 3;
#pragma unroll
        for (int ks = 0; ks < 2; ks++) {
            int k16 = ks << 4;
            wmma::fragment<wmma::matrix_a, 16, 16, 16, __nv_bfloat16, wmma::row_major> af[4];
            wmma::fragment<wmma::matrix_b, 16, 16, 16, __nv_bfloat16, wmma::row_major> bf[4];
#pragma unroll
            for (int mi = 0; mi < 4; mi++)
                wmma::load_matrix_sync(af[mi], &As[buf][wm * 64 + mi * 16][k16], 40);
#pragma unroll
            for (int ni = 0; ni < 4; ni++)
                wmma::load_matrix_sync(bf[ni], &Bs[buf][k16][wn * 64 + ni * 16], 264);
#pragma unroll
            for (int mi = 0; mi < 4; mi++)
#pragma unroll
                for (int ni = 0; ni < 4; ni++)
                    wmma::mma_sync(acc[mi][ni], af[mi], bf[ni], acc[mi][ni]);
        }
    }

#pragma unroll
    for (int mi = 0; mi < 4; mi++)
#pragma unroll
        for (int ni = 0; ni < 4; ni++) {
            size_t row = (size_t)(bm + wm * 64 + mi * 16);
            size_t col = (size_t)(bn + wn * 64 + ni * 16);
            float* cp = Cmat + row * N + col;
            if (Res) {
                wmma::fragment<wmma::accumulator, 16, 16, 16, float> rf;
                wmma::load_matrix_sync(rf, Res + row * N + col, N, wmma::mem_row_major);
#pragma unroll
                for (int t = 0; t < rf.num_elements; t++)
                    acc[mi][ni].x[t] = acc[mi][ni].x[t] * alpha + rf.x[t];
            } else if (alpha != 1.f) {
#pragma unroll
                for (int t = 0; t < acc[mi][ni].num_elements; t++)
                    acc[mi][ni].x[t] *= alpha;
            }
            wmma::store_matrix_sync(cp, acc[mi][ni], N, wmma::mem_row_major);
        }
}

// ============================================================
// BF16 GEMM + fused SiLU epilogue (dense or grouped/gathered).
// B is the 128-col interleaved w1|w3 matrix [K][2*Iv].
// Output: U [rows][Iv] bf16, col block = blockNidx*128,
//   u = silu(left128) * right128.
// ============================================================
template <bool GROUPED>
__global__ void __launch_bounds__(256) tgemm_silu(
    const __nv_bfloat16* __restrict__ A, const __nv_bfloat16* __restrict__ Bbase,
    size_t strideB, int K, __nv_bfloat16* __restrict__ U)
{
    constexpr int N = 2 * Iv;   // 4096
    int cnt = Nv, o = 0, base, bnIdx;
    const __nv_bfloat16* B;
    if (GROUPED) {
        int e = blockIdx.z;
        cnt = g_cnt[e];
        base = blockIdx.x * 128;
        if (base >= cnt) return;
        o = g_off[e];
        bnIdx = blockIdx.y;
        B = Bbase + (size_t)e * strideB;
    } else {
        base = blockIdx.y * 128;
        bnIdx = blockIdx.x;
        B = Bbase;
    }
    const int bn = bnIdx * 256;

    extern __shared__ char sm[];
    auto As = (__nv_bfloat16 (*)[128][40])sm;
    auto Bs = (__nv_bfloat16 (*)[32][264])(sm + TG_AS_BYTES);
    const int tid  = threadIdx.x;
    const int warp = tid >> 5;
    const int wm   = warp & 1, wn = warp >> 1;

    wmma::fragment<wmma::accumulator, 16, 16, 16, float> acc[4][4];
#pragma unroll
    for (int mi = 0; mi < 4; mi++)
#pragma unroll
        for (int ni = 0; ni < 4; ni++) wmma::fill_fragment(acc[mi][ni], 0.f);

    int grow[2]; bool gv[2]; int arr[2]; int arc[2];
#pragma unroll
    for (int i = 0; i < 2; i++) {
        int ch = (i << 8) + tid;
        arr[i] = ch >> 2; arc[i] = (ch & 3) << 3;
        int lr = base + arr[i];
        gv[i] = lr < cnt;
        grow[i] = gv[i] ? (GROUPED ? g_perm[o + lr] : lr) : 0;
    }

    const int nch = K >> 5;

    auto issue = [&](int stg, int k0) {
#pragma unroll
        for (int i = 0; i < 2; i++)
            cp16z(&As[stg][arr[i]][arc[i]], A + (size_t)grow[i] * K + k0 + arc[i], gv[i]);
#pragma unroll
        for (int i = 0; i < 4; i++) {
            int ch = (i << 8) + tid;
            int br = ch >> 5, bc = (ch & 31) << 3;
            cp16(&Bs[stg][br][bc], B + (size_t)(k0 + br) * N + bn + bc);
        }
    };

    issue(0, 0);  CP_COMMIT();
    issue(1, 32); CP_COMMIT();

    for (int ch = 0; ch < nch; ch++) {
        CP_WAIT1();
        __syncthreads();
        if (ch + 2 < nch) issue((ch + 2) % 3, (ch + 2) << 5);
        CP_COMMIT();
        int buf = ch % 3;
#pragma unroll
        for (int ks = 0; ks < 2; ks++) {
            int k16 = ks << 4;
            wmma::fragment<wmma::matrix_a, 16, 16, 16, __nv_bfloat16, wmma::row_major> af[4];
            wmma::fragment<wmma::matrix_b, 16, 16, 16, __nv_bfloat16, wmma::row_major> bf[4];
#pragma unroll
            for (int mi = 0; mi < 4; mi++)
                wmma::load_matrix_sync(af[mi], &As[buf][wm * 64 + mi * 16][k16], 40);
#pragma unroll
            for (int ni = 0; ni < 4; ni++)
                wmma::load_matrix_sync(bf[ni], &Bs[buf][k16][wn * 64 + ni * 16], 264);
#pragma unroll
            for (int mi = 0; mi < 4; mi++)
#pragma unroll
                for (int ni = 0; ni < 4; ni++)
                    wmma::mma_sync(acc[mi][ni], af[mi], bf[ni], acc[mi][ni]);
        }
    }

    // fused SiLU epilogue: stage 32x256 fp32 per mi, pair left/right halves.
    __syncthreads();
    float* S = (float*)sm;                  // 32 rows x ldm 264
    const int er = tid >> 3;                // 0..31
    const int ec = (tid & 7) << 4;          // 0,16,...,112
#pragma unroll
    for (int mi = 0; mi < 4; mi++) {
#pragma unroll
        for (int ni = 0; ni < 4; ni++)
            wmma::store_matrix_sync(S + (wm * 16) * 264 + wn * 64 + ni * 16,
                                    acc[mi][ni], 264, wmma::mem_row_major);
        __syncthreads();
        int lr = base + (er >> 4) * 64 + mi * 16 + (er & 15);
        if (lr < cnt) {
            size_t row = (size_t)(GROUPED ? (o + lr) : lr);
            __nv_bfloat16* op = U + row * Iv + bnIdx * 128 + ec;
            const float* sp = S + er * 264 + ec;
#pragma unroll
            for (int j = 0; j < 16; j += 4) {
                float4 a = *(const float4*)(sp + j);
                float4 b = *(const float4*)(sp + 128 + j);
                *(uint2*)(op + j) = f4_to_bf4(silu4(a, b));
            }
        }
        __syncthreads();
    }
}

// ============================================================
// Grouped (per-expert) BF16 GEMM, 128x256 tile, fp32 out (w2 stage).
// ============================================================
template <bool GATHER>
__global__ void __launch_bounds__(256) gg_tgemm_bf(
    const __nv_bfloat16* __restrict__ A, const __nv_bfloat16* __restrict__ Bbase,
    size_t strideB, int K, int N, float* __restrict__ Out)
{
    int e = blockIdx.z;
    int cnt = g_cnt[e];
    int base = blockIdx.x * 128;
    if (base >= cnt) return;
    int o = g_off[e];
    const __nv_bfloat16* B = Bbase + (size_t)e * strideB;

    extern __shared__ char sm[];
    auto As = (__nv_bfloat16 (*)[128][40])sm;
    auto Bs = (__nv_bfloat16 (*)[32][264])(sm + TG_AS_BYTES);
    const int tid  = threadIdx.x;
    const int warp = tid >> 5;
    const int lane = tid & 31;
    const int wm   = warp & 1, wn = warp >> 1;
    const int bn   = blockIdx.y * 256;

    wmma::fragment<wmma::accumulator, 16, 16, 16, float> acc[4][4];
#pragma unroll
    for (int mi = 0; mi < 4; mi++)
#pragma unroll
        for (int ni = 0; ni < 4; ni++) wmma::fill_fragment(acc[mi][ni], 0.f);

    int grow[2]; bool gv[2]; int arr[2]; int arc[2];
#pragma unroll
    for (int i = 0; i < 2; i++) {
        int ch = (i << 8) + tid;
        arr[i] = ch >> 2; arc[i] = (ch & 3) << 3;
        int lr = base + arr[i];
        gv[i] = lr < cnt;
        grow[i] = gv[i] ? (GATHER ? g_perm[o + lr] : (o + lr)) : 0;
    }

    const int nch = K >> 5;

    auto issue = [&](int stg, int k0) {
#pragma unroll
        for (int i = 0; i < 2; i++)
            cp16z(&As[stg][arr[i]][arc[i]], A + (size_t)grow[i] * K + k0 + arc[i], gv[i]);
#pragma unroll
        for (int i = 0; i < 4; i++) {
            int ch = (i << 8) + tid;
            int br = ch >> 5, bc = (ch & 31) << 3;
            cp16(&Bs[stg][br][bc], B + (size_t)(k0 + br) * N + bn + bc);
        }
    };

    issue(0, 0);  CP_COMMIT();
    issue(1, 32); CP_COMMIT();

    for (int ch = 0; ch < nch; ch++) {
        CP_WAIT1();
        __syncthreads();
        if (ch + 2 < nch) issue((ch + 2) % 3, (ch + 2) << 5);
        CP_COMMIT();
        int buf = ch % 3;
#pragma unroll
        for (int ks = 0; ks < 2; ks++) {
            int k16 = ks << 4;
            wmma::fragment<wmma::matrix_a, 16, 16, 16, __nv_bfloat16, wmma::row_major> af[4];
            wmma::fragment<wmma::matrix_b, 16, 16, 16, __nv_bfloat16, wmma::row_major> bf[4];
#pragma unroll
            for (int mi = 0; mi < 4; mi++)
                wmma::load_matrix_sync(af[mi], &As[buf][wm * 64 + mi * 16][k16], 40);
#pragma unroll
            for (int ni = 0; ni < 4; ni++)
                wmma::load_matrix_sync(bf[ni], &Bs[buf][k16][wn * 64 + ni * 16], 264);
#pragma unroll
            for (int mi = 0; mi < 4; mi++)
#pragma unroll
                for (int ni = 0; ni < 4; ni++)
                    wmma::mma_sync(acc[mi][ni], af[mi], bf[ni], acc[mi][ni]);
        }
    }

    __syncthreads();   // done with As/Bs; reuse smem as epilogue stage
    float* stg = (float*)sm + warp * 320;   // 16 rows x ldm 20
    const int sr = lane >> 1, sc0 = (lane & 1) << 3;
#pragma unroll
    for (int mi = 0; mi < 4; mi++)
#pragma unroll
        for (int ni = 0; ni < 4; ni++) {
            wmma::store_matrix_sync(stg, acc[mi][ni], 20, wmma::mem_row_major);
            __syncwarp();
            int lr = base + wm * 64 + mi * 16 + sr;
            if (lr < cnt) {
                size_t row = (size_t)(o + lr);
                int col = bn + wn * 64 + ni * 16 + sc0;
                float4 v0 = *(float4*)(stg + sr * 20 + sc0);
                float4 v1 = *(float4*)(stg + sr * 20 + sc0 + 4);
                *(float4*)(Out + row * N + col)     = v0;
                *(float4*)(Out + row * N + col + 4) = v1;
            }
            __syncwarp();
        }
}

// ============================================================
// K/V up-projection, bf16 wmma. grid (Nv/128, Hv*2). (fp32 inputs)
// ============================================================
__global__ void kvup_wmma(const float* __restrict__ kv,
                          const float* __restrict__ Wk_up, const float* __restrict__ Wv_up,
                          float* __restrict__ kout, float* __restrict__ vout)
{
    int y = blockIdx.y;
    int h = y >> 1, which = y & 1;
    const float* W = (which ? Wv_up : Wk_up) + (size_t)h * Lv * Dv;
    float* outp = which ? vout : kout;
    int bm = blockIdx.x * 128;

    __shared__ __nv_bfloat16 As[2][128][40];
    __shared__ __nv_bfloat16 Bs[2][32][72];
    const int tid  = threadIdx.x;
    const int warp = tid >> 5;
    const int wm   = warp & 3, wn = warp >> 2;

    wmma::fragment<wmma::accumulator, 16, 16, 16, float> acc[2][2];
#pragma unroll
    for (int mi = 0; mi < 2; mi++)
#pragma unroll
        for (int ni = 0; ni < 2; ni++) wmma::fill_fragment(acc[mi][ni], 0.f);

    const int ar0 = tid >> 3, ac = (tid & 7) << 2;
    const int br0 = tid >> 4, bc = (tid & 15) << 2;

    float4 aR[4], bR[2];
    const int nch = Lv >> 5;

#pragma unroll
    for (int i = 0; i < 4; i++)
        aR[i] = *(const float4*)(kv + (size_t)(bm + ar0 + (i << 5)) * Lv + ac);
#pragma unroll
    for (int i = 0; i < 2; i++)
        bR[i] = *(const float4*)(W + (size_t)(br0 + (i << 4)) * Dv + bc);
#pragma unroll
    for (int i = 0; i < 4; i++)
        *(uint2*)&As[0][ar0 + (i << 5)][ac] = f4_to_bf4(aR[i]);
#pragma unroll
    for (int i = 0; i < 2; i++)
        *(uint2*)&Bs[0][br0 + (i << 4)][bc] = f4_to_bf4(bR[i]);
    __syncthreads();

    int cur = 0;
    for (int ch = 0; ch < nch; ch++) {
        bool has = (ch + 1) < nch;
        if (has) {
            int k0 = (ch + 1) << 5;
#pragma unroll
            for (int i = 0; i < 4; i++)
                aR[i] = *(const float4*)(kv + (size_t)(bm + ar0 + (i << 5)) * Lv + k0 + ac);
#pragma unroll
            for (int i = 0; i < 2; i++)
                bR[i] = *(const float4*)(W + (size_t)(k0 + br0 + (i << 4)) * Dv + bc);
        }
#pragma unroll
        for (int ks = 0; ks < 2; ks++) {
            int k16 = ks << 4;
            wmma::fragment<wmma::matrix_a, 16, 16, 16, __nv_bfloat16, wmma::row_major> af[2];
            wmma::fragment<wmma::matrix_b, 16, 16, 16, __nv_bfloat16, wmma::row_major> bf[2];
#pragma unroll
            for (int mi = 0; mi < 2; mi++)
                wmma::load_matrix_sync(af[mi], &As[cur][wm * 32 + mi * 16][k16], 40);
#pragma unroll
            for (int ni = 0; ni < 2; ni++)
                wmma::load_matrix_sync(bf[ni], &Bs[cur][k16][wn * 32 + ni * 16], 72);
#pragma unroll
            for (int mi = 0; mi < 2; mi++)
#pragma unroll
                for (int ni = 0; ni < 2; ni++)
                    wmma::mma_sync(acc[mi][ni], af[mi], bf[ni], acc[mi][ni]);
        }
        if (has) {
            int nxt = cur ^ 1;
#pragma unroll
            for (int i = 0; i < 4; i++)
                *(uint2*)&As[nxt][ar0 + (i << 5)][ac] = f4_to_bf4(aR[i]);
#pragma unroll
            for (int i = 0; i < 2; i++)
                *(uint2*)&Bs[nxt][br0 + (i << 4)][bc] = f4_to_bf4(bR[i]);
        }
        __syncthreads();
        cur ^= 1;
    }

#pragma unroll
    for (int mi = 0; mi < 2; mi++) {
        int n0 = bm + wm * 32 + mi * 16;
        int b = n0 >> 10, t0 = n0 & 1023;
        float* bp = outp + ((size_t)(b * Hv + h) * Tv + t0) * Dv;
#pragma unroll
        for (int ni = 0; ni < 2; ni++)
            wmma::store_matrix_sync(bp + wn * 32 + ni * 16, acc[mi][ni], Dv, wmma::mem_row_major);
    }
}

// ============================================================
// RoPE in place on 64-wide head vectors.
// ============================================================
__global__ void rope_kernel(float* __restrict__ xp, int posDiv)
{
    int idx = blockIdx.x * TB + threadIdx.x;
    int outer = idx >> 5;
    int j = idx & 31;
    int pos = (outer / posDiv) & (Tv - 1);
    float invf = powf(100000.0f, -(float)j * (1.0f / 32.0f));
    float f = (float)pos * invf;
    float s, c; sincosf(f, &s, &c);
    float* p = xp + (size_t)outer * Dv;
    float x1 = p[j], x2 = p[j + 32];
    p[j]      = x1 * c - x2 * s;
    p[j + 32] = x1 * s + x2 * c;
}

// ============================================================
// Flash attention (tf32 wmma, online softmax). Out bf16 token-major.
// ============================================================
constexpr int FLASH_SMEM = (5 * 64 * 68 + 3 * 64) * 4;

__global__ void __launch_bounds__(256) flash_kernel(
    const float* __restrict__ q, const float* __restrict__ k,
    const float* __restrict__ v, __nv_bfloat16* __restrict__ obf)
{
    extern __shared__ float fs[];
    float (*Qs)[68] = (float(*)[68])fs;
    float (*Ks)[68] = (float(*)[68])(fs + 64 * 68);
    float (*Vs)[68] = (float(*)[68])(fs + 2 * 64 * 68);
    float (*Ss)[68] = (float(*)[68])(fs + 3 * 64 * 68);
    float (*Os)[68] = (float(*)[68])(fs + 4 * 64 * 68);
    float* mrow = fs + 5 * 64 * 68;
    float* lrow = mrow + 64;
    float* srow = lrow + 64;

    const int qt = blockIdx.x, bh = blockIdx.y;
    const int b = bh >> 4, h = bh & 15;
    const int qs = qt * 64;
    const int tid = threadIdx.x;
    const int warp = tid >> 5;
    const int wm = warp & 3, wn = warp >> 2;
    const int row = tid >> 2, qd = tid & 3;

#pragma unroll
    for (int i = 0; i < 4; i++) {
        int ch = (i << 8) + tid;
        int r = ch >> 4, c = (ch & 15) << 2;
        cp16(&Qs[r][c], q + (size_t)(b * Tv + qs + r) * Cv + h * Dv + c);
    }
    CP_COMMIT();
    for (int i = tid; i < 64 * 68; i += 256) fs[4 * 64 * 68 + i] = 0.f;
    if (tid < 64) { mrow[tid] = -1e30f; lrow[tid] = 0.f; }
    CP_WAIT0();
    __syncthreads();

    for (int kt = 0; kt <= qt; kt++) {
        int ks = kt * 64;
#pragma unroll
        for (int i = 0; i < 4; i++) {
            int ch = (i << 8) + tid;
            int r = ch >> 4, c = (ch & 15) << 2;
            cp16(&Ks[r][c], k + (size_t)(bh * Tv + ks + r) * Dv + c);
            cp16(&Vs[r][c], v + (size_t)(bh * Tv + ks + r) * Dv + c);
        }
        CP_COMMIT();
        CP_WAIT0();
        __syncthreads();

        {
            wmma::fragment<wmma::accumulator, 16, 16, 8, float> a0, a1;
            wmma::fill_fragment(a0, 0.f); wmma::fill_fragment(a1, 0.f);
#pragma unroll
            for (int k8 = 0; k8 < 64; k8 += 8) {
                wmma::fragment<wmma::matrix_a, 16, 16, 8, wmma::precision::tf32, wmma::row_major> af;
                wmma::fragment<wmma::matrix_b, 16, 16, 8, wmma::precision::tf32, wmma::col_major> bf0, bf1;
                wmma::load_matrix_sync(af, &Qs[wm * 16][k8], 68);
                wmma::load_matrix_sync(bf0, &Ks[wn * 32][k8], 68);
                wmma::load_matrix_sync(bf1, &Ks[wn * 32 + 16][k8], 68);
                wmma::mma_sync(a0, af, bf0, a0);
                wmma::mma_sync(a1, af, bf1, a1);
            }
#pragma unroll
            for (int t = 0; t < a0.num_elements; t++) { a0.x[t] *= 0.125f; a1.x[t] *= 0.125f; }
            wmma::store_matrix_sync(&Ss[wm * 16][wn * 32], a0, 68, wmma::mem_row_major);
            wmma::store_matrix_sync(&Ss[wm * 16][wn * 32 + 16], a1, 68, wmma::mem_row_major);
        }
        __syncthreads();

        {
            const bool diag = (kt == qt);
            float sv[16];
            float mloc = -1e30f;
#pragma unroll
            for (int i = 0; i < 16; i++) {
                int j = qd + (i << 2);
                float s = Ss[row][j];
                if (diag && j > row) s = -1e30f;
                sv[i] = s;
                mloc = fmaxf(mloc, s);
            }
            mloc = fmaxf(mloc, __shfl_xor_sync(0xffffffffu, mloc, 1));
            mloc = fmaxf(mloc, __shfl_xor_sync(0xffffffffu, mloc, 2));
            float mold = mrow[row];
            float mnew = fmaxf(mold, mloc);
            float psum = 0.f;
#pragma unroll
            for (int i = 0; i < 16; i++) {
                int j = qd + (i << 2);
                float p = (sv[i] > -1e29f) ? expf(sv[i] - mnew) : 0.f;
                Ss[row][j] = to_tf32(p);
                psum += p;
            }
            psum += __shfl_xor_sync(0xffffffffu, psum, 1);
            psum += __shfl_xor_sync(0xffffffffu, psum, 2);
            if (qd == 0) {
                float scl = expf(mold - mnew);
                mrow[row] = mnew;
                lrow[row] = lrow[row] * scl + psum;
                srow[row] = scl;
            }
        }
        __syncthreads();

        {
            wmma::fragment<wmma::matrix_a, 16, 16, 8, wmma::precision::tf32, wmma::row_major> af[8];
#pragma unroll
            for (int kk = 0; kk < 8; kk++)
                wmma::load_matrix_sync(af[kk], &Ss[wm * 16][kk * 8], 68);
            __syncthreads();
            wmma::fragment<wmma::accumulator, 16, 16, 8, float> a0, a1;
            wmma::fill_fragment(a0, 0.f); wmma::fill_fragment(a1, 0.f);
#pragma unroll
            for (int kk = 0; kk < 8; kk++) {
                wmma::fragment<wmma::matrix_b, 16, 16, 8, wmma::precision::tf32, wmma::row_major> bf0, bf1;
                wmma::load_matrix_sync(bf0, &Vs[kk * 8][wn * 32], 68);
                wmma::load_matrix_sync(bf1, &Vs[kk * 8][wn * 32 + 16], 68);
                wmma::mma_sync(a0, af[kk], bf0, a0);
                wmma::mma_sync(a1, af[kk], bf1, a1);
            }
            wmma::store_matrix_sync(&Ss[wm * 16][wn * 32], a0, 68, wmma::mem_row_major);
            wmma::store_matrix_sync(&Ss[wm * 16][wn * 32 + 16], a1, 68, wmma::mem_row_major);
        }
        __syncthreads();

        {
            float scl = srow[row];
#pragma unroll
            for (int i = 0; i < 16; i++) {
                int j = qd + (i << 2);
                Os[row][j] = Os[row][j] * scl + Ss[row][j];
            }
        }
        __syncthreads();
    }

    {
        float inv = 1.f / lrow[row];
        __nv_bfloat16* op = obf + (size_t)(b * Tv + qs + row) * Cv + h * Dv;
#pragma unroll
        for (int i = 0; i < 16; i++) {
            int j = qd + (i << 2);
            op[j] = __float2bfloat16(Os[row][j] * inv);
        }
    }
}

// ============================================================
// Router
// ============================================================
__global__ void router_kernel(const float* __restrict__ h2, const float* __restrict__ Wr,
                              const float* __restrict__ rb)
{
    int n = blockIdx.x, tid = threadIdx.x;
    const float* xr = h2 + (size_t)n * Cv;
    float part[Ev];
#pragma unroll
    for (int e = 0; e < Ev; e++) part[e] = 0.f;
    for (int c = tid; c < Cv; c += TB) {
        float xv = xr[c];
#pragma unroll
        for (int e = 0; e < Ev; e++) part[e] += xv * Wr[c * Ev + e];
    }
    __shared__ float sd[Ev][TB];
#pragma unroll
    for (int e = 0; e < Ev; e++) sd[e][tid] = part[e];
    __syncthreads();
    for (int st = TB / 2; st > 0; st >>= 1) {
        if (tid < st)
#pragma unroll
            for (int e = 0; e < Ev; e++) sd[e][tid] += sd[e][tid + st];
        __syncthreads();
    }
    if (tid == 0) {
        int best = 0; float bp = -1.f;
#pragma unroll
        for (int e = 0; e < Ev; e++) {
            float lg = fminf(fmaxf(sd[e][0] + rb[e], -50.f), 50.f);
            float pr = 1.f / (1.f + expf(-lg));
            if (pr > bp) { bp = pr; best = e; }
        }
        g_sel[n] = best;
        g_p[n]   = fminf(fmaxf(bp, 1e-8f), 1.f - 1e-8f);
    }
}

__global__ void zero_kernel() {
    int t = threadIdx.x;
    if (t < Ev) { g_cnt[t] = 0; g_cur[t] = 0; }
}
__global__ void hist_kernel() {
    int n = blockIdx.x * TB + threadIdx.x;
    if (n < Nv) atomicAdd(&g_cnt[g_sel[n]], 1);
}
__global__ void offsets_kernel() {
    int s = 0;
    for (int e = 0; e < Ev; e++) { g_off[e] = s; s += g_cnt[e]; }
}
__global__ void scatter_kernel() {
    int n = blockIdx.x * TB + threadIdx.x;
    if (n < Nv) {
        int e = g_sel[n];
        int pos = atomicAdd(&g_cur[e], 1);
        g_perm[g_off[e] + pos] = n;
    }
}

__global__ void combine_kernel(const float* __restrict__ x1, const float* __restrict__ sh,
                               const float* __restrict__ yc, float* __restrict__ out)
{
    int s = blockIdx.x;
    int n = g_perm[s];
    float p = g_p[n];
    float tw = fminf(fmaxf(0.5f + p + 1e-8f, 0.5f), 2.0f);
    float wsh = 0.5f / tw, wex = p / tw;
    const float* a = x1 + (size_t)n * Cv;
    const float* b = sh + (size_t)n * Cv;
    const float* c = yc + (size_t)s * Cv;
    float* o = out + (size_t)n * Cv;
    for (int i = threadIdx.x; i < Cv; i += TB)
        o[i] = a[i] + wsh * b[i] + wex * c[i];
}

// ============================================================
// launcher
// ============================================================
extern "C" void kernel_launch(void* const* d_in, const int* in_sizes, int n_in,
                              void* d_out, int out_size)
{
    const float* x    = (const float*)d_in[0];
    const float* ln1  = (const float*)d_in[1];
    const float* ln2  = (const float*)d_in[2];
    const float* Wq   = (const float*)d_in[3];
    const float* Wkv  = (const float*)d_in[4];
    const float* Wk_up= (const float*)d_in[5];
    const float* Wv_up= (const float*)d_in[6];
    const float* Wo   = (const float*)d_in[7];
    const float* Wr   = (const float*)d_in[8];
    const float* rb   = (const float*)d_in[9];
    const float* sw1  = (const float*)d_in[10];
    const float* sw2  = (const float*)d_in[11];
    const float* sw3  = (const float*)d_in[12];
    const float* ew1  = (const float*)d_in[13];
    const float* ew2  = (const float*)d_in[14];
    const float* ew3  = (const float*)d_in[15];
    float* out = (float*)d_out;

    float *pkv, *pq, *pk, *pv, *px1, *ph2, *psh, *pyc;
    __nv_bfloat16 *phbf, *ph2bf, *patbf, *pubf, *pucbf;
    __nv_bfloat16 *wq, *wkv, *wo, *s13, *s2, *e13, *e2;
    cudaGetSymbolAddress((void**)&pkv, g_kv);
    cudaGetSymbolAddress((void**)&pq,  g_q);
    cudaGetSymbolAddress((void**)&pk,  g_k);
    cudaGetSymbolAddress((void**)&pv,  g_v);
    cudaGetSymbolAddress((void**)&px1, g_x1);
    cudaGetSymbolAddress((void**)&ph2, g_h2);
    cudaGetSymbolAddress((void**)&psh, g_sh);
    cudaGetSymbolAddress((void**)&pyc, g_yc);
    cudaGetSymbolAddress((void**)&phbf,  g_hbf);
    cudaGetSymbolAddress((void**)&ph2bf, g_h2bf);
    cudaGetSymbolAddress((void**)&patbf, g_atbf);
    cudaGetSymbolAddress((void**)&pubf,  g_ubf);
    cudaGetSymbolAddress((void**)&pucbf, g_ucbf);
    cudaGetSymbolAddress((void**)&wq,  g_Wq_bf);
    cudaGetSymbolAddress((void**)&wkv, g_Wkv_bf);
    cudaGetSymbolAddress((void**)&wo,  g_Wo_bf);
    cudaGetSymbolAddress((void**)&s13, g_s13_bf);
    cudaGetSymbolAddress((void**)&s2,  g_sw2_bf);
    cudaGetSymbolAddress((void**)&e13, g_e13_bf);
    cudaGetSymbolAddress((void**)&e2,  g_ew2_bf);

    cudaFuncSetAttribute(flash_kernel, cudaFuncAttributeMaxDynamicSharedMemorySize, FLASH_SMEM);
    cudaFuncSetAttribute(tgemm_bf, cudaFuncAttributeMaxDynamicSharedMemorySize, TG_SMEM);
    cudaFuncSetAttribute(tgemm_silu<false>, cudaFuncAttributeMaxDynamicSharedMemorySize, TG_SMEM);
    cudaFuncSetAttribute(tgemm_silu<true>,  cudaFuncAttributeMaxDynamicSharedMemorySize, TG_SMEM);
    cudaFuncSetAttribute(gg_tgemm_bf<true>,  cudaFuncAttributeMaxDynamicSharedMemorySize, TG_SMEM);
    cudaFuncSetAttribute(gg_tgemm_bf<false>, cudaFuncAttributeMaxDynamicSharedMemorySize, TG_SMEM);

    // ---- weight conversion (bf16; s13/e13 interleaved 128-blocks) ----
    f2bf_kernel<<<(Cv * Cv) / (TB * 8), TB>>>(Wq,  wq,  Cv * Cv);
    f2bf_kernel<<<(Cv * Lv) / (TB * 8), TB>>>(Wkv, wkv, Cv * Lv);
    f2bf_kernel<<<(Cv * Cv) / (TB * 8), TB>>>(Wo,  wo,  Cv * Cv);
    f2bf_pair<<<dim3((Cv * Iv) / (TB * 4), 1, 1),  TB>>>(sw1, sw3, s13);
    f2bf_kernel<<<(Iv * Cv) / (TB * 8), TB>>>(sw2, s2, Iv * Cv);
    f2bf_pair<<<dim3((Cv * Iv) / (TB * 4), 1, Ev), TB>>>(ew1, ew3, e13);
    f2bf_kernel<<<(Ev * Iv * Cv) / (TB * 8), TB>>>(ew2, e2, Ev * Iv * Cv);

    // ---- attention ----
    rmsnorm_kernel<<<Nv, TB>>>(x, ln1, nullptr, phbf);
    tgemm_bf<<<dim3(Cv / 256, Nv / 128), TB, TG_SMEM>>>(phbf, wq,  pq,  nullptr, Cv, Cv, 1.f);
    tgemm_bf<<<dim3(Lv / 256, Nv / 128), TB, TG_SMEM>>>(phbf, wkv, pkv, nullptr, Cv, Lv, 0.25f);
    kvup_wmma<<<dim3(Nv / 128, Hv * 2), TB>>>(pkv, Wk_up, Wv_up, pk, pv);
    rope_kernel<<<(Nv * Hv * 32) / TB, TB>>>(pq, Hv);
    rope_kernel<<<(Nv * Hv * 32) / TB, TB>>>(pk, 1);
    flash_kernel<<<dim3(Tv / 64, BHv), TB, FLASH_SMEM>>>(pq, pk, pv, patbf);
    tgemm_bf<<<dim3(Cv / 256, Nv / 128), TB, TG_SMEM>>>(patbf, wo, px1, x, Cv, Cv, 1.f);

    // ---- MoE ----
    rmsnorm_kernel<<<Nv, TB>>>(px1, ln2, ph2, ph2bf);
    router_kernel<<<Nv, TB>>>(ph2, Wr, rb);
    zero_kernel<<<1, 32>>>();
    hist_kernel<<<Nv / TB, TB>>>();
    offsets_kernel<<<1, 1>>>();
    scatter_kernel<<<Nv / TB, TB>>>();

    // shared expert: fused w1|w3 GEMM + SiLU epilogue -> ubf
    tgemm_silu<false><<<dim3((2 * Iv) / 256, Nv / 128), TB, TG_SMEM>>>(ph2bf, s13, 0, Cv, pubf);
    tgemm_bf<<<dim3(Cv / 256, Nv / 128), TB, TG_SMEM>>>(pubf, s2, psh, nullptr, Iv, Cv, 1.f);

    // routed experts: fused grouped w1|w3 GEMM + SiLU epilogue -> ucbf (compact)
    tgemm_silu<true><<<dim3(Nv / 128, (2 * Iv) / 256, Ev), TB, TG_SMEM>>>(ph2bf, e13, (size_t)Cv * 2 * Iv, Cv, pucbf);
    gg_tgemm_bf<false><<<dim3(Nv / 128, Cv / 256, Ev), TB, TG_SMEM>>>(pucbf, e2, (size_t)Iv * Cv, Iv, Cv, pyc);

    combine_kernel<<<Nv, TB>>>(px1, psh, pyc, out);
}

// round 10
// speedup vs baseline: 4.2883x; 1.0101x over previous
#include <cuda_runtime.h>
#include <cuda_bf16.h>
#include <mma.h>
#include <cstdint>

using namespace nvcuda;

#define TB 256

// ---- problem constants ----
constexpr int Bv = 8, Tv = 1024, Hv = 16, Dv = 64, Cv = 1024, Lv = 256, Ev = 8, Iv = 2048;
constexpr int Nv  = Bv * Tv;   // 8192 tokens
constexpr int BHv = Bv * Hv;   // 128

// ---- scratch (device globals; allocation-free) ----
__device__ float g_kv [Nv * Lv];
__device__ float g_q  [Nv * Cv];
__device__ float g_k  [Nv * Cv];          // [b,h,t,d]
__device__ float g_v  [Nv * Cv];          // [b,h,t,d]
__device__ float g_x1 [Nv * Cv];
__device__ float g_h2 [Nv * Cv];
__device__ float g_sh [Nv * Cv];
__device__ int   g_sel[Nv];
__device__ float g_p  [Nv];
__device__ int   g_cnt[Ev];
__device__ int   g_off[Ev];
__device__ int   g_cur[Ev];
__device__ int   g_perm[Nv];

// bf16 activation buffers
__device__ __nv_bfloat16 g_hbf  [Nv * Cv];
__device__ __nv_bfloat16 g_h2bf [Nv * Cv];
__device__ __nv_bfloat16 g_atbf [Nv * Cv];
__device__ __nv_bfloat16 g_ubf  [Nv * Iv];
__device__ __nv_bfloat16 g_ucbf [Nv * Iv];

// bf16 weight buffers (converted per launch); row-major [K, N]
__device__ __nv_bfloat16 g_Wq_bf [Cv * Cv];
__device__ __nv_bfloat16 g_Wkv_bf[Cv * Lv];
__device__ __nv_bfloat16 g_Wo_bf [Cv * Cv];
__device__ __nv_bfloat16 g_s13_bf[Cv * 2 * Iv];        // sw1|sw3 interleaved 128-col blocks
__device__ __nv_bfloat16 g_sw2_bf[Iv * Cv];
__device__ __nv_bfloat16 g_e13_bf[Ev * Cv * 2 * Iv];   // ew1|ew3 interleaved 128-col blocks
__device__ __nv_bfloat16 g_ew2_bf[Ev * Iv * Cv];

__device__ __forceinline__ uint2 f4_to_bf4(float4 v) {
    __nv_bfloat162 lo = __floats2bfloat162_rn(v.x, v.y);
    __nv_bfloat162 hi = __floats2bfloat162_rn(v.z, v.w);
    uint2 r;
    r.x = *reinterpret_cast<unsigned int*>(&lo);
    r.y = *reinterpret_cast<unsigned int*>(&hi);
    return r;
}
__device__ __forceinline__ float to_tf32(float x) {
    float r; asm("cvt.rna.tf32.f32 %0, %1;" : "=f"(r) : "f"(x)); return r;
}
__device__ __forceinline__ void cp16(void* sdst, const void* gsrc) {
    uint32_t s = (uint32_t)__cvta_generic_to_shared(sdst);
    asm volatile("cp.async.ca.shared.global [%0], [%1], 16;" :: "r"(s), "l"(gsrc));
}
__device__ __forceinline__ void cp16z(void* sdst, const void* gsrc, bool p) {
    uint32_t s = (uint32_t)__cvta_generic_to_shared(sdst);
    asm volatile("cp.async.ca.shared.global [%0], [%1], 16, %2;" :: "r"(s), "l"(gsrc), "r"(p ? 16 : 0));
}
#define CP_COMMIT() asm volatile("cp.async.commit_group;")
#define CP_WAIT1()  asm volatile("cp.async.wait_group 1;")
#define CP_WAIT0()  asm volatile("cp.async.wait_group 0;")

__device__ __forceinline__ float4 silu4(float4 a, float4 b) {
    float4 r;
    r.x = (a.x / (1.f + expf(-a.x))) * b.x;
    r.y = (a.y / (1.f + expf(-a.y))) * b.y;
    r.z = (a.z / (1.f + expf(-a.z))) * b.z;
    r.w = (a.w / (1.f + expf(-a.w))) * b.w;
    return r;
}

// GEMM dynamic smem: As[3][128][40] + Bs[3][32][264] bf16
constexpr int TG_AS_BYTES = 3 * 128 * 40 * 2;   // 30720
constexpr int TG_SMEM = TG_AS_BYTES + 3 * 32 * 264 * 2;  // 81408

// ============================================================
// fp32 -> bf16 convert (n multiple of 8)
// ============================================================
__global__ void f2bf_kernel(const float* __restrict__ in, __nv_bfloat16* __restrict__ out, int n)
{
    int i = (blockIdx.x * TB + threadIdx.x) << 3;
    if (i < n) {
        float4 v0 = *(const float4*)(in + i);
        float4 v1 = *(const float4*)(in + i + 4);
        *(uint2*)(out + i)     = f4_to_bf4(v0);
        *(uint2*)(out + i + 4) = f4_to_bf4(v1);
    }
}

// ============================================================
// Paired convert, 128-col interleaved, 8 elems/thread per input:
// in1/in2 [Cv][Iv] fp32 -> out [Cv][2*Iv] bf16,
// out[r][blk*256 + c] = in1[r][blk*128+c], +128 = in2. z = expert.
// ============================================================
__global__ void f2bf_pair(const float* __restrict__ in1, const float* __restrict__ in2,
                          __nv_bfloat16* __restrict__ out)
{
    size_t zi = (size_t)blockIdx.z * Cv * Iv;
    size_t zo = (size_t)blockIdx.z * Cv * 2 * Iv;
    int i = (blockIdx.x * TB + threadIdx.x) << 3;   // exact grid: Cv*Iv/8 threads
    int r = i >> 11;            // / Iv (2048)
    int c = i & (Iv - 1);
    int blk = c >> 7, cc = c & 127;   // 8 consecutive stay inside one 128-block
    float4 a0 = *(const float4*)(in1 + zi + i);
    float4 a1 = *(const float4*)(in1 + zi + i + 4);
    float4 b0 = *(const float4*)(in2 + zi + i);
    float4 b1 = *(const float4*)(in2 + zi + i + 4);
    size_t ob = zo + (size_t)r * (2 * Iv) + blk * 256 + cc;
    *(uint2*)(out + ob)           = f4_to_bf4(a0);
    *(uint2*)(out + ob + 4)       = f4_to_bf4(a1);
    *(uint2*)(out + ob + 128)     = f4_to_bf4(b0);
    *(uint2*)(out + ob + 128 + 4) = f4_to_bf4(b1);
}

// ============================================================
// RMSNorm: one block per token; dual fp32 (optional) + bf16 output
// ============================================================
__global__ void rmsnorm_kernel(const float* __restrict__ x, const float* __restrict__ w,
                               float* __restrict__ y, __nv_bfloat16* __restrict__ yb)
{
    int n = blockIdx.x, tid = threadIdx.x;
    const float* xr = x + (size_t)n * Cv;
    __shared__ float red[TB];
    float ss = 0.f;
    for (int c = tid; c < Cv; c += TB) { float v = xr[c]; ss += v * v; }
    red[tid] = ss; __syncthreads();
    for (int s = TB / 2; s > 0; s >>= 1) { if (tid < s) red[tid] += red[tid + s]; __syncthreads(); }
    float rs = rsqrtf(red[0] / (float)Cv + 1e-6f);
    __nv_bfloat16* ybr = yb + (size_t)n * Cv;
    float* yr = y ? y + (size_t)n * Cv : nullptr;
    for (int c = tid; c < Cv; c += TB) {
        float v = xr[c] * rs * w[c];
        ybr[c] = __float2bfloat16(v);
        if (yr) yr[c] = v;
    }
}

// ============================================================
// BF16 cp.async 3-stage GEMM, 128x256 block tile, 64x64 warp tile.
// C = alpha*A[M,K]@B[K,N] (+Res). M mult 128, N mult 256, K mult 96.
// ============================================================
__global__ void __launch_bounds__(256) tgemm_bf(
    const __nv_bfloat16* __restrict__ A, const __nv_bfloat16* __restrict__ B,
    float* __restrict__ Cmat, const float* __restrict__ Res,
    int K, int N, float alpha)
{
    extern __shared__ char sm[];
    auto As = (__nv_bfloat16 (*)[128][40])sm;
    auto Bs = (__nv_bfloat16 (*)[32][264])(sm + TG_AS_BYTES);
    const int tid  = threadIdx.x;
    const int warp = tid >> 5;
    const int wm   = warp & 1, wn = warp >> 1;
    const int bm   = blockIdx.y * 128, bn = blockIdx.x * 256;

    wmma::fragment<wmma::accumulator, 16, 16, 16, float> acc[4][4];
#pragma unroll
    for (int mi = 0; mi < 4; mi++)
#pragma unroll
        for (int ni = 0; ni < 4; ni++) wmma::fill_fragment(acc[mi][ni], 0.f);

    const int nch = K >> 5;

    auto issue = [&](int stage, int k0) {
#pragma unroll
        for (int i = 0; i < 2; i++) {
            int ch = (i << 8) + tid;
            int ar = ch >> 2, ac = (ch & 3) << 3;
            cp16(&As[stage][ar][ac], A + (size_t)(bm + ar) * K + k0 + ac);
        }
#pragma unroll
        for (int i = 0; i < 4; i++) {
            int ch = (i << 8) + tid;
            int br = ch >> 5, bc = (ch & 31) << 3;
            cp16(&Bs[stage][br][bc], B + (size_t)(k0 + br) * N + bn + bc);
        }
    };

    issue(0, 0);  CP_COMMIT();
    issue(1, 32); CP_COMMIT();

    for (int ch = 0; ch < nch; ch++) {
        CP_WAIT1();
        __syncthreads();
        if (ch + 2 < nch) issue((ch + 2) % 3, (ch + 2) << 5);
        CP_COMMIT();
        int buf = ch % 3;
#pragma unroll
        for (int ks = 0; ks < 2; ks++) {
            int k16 = ks << 4;
            wmma::fragment<wmma::matrix_a, 16, 16, 16, __nv_bfloat16, wmma::row_major> af[4];
            wmma::fragment<wmma::matrix_b, 16, 16, 16, __nv_bfloat16, wmma::row_major> bf[4];
#pragma unroll
            for (int mi = 0; mi < 4; mi++)
                wmma::load_matrix_sync(af[mi], &As[buf][wm * 64 + mi * 16][k16], 40);
#pragma unroll
            for (int ni = 0; ni < 4; ni++)
                wmma::load_matrix_sync(bf[ni], &Bs[buf][k16][wn * 64 + ni * 16], 264);
#pragma unroll
            for (int mi = 0; mi < 4; mi++)
#pragma unroll
                for (int ni = 0; ni < 4; ni++)
                    wmma::mma_sync(acc[mi][ni], af[mi], bf[ni], acc[mi][ni]);
        }
    }

#pragma unroll
    for (int mi = 0; mi < 4; mi++)
#pragma unroll
        for (int ni = 0; ni < 4; ni++) {
            size_t row = (size_t)(bm + wm * 64 + mi * 16);
            size_t col = (size_t)(bn + wn * 64 + ni * 16);
            float* cp = Cmat + row * N + col;
            if (Res) {
                wmma::fragment<wmma::accumulator, 16, 16, 16, float> rf;
                wmma::load_matrix_sync(rf, Res + row * N + col, N, wmma::mem_row_major);
#pragma unroll
                for (int t = 0; t < rf.num_elements; t++)
                    acc[mi][ni].x[t] = acc[mi][ni].x[t] * alpha + rf.x[t];
            } else if (alpha != 1.f) {
#pragma unroll
                for (int t = 0; t < acc[mi][ni].num_elements; t++)
                    acc[mi][ni].x[t] *= alpha;
            }
            wmma::store_matrix_sync(cp, acc[mi][ni], N, wmma::mem_row_major);
        }
}

// ============================================================
// BF16 GEMM + fused SiLU epilogue (dense or grouped/gathered).
// B is the 128-col interleaved w1|w3 matrix [K][2*Iv].
// Output: U [rows][Iv] bf16; u = silu(left128) * right128.
// ============================================================
template <bool GROUPED>
__global__ void __launch_bounds__(256) tgemm_silu(
    const __nv_bfloat16* __restrict__ A, const __nv_bfloat16* __restrict__ Bbase,
    size_t strideB, int K, __nv_bfloat16* __restrict__ U)
{
    constexpr int N = 2 * Iv;   // 4096
    int cnt = Nv, o = 0, base, bnIdx;
    const __nv_bfloat16* B;
    if (GROUPED) {
        int e = blockIdx.z;
        cnt = g_cnt[e];
        base = blockIdx.x * 128;
        if (base >= cnt) return;
        o = g_off[e];
        bnIdx = blockIdx.y;
        B = Bbase + (size_t)e * strideB;
    } else {
        base = blockIdx.y * 128;
        bnIdx = blockIdx.x;
        B = Bbase;
    }
    const int bn = bnIdx * 256;

    extern __shared__ char sm[];
    auto As = (__nv_bfloat16 (*)[128][40])sm;
    auto Bs = (__nv_bfloat16 (*)[32][264])(sm + TG_AS_BYTES);
    const int tid  = threadIdx.x;
    const int warp = tid >> 5;
    const int wm   = warp & 1, wn = warp >> 1;

    wmma::fragment<wmma::accumulator, 16, 16, 16, float> acc[4][4];
#pragma unroll
    for (int mi = 0; mi < 4; mi++)
#pragma unroll
        for (int ni = 0; ni < 4; ni++) wmma::fill_fragment(acc[mi][ni], 0.f);

    int grow[2]; bool gv[2]; int arr[2]; int arc[2];
#pragma unroll
    for (int i = 0; i < 2; i++) {
        int ch = (i << 8) + tid;
        arr[i] = ch >> 2; arc[i] = (ch & 3) << 3;
        int lr = base + arr[i];
        gv[i] = lr < cnt;
        grow[i] = gv[i] ? (GROUPED ? g_perm[o + lr] : lr) : 0;
    }

    const int nch = K >> 5;

    auto issue = [&](int stg, int k0) {
#pragma unroll
        for (int i = 0; i < 2; i++)
            cp16z(&As[stg][arr[i]][arc[i]], A + (size_t)grow[i] * K + k0 + arc[i], gv[i]);
#pragma unroll
        for (int i = 0; i < 4; i++) {
            int ch = (i << 8) + tid;
            int br = ch >> 5, bc = (ch & 31) << 3;
            cp16(&Bs[stg][br][bc], B + (size_t)(k0 + br) * N + bn + bc);
        }
    };

    issue(0, 0);  CP_COMMIT();
    issue(1, 32); CP_COMMIT();

    for (int ch = 0; ch < nch; ch++) {
        CP_WAIT1();
        __syncthreads();
        if (ch + 2 < nch) issue((ch + 2) % 3, (ch + 2) << 5);
        CP_COMMIT();
        int buf = ch % 3;
#pragma unroll
        for (int ks = 0; ks < 2; ks++) {
            int k16 = ks << 4;
            wmma::fragment<wmma::matrix_a, 16, 16, 16, __nv_bfloat16, wmma::row_major> af[4];
            wmma::fragment<wmma::matrix_b, 16, 16, 16, __nv_bfloat16, wmma::row_major> bf[4];
#pragma unroll
            for (int mi = 0; mi < 4; mi++)
                wmma::load_matrix_sync(af[mi], &As[buf][wm * 64 + mi * 16][k16], 40);
#pragma unroll
            for (int ni = 0; ni < 4; ni++)
                wmma::load_matrix_sync(bf[ni], &Bs[buf][k16][wn * 64 + ni * 16], 264);
#pragma unroll
            for (int mi = 0; mi < 4; mi++)
#pragma unroll
                for (int ni = 0; ni < 4; ni++)
                    wmma::mma_sync(acc[mi][ni], af[mi], bf[ni], acc[mi][ni]);
        }
    }

    // fused SiLU epilogue: stage 32x256 fp32 per mi, pair left/right halves.
    __syncthreads();
    float* S = (float*)sm;                  // 32 rows x ldm 264
    const int er = tid >> 3;                // 0..31
    const int ec = (tid & 7) << 4;          // 0,16,...,112
#pragma unroll
    for (int mi = 0; mi < 4; mi++) {
#pragma unroll
        for (int ni = 0; ni < 4; ni++)
            wmma::store_matrix_sync(S + (wm * 16) * 264 + wn * 64 + ni * 16,
                                    acc[mi][ni], 264, wmma::mem_row_major);
        __syncthreads();
        int lr = base + (er >> 4) * 64 + mi * 16 + (er & 15);
        if (lr < cnt) {
            size_t row = (size_t)(GROUPED ? (o + lr) : lr);
            __nv_bfloat16* op = U + row * Iv + bnIdx * 128 + ec;
            const float* sp = S + er * 264 + ec;
#pragma unroll
            for (int j = 0; j < 16; j += 4) {
                float4 a = *(const float4*)(sp + j);
                float4 b = *(const float4*)(sp + 128 + j);
                *(uint2*)(op + j) = f4_to_bf4(silu4(a, b));
            }
        }
        __syncthreads();
    }
}

// ============================================================
// Grouped w2 GEMM + fused combine epilogue:
// out[n] = x1[n] + (0.5/tw)*sh[n] + (p/tw)*acc,  n = g_perm[compact row].
// A compact [rows][Iv] bf16, B per-expert [Iv][Cv] bf16.
// ============================================================
__global__ void __launch_bounds__(256) gg_w2_combine(
    const __nv_bfloat16* __restrict__ A, const __nv_bfloat16* __restrict__ Bbase,
    size_t strideB, int K,
    const float* __restrict__ x1, const float* __restrict__ sh,
    float* __restrict__ Out)
{
    constexpr int N = Cv;
    int e = blockIdx.z;
    int cnt = g_cnt[e];
    int base = blockIdx.x * 128;
    if (base >= cnt) return;
    int o = g_off[e];
    const __nv_bfloat16* B = Bbase + (size_t)e * strideB;

    extern __shared__ char sm[];
    auto As = (__nv_bfloat16 (*)[128][40])sm;
    auto Bs = (__nv_bfloat16 (*)[32][264])(sm + TG_AS_BYTES);
    const int tid  = threadIdx.x;
    const int warp = tid >> 5;
    const int lane = tid & 31;
    const int wm   = warp & 1, wn = warp >> 1;
    const int bn   = blockIdx.y * 256;

    wmma::fragment<wmma::accumulator, 16, 16, 16, float> acc[4][4];
#pragma unroll
    for (int mi = 0; mi < 4; mi++)
#pragma unroll
        for (int ni = 0; ni < 4; ni++) wmma::fill_fragment(acc[mi][ni], 0.f);

    int grow[2]; bool gv[2]; int arr[2]; int arc[2];
#pragma unroll
    for (int i = 0; i < 2; i++) {
        int ch = (i << 8) + tid;
        arr[i] = ch >> 2; arc[i] = (ch & 3) << 3;
        int lr = base + arr[i];
        gv[i] = lr < cnt;
        grow[i] = gv[i] ? (o + lr) : 0;   // compact rows (no gather)
    }

    const int nch = K >> 5;

    auto issue = [&](int stg, int k0) {
#pragma unroll
        for (int i = 0; i < 2; i++)
            cp16z(&As[stg][arr[i]][arc[i]], A + (size_t)grow[i] * K + k0 + arc[i], gv[i]);
#pragma unroll
        for (int i = 0; i < 4; i++) {
            int ch = (i << 8) + tid;
            int br = ch >> 5, bc = (ch & 31) << 3;
            cp16(&Bs[stg][br][bc], B + (size_t)(k0 + br) * N + bn + bc);
        }
    };

    issue(0, 0);  CP_COMMIT();
    issue(1, 32); CP_COMMIT();

    for (int ch = 0; ch < nch; ch++) {
        CP_WAIT1();
        __syncthreads();
        if (ch + 2 < nch) issue((ch + 2) % 3, (ch + 2) << 5);
        CP_COMMIT();
        int buf = ch % 3;
#pragma unroll
        for (int ks = 0; ks < 2; ks++) {
            int k16 = ks << 4;
            wmma::fragment<wmma::matrix_a, 16, 16, 16, __nv_bfloat16, wmma::row_major> af[4];
            wmma::fragment<wmma::matrix_b, 16, 16, 16, __nv_bfloat16, wmma::row_major> bf[4];
#pragma unroll
            for (int mi = 0; mi < 4; mi++)
                wmma::load_matrix_sync(af[mi], &As[buf][wm * 64 + mi * 16][k16], 40);
#pragma unroll
            for (int ni = 0; ni < 4; ni++)
                wmma::load_matrix_sync(bf[ni], &Bs[buf][k16][wn * 64 + ni * 16], 264);
#pragma unroll
            for (int mi = 0; mi < 4; mi++)
#pragma unroll
                for (int ni = 0; ni < 4; ni++)
                    wmma::mma_sync(acc[mi][ni], af[mi], bf[ni], acc[mi][ni]);
        }
    }

    __syncthreads();   // done with As/Bs; reuse smem as epilogue stage
    float* stg = (float*)sm + warp * 320;   // 16 rows x ldm 20
    const int sr = lane >> 1, sc0 = (lane & 1) << 3;
#pragma unroll
    for (int mi = 0; mi < 4; mi++)
#pragma unroll
        for (int ni = 0; ni < 4; ni++) {
            wmma::store_matrix_sync(stg, acc[mi][ni], 20, wmma::mem_row_major);
            __syncwarp();
            int lr = base + wm * 64 + mi * 16 + sr;
            if (lr < cnt) {
                int n = g_perm[o + lr];
                float p = g_p[n];
                float tw = fminf(fmaxf(0.5f + p + 1e-8f, 0.5f), 2.0f);
                float wsh = 0.5f / tw, wex = p / tw;
                int col = bn + wn * 64 + ni * 16 + sc0;
                const float* xr = x1 + (size_t)n * Cv + col;
                const float* sr2 = sh + (size_t)n * Cv + col;
                float* orow = Out + (size_t)n * Cv + col;
                float4 a0 = *(float4*)(stg + sr * 20 + sc0);
                float4 a1 = *(float4*)(stg + sr * 20 + sc0 + 4);
                float4 xv0 = *(const float4*)(xr);
                float4 xv1 = *(const float4*)(xr + 4);
                float4 sv0 = *(const float4*)(sr2);
                float4 sv1 = *(const float4*)(sr2 + 4);
                float4 r0, r1;
                r0.x = xv0.x + wsh * sv0.x + wex * a0.x;
                r0.y = xv0.y + wsh * sv0.y + wex * a0.y;
                r0.z = xv0.z + wsh * sv0.z + wex * a0.z;
                r0.w = xv0.w + wsh * sv0.w + wex * a0.w;
                r1.x = xv1.x + wsh * sv1.x + wex * a1.x;
                r1.y = xv1.y + wsh * sv1.y + wex * a1.y;
                r1.z = xv1.z + wsh * sv1.z + wex * a1.z;
                r1.w = xv1.w + wsh * sv1.w + wex * a1.w;
                *(float4*)(orow)     = r0;
                *(float4*)(orow + 4) = r1;
            }
            __syncwarp();
        }
}

// ============================================================
// K/V up-projection, bf16 wmma. grid (Nv/128, Hv*2). (fp32 inputs)
// ============================================================
__global__ void kvup_wmma(const float* __restrict__ kv,
                          const float* __restrict__ Wk_up, const float* __restrict__ Wv_up,
                          float* __restrict__ kout, float* __restrict__ vout)
{
    int y = blockIdx.y;
    int h = y >> 1, which = y & 1;
    const float* W = (which ? Wv_up : Wk_up) + (size_t)h * Lv * Dv;
    float* outp = which ? vout : kout;
    int bm = blockIdx.x * 128;

    __shared__ __nv_bfloat16 As[2][128][40];
    __shared__ __nv_bfloat16 Bs[2][32][72];
    const int tid  = threadIdx.x;
    const int warp = tid >> 5;
    const int wm   = warp & 3, wn = warp >> 2;

    wmma::fragment<wmma::accumulator, 16, 16, 16, float> acc[2][2];
#pragma unroll
    for (int mi = 0; mi < 2; mi++)
#pragma unroll
        for (int ni = 0; ni < 2; ni++) wmma::fill_fragment(acc[mi][ni], 0.f);

    const int ar0 = tid >> 3, ac = (tid & 7) << 2;
    const int br0 = tid >> 4, bc = (tid & 15) << 2;

    float4 aR[4], bR[2];
    const int nch = Lv >> 5;

#pragma unroll
    for (int i = 0; i < 4; i++)
        aR[i] = *(const float4*)(kv + (size_t)(bm + ar0 + (i << 5)) * Lv + ac);
#pragma unroll
    for (int i = 0; i < 2; i++)
        bR[i] = *(const float4*)(W + (size_t)(br0 + (i << 4)) * Dv + bc);
#pragma unroll
    for (int i = 0; i < 4; i++)
        *(uint2*)&As[0][ar0 + (i << 5)][ac] = f4_to_bf4(aR[i]);
#pragma unroll
    for (int i = 0; i < 2; i++)
        *(uint2*)&Bs[0][br0 + (i << 4)][bc] = f4_to_bf4(bR[i]);
    __syncthreads();

    int cur = 0;
    for (int ch = 0; ch < nch; ch++) {
        bool has = (ch + 1) < nch;
        if (has) {
            int k0 = (ch + 1) << 5;
#pragma unroll
            for (int i = 0; i < 4; i++)
                aR[i] = *(const float4*)(kv + (size_t)(bm + ar0 + (i << 5)) * Lv + k0 + ac);
#pragma unroll
            for (int i = 0; i < 2; i++)
                bR[i] = *(const float4*)(W + (size_t)(k0 + br0 + (i << 4)) * Dv + bc);
        }
#pragma unroll
        for (int ks = 0; ks < 2; ks++) {
            int k16 = ks << 4;
            wmma::fragment<wmma::matrix_a, 16, 16, 16, __nv_bfloat16, wmma::row_major> af[2];
            wmma::fragment<wmma::matrix_b, 16, 16, 16, __nv_bfloat16, wmma::row_major> bf[2];
#pragma unroll
            for (int mi = 0; mi < 2; mi++)
                wmma::load_matrix_sync(af[mi], &As[cur][wm * 32 + mi * 16][k16], 40);
#pragma unroll
            for (int ni = 0; ni < 2; ni++)
                wmma::load_matrix_sync(bf[ni], &Bs[cur][k16][wn * 32 + ni * 16], 72);
#pragma unroll
            for (int mi = 0; mi < 2; mi++)
#pragma unroll
                for (int ni = 0; ni < 2; ni++)
                    wmma::mma_sync(acc[mi][ni], af[mi], bf[ni], acc[mi][ni]);
        }
        if (has) {
            int nxt = cur ^ 1;
#pragma unroll
            for (int i = 0; i < 4; i++)
                *(uint2*)&As[nxt][ar0 + (i << 5)][ac] = f4_to_bf4(aR[i]);
#pragma unroll
            for (int i = 0; i < 2; i++)
                *(uint2*)&Bs[nxt][br0 + (i << 4)][bc] = f4_to_bf4(bR[i]);
        }
        __syncthreads();
        cur ^= 1;
    }

#pragma unroll
    for (int mi = 0; mi < 2; mi++) {
        int n0 = bm + wm * 32 + mi * 16;
        int b = n0 >> 10, t0 = n0 & 1023;
        float* bp = outp + ((size_t)(b * Hv + h) * Tv + t0) * Dv;
#pragma unroll
        for (int ni = 0; ni < 2; ni++)
            wmma::store_matrix_sync(bp + wn * 32 + ni * 16, acc[mi][ni], Dv, wmma::mem_row_major);
    }
}

// ============================================================
// RoPE: q and k in one launch. which=0 -> q (posDiv=Hv), 1 -> k (posDiv=1).
// ============================================================
__global__ void rope_kernel(float* __restrict__ qp, float* __restrict__ kp)
{
    int gi = blockIdx.x * TB + threadIdx.x;      // 2 * Nv*Hv*32 total
    int which = gi >= (Nv * Hv * 32);
    int idx = which ? gi - Nv * Hv * 32 : gi;
    int outer = idx >> 5;
    int j = idx & 31;
    int pos = which ? (outer & (Tv - 1)) : ((outer / Hv) & (Tv - 1));
    float invf = powf(100000.0f, -(float)j * (1.0f / 32.0f));
    float f = (float)pos * invf;
    float s, c; sincosf(f, &s, &c);
    float* p = (which ? kp : qp) + (size_t)outer * Dv;
    float x1 = p[j], x2 = p[j + 32];
    p[j]      = x1 * c - x2 * s;
    p[j + 32] = x1 * s + x2 * c;
}

// ============================================================
// Flash attention (tf32 wmma, online softmax). Out bf16 token-major.
// ============================================================
constexpr int FLASH_SMEM = (5 * 64 * 68 + 3 * 64) * 4;

__global__ void __launch_bounds__(256) flash_kernel(
    const float* __restrict__ q, const float* __restrict__ k,
    const float* __restrict__ v, __nv_bfloat16* __restrict__ obf)
{
    extern __shared__ float fs[];
    float (*Qs)[68] = (float(*)[68])fs;
    float (*Ks)[68] = (float(*)[68])(fs + 64 * 68);
    float (*Vs)[68] = (float(*)[68])(fs + 2 * 64 * 68);
    float (*Ss)[68] = (float(*)[68])(fs + 3 * 64 * 68);
    float (*Os)[68] = (float(*)[68])(fs + 4 * 64 * 68);
    float* mrow = fs + 5 * 64 * 68;
    float* lrow = mrow + 64;
    float* srow = lrow + 64;

    const int qt = blockIdx.x, bh = blockIdx.y;
    const int b = bh >> 4, h = bh & 15;
    const int qs = qt * 64;
    const int tid = threadIdx.x;
    const int warp = tid >> 5;
    const int wm = warp & 3, wn = warp >> 2;
    const int row = tid >> 2, qd = tid & 3;

#pragma unroll
    for (int i = 0; i < 4; i++) {
        int ch = (i << 8) + tid;
        int r = ch >> 4, c = (ch & 15) << 2;
        cp16(&Qs[r][c], q + (size_t)(b * Tv + qs + r) * Cv + h * Dv + c);
    }
    CP_COMMIT();
    for (int i = tid; i < 64 * 68; i += 256) fs[4 * 64 * 68 + i] = 0.f;
    if (tid < 64) { mrow[tid] = -1e30f; lrow[tid] = 0.f; }
    CP_WAIT0();
    __syncthreads();

    for (int kt = 0; kt <= qt; kt++) {
        int ks = kt * 64;
#pragma unroll
        for (int i = 0; i < 4; i++) {
            int ch = (i << 8) + tid;
            int r = ch >> 4, c = (ch & 15) << 2;
            cp16(&Ks[r][c], k + (size_t)(bh * Tv + ks + r) * Dv + c);
            cp16(&Vs[r][c], v + (size_t)(bh * Tv + ks + r) * Dv + c);
        }
        CP_COMMIT();
        CP_WAIT0();
        __syncthreads();

        {
            wmma::fragment<wmma::accumulator, 16, 16, 8, float> a0, a1;
            wmma::fill_fragment(a0, 0.f); wmma::fill_fragment(a1, 0.f);
#pragma unroll
            for (int k8 = 0; k8 < 64; k8 += 8) {
                wmma::fragment<wmma::matrix_a, 16, 16, 8, wmma::precision::tf32, wmma::row_major> af;
                wmma::fragment<wmma::matrix_b, 16, 16, 8, wmma::precision::tf32, wmma::col_major> bf0, bf1;
                wmma::load_matrix_sync(af, &Qs[wm * 16][k8], 68);
                wmma::load_matrix_sync(bf0, &Ks[wn * 32][k8], 68);
                wmma::load_matrix_sync(bf1, &Ks[wn * 32 + 16][k8], 68);
                wmma::mma_sync(a0, af, bf0, a0);
                wmma::mma_sync(a1, af, bf1, a1);
            }
#pragma unroll
            for (int t = 0; t < a0.num_elements; t++) { a0.x[t] *= 0.125f; a1.x[t] *= 0.125f; }
            wmma::store_matrix_sync(&Ss[wm * 16][wn * 32], a0, 68, wmma::mem_row_major);
            wmma::store_matrix_sync(&Ss[wm * 16][wn * 32 + 16], a1, 68, wmma::mem_row_major);
        }
        __syncthreads();

        {
            const bool diag = (kt == qt);
            float sv[16];
            float mloc = -1e30f;
#pragma unroll
            for (int i = 0; i < 16; i++) {
                int j = qd + (i << 2);
                float s = Ss[row][j];
                if (diag && j > row) s = -1e30f;
                sv[i] = s;
                mloc = fmaxf(mloc, s);
            }
            mloc = fmaxf(mloc, __shfl_xor_sync(0xffffffffu, mloc, 1));
            mloc = fmaxf(mloc, __shfl_xor_sync(0xffffffffu, mloc, 2));
            float mold = mrow[row];
            float mnew = fmaxf(mold, mloc);
            float psum = 0.f;
#pragma unroll
            for (int i = 0; i < 16; i++) {
                int j = qd + (i << 2);
                float p = (sv[i] > -1e29f) ? expf(sv[i] - mnew) : 0.f;
                Ss[row][j] = to_tf32(p);
                psum += p;
            }
            psum += __shfl_xor_sync(0xffffffffu, psum, 1);
            psum += __shfl_xor_sync(0xffffffffu, psum, 2);
            if (qd == 0) {
                float scl = expf(mold - mnew);
                mrow[row] = mnew;
                lrow[row] = lrow[row] * scl + psum;
                srow[row] = scl;
            }
        }
        __syncthreads();

        {
            wmma::fragment<wmma::matrix_a, 16, 16, 8, wmma::precision::tf32, wmma::row_major> af[8];
#pragma unroll
            for (int kk = 0; kk < 8; kk++)
                wmma::load_matrix_sync(af[kk], &Ss[wm * 16][kk * 8], 68);
            __syncthreads();
            wmma::fragment<wmma::accumulator, 16, 16, 8, float> a0, a1;
            wmma::fill_fragment(a0, 0.f); wmma::fill_fragment(a1, 0.f);
#pragma unroll
            for (int kk = 0; kk < 8; kk++) {
                wmma::fragment<wmma::matrix_b, 16, 16, 8, wmma::precision::tf32, wmma::row_major> bf0, bf1;
                wmma::load_matrix_sync(bf0, &Vs[kk * 8][wn * 32], 68);
                wmma::load_matrix_sync(bf1, &Vs[kk * 8][wn * 32 + 16], 68);
                wmma::mma_sync(a0, af[kk], bf0, a0);
                wmma::mma_sync(a1, af[kk], bf1, a1);
            }
            wmma::store_matrix_sync(&Ss[wm * 16][wn * 32], a0, 68, wmma::mem_row_major);
            wmma::store_matrix_sync(&Ss[wm * 16][wn * 32 + 16], a1, 68, wmma::mem_row_major);
        }
        __syncthreads();

        {
            float scl = srow[row];
#pragma unroll
            for (int i = 0; i < 16; i++) {
                int j = qd + (i << 2);
                Os[row][j] = Os[row][j] * scl + Ss[row][j];
            }
        }
        __syncthreads();
    }

    {
        float inv = 1.f / lrow[row];
        __nv_bfloat16* op = obf + (size_t)(b * Tv + qs + row) * Cv + h * Dv;
#pragma unroll
        for (int i = 0; i < 16; i++) {
            int j = qd + (i << 2);
            op[j] = __float2bfloat16(Os[row][j] * inv);
        }
    }
}

// ============================================================
// Router
// ============================================================
__global__ void router_kernel(const float* __restrict__ h2, const float* __restrict__ Wr,
                              const float* __restrict__ rb)
{
    int n = blockIdx.x, tid = threadIdx.x;
    const float* xr = h2 + (size_t)n * Cv;
    float part[Ev];
#pragma unroll
    for (int e = 0; e < Ev; e++) part[e] = 0.f;
    for (int c = tid; c < Cv; c += TB) {
        float xv = xr[c];
#pragma unroll
        for (int e = 0; e < Ev; e++) part[e] += xv * Wr[c * Ev + e];
    }
    __shared__ float sd[Ev][TB];
#pragma unroll
    for (int e = 0; e < Ev; e++) sd[e][tid] = part[e];
    __syncthreads();
    for (int st = TB / 2; st > 0; st >>= 1) {
        if (tid < st)
#pragma unroll
            for (int e = 0; e < Ev; e++) sd[e][tid] += sd[e][tid + st];
        __syncthreads();
    }
    if (tid == 0) {
        int best = 0; float bp = -1.f;
#pragma unroll
        for (int e = 0; e < Ev; e++) {
            float lg = fminf(fmaxf(sd[e][0] + rb[e], -50.f), 50.f);
            float pr = 1.f / (1.f + expf(-lg));
            if (pr > bp) { bp = pr; best = e; }
        }
        g_sel[n] = best;
        g_p[n]   = fminf(fmaxf(bp, 1e-8f), 1.f - 1e-8f);
    }
}

__global__ void zero_kernel() {
    int t = threadIdx.x;
    if (t < Ev) { g_cnt[t] = 0; g_cur[t] = 0; }
}
__global__ void hist_kernel() {
    int n = blockIdx.x * TB + threadIdx.x;
    if (n < Nv) atomicAdd(&g_cnt[g_sel[n]], 1);
}
__global__ void offsets_kernel() {
    int s = 0;
    for (int e = 0; e < Ev; e++) { g_off[e] = s; s += g_cnt[e]; }
}
__global__ void scatter_kernel() {
    int n = blockIdx.x * TB + threadIdx.x;
    if (n < Nv) {
        int e = g_sel[n];
        int pos = atomicAdd(&g_cur[e], 1);
        g_perm[g_off[e] + pos] = n;
    }
}

// ============================================================
// launcher
// ============================================================
extern "C" void kernel_launch(void* const* d_in, const int* in_sizes, int n_in,
                              void* d_out, int out_size)
{
    const float* x    = (const float*)d_in[0];
    const float* ln1  = (const float*)d_in[1];
    const float* ln2  = (const float*)d_in[2];
    const float* Wq   = (const float*)d_in[3];
    const float* Wkv  = (const float*)d_in[4];
    const float* Wk_up= (const float*)d_in[5];
    const float* Wv_up= (const float*)d_in[6];
    const float* Wo   = (const float*)d_in[7];
    const float* Wr   = (const float*)d_in[8];
    const float* rb   = (const float*)d_in[9];
    const float* sw1  = (const float*)d_in[10];
    const float* sw2  = (const float*)d_in[11];
    const float* sw3  = (const float*)d_in[12];
    const float* ew1  = (const float*)d_in[13];
    const float* ew2  = (const float*)d_in[14];
    const float* ew3  = (const float*)d_in[15];
    float* out = (float*)d_out;

    float *pkv, *pq, *pk, *pv, *px1, *ph2, *psh;
    __nv_bfloat16 *phbf, *ph2bf, *patbf, *pubf, *pucbf;
    __nv_bfloat16 *wq, *wkv, *wo, *s13, *s2, *e13, *e2;
    cudaGetSymbolAddress((void**)&pkv, g_kv);
    cudaGetSymbolAddress((void**)&pq,  g_q);
    cudaGetSymbolAddress((void**)&pk,  g_k);
    cudaGetSymbolAddress((void**)&pv,  g_v);
    cudaGetSymbolAddress((void**)&px1, g_x1);
    cudaGetSymbolAddress((void**)&ph2, g_h2);
    cudaGetSymbolAddress((void**)&psh, g_sh);
    cudaGetSymbolAddress((void**)&phbf,  g_hbf);
    cudaGetSymbolAddress((void**)&ph2bf, g_h2bf);
    cudaGetSymbolAddress((void**)&patbf, g_atbf);
    cudaGetSymbolAddress((void**)&pubf,  g_ubf);
    cudaGetSymbolAddress((void**)&pucbf, g_ucbf);
    cudaGetSymbolAddress((void**)&wq,  g_Wq_bf);
    cudaGetSymbolAddress((void**)&wkv, g_Wkv_bf);
    cudaGetSymbolAddress((void**)&wo,  g_Wo_bf);
    cudaGetSymbolAddress((void**)&s13, g_s13_bf);
    cudaGetSymbolAddress((void**)&s2,  g_sw2_bf);
    cudaGetSymbolAddress((void**)&e13, g_e13_bf);
    cudaGetSymbolAddress((void**)&e2,  g_ew2_bf);

    cudaFuncSetAttribute(flash_kernel, cudaFuncAttributeMaxDynamicSharedMemorySize, FLASH_SMEM);
    cudaFuncSetAttribute(tgemm_bf, cudaFuncAttributeMaxDynamicSharedMemorySize, TG_SMEM);
    cudaFuncSetAttribute(tgemm_silu<false>, cudaFuncAttributeMaxDynamicSharedMemorySize, TG_SMEM);
    cudaFuncSetAttribute(tgemm_silu<true>,  cudaFuncAttributeMaxDynamicSharedMemorySize, TG_SMEM);
    cudaFuncSetAttribute(gg_w2_combine, cudaFuncAttributeMaxDynamicSharedMemorySize, TG_SMEM);

    // ---- weight conversion (bf16; s13/e13 interleaved 128-blocks) ----
    f2bf_kernel<<<(Cv * Cv) / (TB * 8), TB>>>(Wq,  wq,  Cv * Cv);
    f2bf_kernel<<<(Cv * Lv) / (TB * 8), TB>>>(Wkv, wkv, Cv * Lv);
    f2bf_kernel<<<(Cv * Cv) / (TB * 8), TB>>>(Wo,  wo,  Cv * Cv);
    f2bf_pair<<<dim3((Cv * Iv) / (TB * 8), 1, 1),  TB>>>(sw1, sw3, s13);
    f2bf_kernel<<<(Iv * Cv) / (TB * 8), TB>>>(sw2, s2, Iv * Cv);
    f2bf_pair<<<dim3((Cv * Iv) / (TB * 8), 1, Ev), TB>>>(ew1, ew3, e13);
    f2bf_kernel<<<(Ev * Iv * Cv) / (TB * 8), TB>>>(ew2, e2, Ev * Iv * Cv);

    // ---- attention ----
    rmsnorm_kernel<<<Nv, TB>>>(x, ln1, nullptr, phbf);
    tgemm_bf<<<dim3(Cv / 256, Nv / 128), TB, TG_SMEM>>>(phbf, wq,  pq,  nullptr, Cv, Cv, 1.f);
    tgemm_bf<<<dim3(Lv / 256, Nv / 128), TB, TG_SMEM>>>(phbf, wkv, pkv, nullptr, Cv, Lv, 0.25f);
    kvup_wmma<<<dim3(Nv / 128, Hv * 2), TB>>>(pkv, Wk_up, Wv_up, pk, pv);
    rope_kernel<<<(2 * Nv * Hv * 32) / TB, TB>>>(pq, pk);
    flash_kernel<<<dim3(Tv / 64, BHv), TB, FLASH_SMEM>>>(pq, pk, pv, patbf);
    tgemm_bf<<<dim3(Cv / 256, Nv / 128), TB, TG_SMEM>>>(patbf, wo, px1, x, Cv, Cv, 1.f);

    // ---- MoE ----
    rmsnorm_kernel<<<Nv, TB>>>(px1, ln2, ph2, ph2bf);
    router_kernel<<<Nv, TB>>>(ph2, Wr, rb);
    zero_kernel<<<1, 32>>>();
    hist_kernel<<<Nv / TB, TB>>>();
    offsets_kernel<<<1, 1>>>();
    scatter_kernel<<<Nv / TB, TB>>>();

    // shared expert: fused w1|w3 GEMM + SiLU epilogue -> ubf
    tgemm_silu<false><<<dim3((2 * Iv) / 256, Nv / 128), TB, TG_SMEM>>>(ph2bf, s13, 0, Cv, pubf);
    tgemm_bf<<<dim3(Cv / 256, Nv / 128), TB, TG_SMEM>>>(pubf, s2, psh, nullptr, Iv, Cv, 1.f);

    // routed experts: fused grouped w1|w3 GEMM + SiLU -> ucbf, then w2 + combine -> out
    tgemm_silu<true><<<dim3(Nv / 128, (2 * Iv) / 256, Ev), TB, TG_SMEM>>>(ph2bf, e13, (size_t)Cv * 2 * Iv, Cv, pucbf);
    gg_w2_combine<<<dim3(Nv / 128, Cv / 256, Ev), TB, TG_SMEM>>>(pucbf, e2, (size_t)Iv * Cv, Iv, px1, psh, out);
}